// round 4
// baseline (speedup 1.0000x reference)
#include <cuda_runtime.h>
#include <cuda_bf16.h>
#include <math.h>
#include <stdint.h>

#define N_TOK 4096
#define DIM   1024
#define HID   768
#define NE    23
#define TOPK  3
#define NSLOT (N_TOK * TOPK)

#define TBM 128
#define TBN 128
#define TBK 32
#define A_STRIDE 80
#define B_STRIDE 272
#define AH_OFF 0
#define AL_OFF 10240
#define BH_OFF 20480
#define BL_OFF 29184
#define STG    37888
#define SMEM_SZ (2 * STG)

// ---------------- scratch ----------------
__device__ float g_gw[(size_t)N_TOK * NE];
__device__ int   g_counts[NE];
__device__ int   g_list[(size_t)NE * N_TOK];
__device__ float g_tw[NSLOT];
__device__ float g_Hs[(size_t)N_TOK * HID];
__device__ float g_Hr[(size_t)NSLOT * HID];
__device__ float g_Yr[(size_t)NSLOT * DIM];

__device__ __forceinline__ float gelu_exact(float v) {
    return 0.5f * v * (1.0f + erff(v * 0.7071067811865476f));
}
__device__ __forceinline__ uint32_t smem_u32(const void* p) {
    uint32_t a;
    asm("{ .reg .u64 t; cvta.to.shared.u64 t, %1; cvt.u32.u64 %0, t; }" : "=r"(a) : "l"(p));
    return a;
}
__device__ __forceinline__ void ldsm_x4(uint32_t addr, uint32_t* r) {
    asm volatile("ldmatrix.sync.aligned.m8n8.x4.shared.b16 {%0,%1,%2,%3}, [%4];"
                 : "=r"(r[0]), "=r"(r[1]), "=r"(r[2]), "=r"(r[3]) : "r"(addr));
}
__device__ __forceinline__ void ldsm_x4_t(uint32_t addr, uint32_t* r) {
    asm volatile("ldmatrix.sync.aligned.m8n8.x4.trans.shared.b16 {%0,%1,%2,%3}, [%4];"
                 : "=r"(r[0]), "=r"(r[1]), "=r"(r[2]), "=r"(r[3]) : "r"(addr));
}
__device__ __forceinline__ void mma_bf16(float* c, const uint32_t* a, uint32_t b0, uint32_t b1) {
    asm volatile("mma.sync.aligned.m16n8k16.row.col.f32.bf16.bf16.f32 "
                 "{%0,%1,%2,%3}, {%4,%5,%6,%7}, {%8,%9}, {%0,%1,%2,%3};"
                 : "+f"(c[0]), "+f"(c[1]), "+f"(c[2]), "+f"(c[3])
                 : "r"(a[0]), "r"(a[1]), "r"(a[2]), "r"(a[3]), "r"(b0), "r"(b1));
}
__device__ __forceinline__ uint32_t pack2(__nv_bfloat16 a, __nv_bfloat16 b) {
    return (uint32_t)__bfloat16_as_ushort(a) | ((uint32_t)__bfloat16_as_ushort(b) << 16);
}
__device__ __forceinline__ void split4(float4 v, uint2& h, uint2& l) {
    float vv[4] = {v.x, v.y, v.z, v.w};
    __nv_bfloat16 hh[4], ll[4];
    #pragma unroll
    for (int q = 0; q < 4; q++) {
        hh[q] = __float2bfloat16(vv[q]);
        ll[q] = __float2bfloat16(vv[q] - __bfloat162float(hh[q]));
    }
    h = make_uint2(pack2(hh[0], hh[1]), pack2(hh[2], hh[3]));
    l = make_uint2(pack2(ll[0], ll[1]), pack2(ll[2], ll[3]));
}

// ---------------- init ----------------
__global__ void init_kernel() {
    int t = threadIdx.x;
    if (t < NE) g_counts[t] = 0;
}

// ---------------- gate (known-correct) ----------------
__global__ void gate_kernel(const float* __restrict__ x,
                            const float* __restrict__ gW,
                            const float* __restrict__ gb,
                            const float* __restrict__ rbias)
{
    __shared__ float xs[DIM];
    __shared__ float gv[NE];
    __shared__ float gsum_s;
    int n = blockIdx.x;
    int t = threadIdx.x;

    const float4* xv  = (const float4*)(x + (size_t)n * DIM);
    float4*       xsv = (float4*)xs;
    for (int i = t; i < DIM / 4; i += 128) xsv[i] = xv[i];
    __syncthreads();

    int e = t >> 2, j = t & 3;
    float acc = 0.f;
    if (e < NE) {
        for (int i = j; i < DIM; i += 4)
            acc += xs[i] * gW[i * NE + e];
    }
    acc += __shfl_xor_sync(0xffffffffu, acc, 1);
    acc += __shfl_xor_sync(0xffffffffu, acc, 2);
    if (e < NE && j == 0)
        gv[e] = 1.0f / (1.0f + expf(-(acc + gb[e])));
    __syncthreads();

    if (t == 0) {
        float s = 0.f;
        for (int q = 0; q < NE; q++) s += gv[q];
        gsum_s = s;
    }
    __syncthreads();

    if (t < NE) g_gw[(size_t)n * NE + t] = gv[t] / gsum_s;

    if (t == 0) {
        int   idx[TOPK];
        float w[TOPK];
        unsigned used = 0;
        for (int k = 0; k < TOPK; k++) {
            float best = -1e30f; int bi = 0;
            for (int q = 0; q < NE; q++) {
                if (used & (1u << q)) continue;
                float s = gv[q] + rbias[q];
                if (s > best) { best = s; bi = q; }
            }
            used |= (1u << bi);
            idx[k] = bi;
            w[k]   = gv[bi];
        }
        float ws = w[0] + w[1] + w[2];
        for (int k = 0; k < TOPK; k++) {
            int slot = n * TOPK + k;
            g_tw[slot] = w[k] / ws;
            int pos = atomicAdd(&g_counts[idx[k]], 1);
            g_list[(size_t)idx[k] * N_TOK + pos] = slot;
        }
    }
}

// ---------------- aux loss ----------------
__global__ void aux_kernel(float* __restrict__ out, int out_size)
{
    __shared__ float sm[256 * NE];
    int t = threadIdx.x;
    float loc[NE];
    #pragma unroll
    for (int e = 0; e < NE; e++) loc[e] = 0.f;
    for (int n = t; n < N_TOK; n += 256) {
        #pragma unroll
        for (int e = 0; e < NE; e++) loc[e] += g_gw[(size_t)n * NE + e];
    }
    for (int e = 0; e < NE; e++) sm[t * NE + e] = loc[e];
    __syncthreads();
    for (int s = 128; s > 0; s >>= 1) {
        if (t < s)
            for (int e = 0; e < NE; e++) sm[t * NE + e] += sm[(t + s) * NE + e];
        __syncthreads();
    }
    if (t == 0 && out_size > N_TOK * DIM) {
        float aux = 0.f;
        for (int e = 0; e < NE; e++) {
            float P = sm[e] / (float)N_TOK;
            float F = ((float)NE * (float)g_counts[e]) / ((float)TOPK * (float)N_TOK);
            aux += P * F;
        }
        out[(size_t)N_TOK * DIM] = aux;
    }
}

// ---------------- merged bf16 3-term split GEMM ----------------
// blockIdx.z in [0, NE]: z<NE -> routed expert z; z==NE -> shared expert.
// MLP1: Out = gelu(D + bias); MLP2: Out = (D + bias) * (routed? tw : 1)
template<int KDIM, int NOUT, bool MLP1>
__global__ void __launch_bounds__(256, 1) mma_mlp(
    const float* __restrict__ Ar, const float* __restrict__ Ash,
    const float* __restrict__ Br, const float* __restrict__ Bsh,
    const float* __restrict__ biasR, const float* __restrict__ biasS,
    float* __restrict__ OutR, float* __restrict__ OutS)
{
    constexpr int NC = KDIM / TBK;

    int ez = blockIdx.z;
    bool sh = (ez == NE);
    int cnt = sh ? N_TOK : g_counts[ez];
    int m0  = blockIdx.x * TBM;
    if (m0 >= cnt) return;
    int n0  = blockIdx.y * TBN;

    extern __shared__ char smem[];
    uint32_t sbase = smem_u32(smem);

    int tid  = threadIdx.x;
    int wid  = tid >> 5;
    int lane = tid & 31;
    int wm   = wid >> 2;
    int wn   = wid & 3;

    const float* A    = sh ? Ash : Ar;
    const float* Bgz  = sh ? Bsh : (Br + (size_t)ez * KDIM * NOUT);
    const float* bias = sh ? biasS : (biasR + (size_t)ez * NOUT);

    // ---- loader setup ----
    int arow = tid >> 1;
    int ah   = tid & 1;
    int gi_a = m0 + arow;
    int grow;
    if (sh) {
        grow = gi_a;
    } else {
        int gg   = (gi_a < cnt) ? gi_a : (cnt - 1);
        int slot = g_list[(size_t)ez * N_TOK + gg];
        grow = MLP1 ? (slot / TOPK) : slot;
    }
    const float* Aptr = A + (size_t)grow * KDIM + ah * 16;
    uint32_t aoff = (uint32_t)(arow * A_STRIDE + ah * 32);

    int bk = tid >> 3;
    int bc = tid & 7;
    const float* Bptr = Bgz + (size_t)bk * NOUT + n0 + bc * 4;
    uint32_t boff = (uint32_t)(bk * B_STRIDE + bc * 8);

    float4 fa[4], fb[4];
    #pragma unroll
    for (int q = 0; q < 4; q++) {
        fa[q] = *(const float4*)(Aptr + q * 4);
        fb[q] = *(const float4*)(Bptr + q * 32);
    }
    // store chunk 0 -> stage 0
    {
        char* st = smem;
        #pragma unroll
        for (int q = 0; q < 4; q++) {
            uint2 h, l;
            split4(fa[q], h, l);
            *(uint2*)(st + AH_OFF + aoff + q * 8) = h;
            *(uint2*)(st + AL_OFF + aoff + q * 8) = l;
            split4(fb[q], h, l);
            *(uint2*)(st + BH_OFF + boff + q * 64) = h;
            *(uint2*)(st + BL_OFF + boff + q * 64) = l;
        }
    }
    __syncthreads();
    // prefetch chunk 1
    if (NC > 1) {
        #pragma unroll
        for (int q = 0; q < 4; q++) {
            fa[q] = *(const float4*)(Aptr + TBK + q * 4);
            fb[q] = *(const float4*)(Bptr + (size_t)TBK * NOUT + q * 32);
        }
    }

    float acc[4][4][4];
    #pragma unroll
    for (int i = 0; i < 4; i++)
        #pragma unroll
        for (int j = 0; j < 4; j++)
            #pragma unroll
            for (int q = 0; q < 4; q++) acc[i][j][q] = 0.f;

    uint32_t aAddr = sbase + AH_OFF + (uint32_t)((wm * 64 + (lane & 15)) * A_STRIDE + ((lane >> 4) << 4));
    uint32_t bAddr = sbase + BH_OFF + (uint32_t)((lane & 15) * B_STRIDE + ((wn * 32 + (lane >> 4) * 8) << 1));

    for (int c = 0; c < NC; c++) {
        int s = c & 1;
        // 1) store prefetched chunk c+1 into the other stage (overlaps with mma below)
        if (c + 1 < NC) {
            char* st = smem + (s ^ 1) * STG;
            #pragma unroll
            for (int q = 0; q < 4; q++) {
                uint2 h, l;
                split4(fa[q], h, l);
                *(uint2*)(st + AH_OFF + aoff + q * 8) = h;
                *(uint2*)(st + AL_OFF + aoff + q * 8) = l;
                split4(fb[q], h, l);
                *(uint2*)(st + BH_OFF + boff + q * 64) = h;
                *(uint2*)(st + BL_OFF + boff + q * 64) = l;
            }
            // 2) issue global prefetch for chunk c+2 (retires under compute)
            if (c + 2 < NC) {
                int k0 = (c + 2) * TBK;
                #pragma unroll
                for (int q = 0; q < 4; q++) {
                    fa[q] = *(const float4*)(Aptr + k0 + q * 4);
                    fb[q] = *(const float4*)(Bptr + (size_t)k0 * NOUT + q * 32);
                }
            }
        }
        // 3) compute from stage s
        uint32_t aS = aAddr + (uint32_t)(s * STG);
        uint32_t bS = bAddr + (uint32_t)(s * STG);
        #pragma unroll
        for (int ks = 0; ks < 2; ks++) {
            uint32_t ahF[4][4], alF[4][4];
            #pragma unroll
            for (int i = 0; i < 4; i++) {
                ldsm_x4(aS + ks * 32 + i * (16 * A_STRIDE), ahF[i]);
                ldsm_x4(aS + ks * 32 + i * (16 * A_STRIDE) + (AL_OFF - AH_OFF), alF[i]);
            }
            uint32_t bhF[2][4], blF[2][4];
            #pragma unroll
            for (int g = 0; g < 2; g++) {
                ldsm_x4_t(bS + ks * (16 * B_STRIDE) + g * 32, bhF[g]);
                ldsm_x4_t(bS + ks * (16 * B_STRIDE) + g * 32 + (BL_OFF - BH_OFF), blF[g]);
            }
            #pragma unroll
            for (int i = 0; i < 4; i++) {
                #pragma unroll
                for (int j = 0; j < 4; j++) {
                    int g = j >> 1, o = (j & 1) * 2;
                    mma_bf16(acc[i][j], ahF[i], bhF[g][o], bhF[g][o + 1]);
                    mma_bf16(acc[i][j], ahF[i], blF[g][o], blF[g][o + 1]);
                    mma_bf16(acc[i][j], alF[i], bhF[g][o], bhF[g][o + 1]);
                }
            }
        }
        __syncthreads();   // single barrier per chunk
    }

    // ---- epilogue ----
    float* epi = (float*)smem;
    {
        int rb = wm * 64 + (lane >> 2);
        int cb = wn * 32 + (lane & 3) * 2;
        #pragma unroll
        for (int i = 0; i < 4; i++) {
            #pragma unroll
            for (int j = 0; j < 4; j++) {
                int r = rb + i * 16;
                int cc = cb + j * 8;
                epi[r * 132 + cc]           = acc[i][j][0];
                epi[r * 132 + cc + 1]       = acc[i][j][1];
                epi[(r + 8) * 132 + cc]     = acc[i][j][2];
                epi[(r + 8) * 132 + cc + 1] = acc[i][j][3];
            }
        }
    }
    __syncthreads();

    for (int i = tid; i < TBM * (TBN / 4); i += 256) {
        int r  = i >> 5;
        int c4 = i & 31;
        int gi = m0 + r;
        if (gi >= cnt) continue;
        float4 v = *(float4*)&epi[r * 132 + c4 * 4];
        int col = n0 + c4 * 4;
        float4 b4 = *(const float4*)(bias + col);
        v.x += b4.x; v.y += b4.y; v.z += b4.z; v.w += b4.w;
        float* Out;
        size_t orow;
        if (sh) {
            Out = OutS; orow = (size_t)gi;
        } else {
            int slot = g_list[(size_t)ez * N_TOK + gi];
            Out = OutR; orow = (size_t)slot;
            if (!MLP1) {
                float w = g_tw[slot];
                v.x *= w; v.y *= w; v.z *= w; v.w *= w;
            }
        }
        if (MLP1) {
            v.x = gelu_exact(v.x); v.y = gelu_exact(v.y);
            v.z = gelu_exact(v.z); v.w = gelu_exact(v.w);
        }
        *(float4*)(Out + orow * NOUT + col) = v;
    }
}

// ---------------- combine ----------------
__global__ void combine_kernel(float* __restrict__ out)
{
    int idx = blockIdx.x * blockDim.x + threadIdx.x;
    if (idx >= N_TOK * (DIM / 4)) return;
    int n  = idx / (DIM / 4);
    int d4 = idx % (DIM / 4);
    float4 v = ((float4*)out)[idx];
    const float4* yr = (const float4*)g_Yr;
    #pragma unroll
    for (int k = 0; k < TOPK; k++) {
        float4 y = yr[(size_t)(n * TOPK + k) * (DIM / 4) + d4];
        v.x += y.x; v.y += y.y; v.z += y.z; v.w += y.w;
    }
    ((float4*)out)[idx] = v;
}

// ---------------- launch ----------------
extern "C" void kernel_launch(void* const* d_in, const int* in_sizes, int n_in,
                              void* d_out, int out_size)
{
    const float* x   = (const float*)d_in[0];
    const float* gW  = (const float*)d_in[1];
    const float* gb  = (const float*)d_in[2];
    const float* rb  = (const float*)d_in[3];
    const float* W1  = (const float*)d_in[4];
    const float* b1  = (const float*)d_in[5];
    const float* W2  = (const float*)d_in[6];
    const float* b2  = (const float*)d_in[7];
    const float* sW1 = (const float*)d_in[8];
    const float* sb1 = (const float*)d_in[9];
    const float* sW2 = (const float*)d_in[10];
    const float* sb2 = (const float*)d_in[11];
    float* out = (float*)d_out;

    void* p;
    cudaGetSymbolAddress(&p, g_Hs); float* Hs = (float*)p;
    cudaGetSymbolAddress(&p, g_Hr); float* Hr = (float*)p;
    cudaGetSymbolAddress(&p, g_Yr); float* Yr = (float*)p;

    cudaFuncSetAttribute(mma_mlp<DIM, HID, true >, cudaFuncAttributeMaxDynamicSharedMemorySize, SMEM_SZ);
    cudaFuncSetAttribute(mma_mlp<HID, DIM, false>, cudaFuncAttributeMaxDynamicSharedMemorySize, SMEM_SZ);

    init_kernel<<<1, 32>>>();
    gate_kernel<<<N_TOK, 128>>>(x, gW, gb, rb);
    aux_kernel<<<1, 256>>>(out, out_size);

    // MLP1 (merged routed + shared): x -> Hr (slots, gelu), Hs (tokens, gelu)
    mma_mlp<DIM, HID, true ><<<dim3(N_TOK / TBM, HID / TBN, NE + 1), 256, SMEM_SZ>>>(
        x, x, W1, sW1, b1, sb1, Hr, Hs);
    // MLP2 (merged): Hr -> Yr (*tw), Hs -> out
    mma_mlp<HID, DIM, false><<<dim3(N_TOK / TBM, DIM / TBN, NE + 1), 256, SMEM_SZ>>>(
        Hr, Hs, W2, sW2, b2, sb2, Yr, out);

    combine_kernel<<<(N_TOK * (DIM / 4) + 255) / 256, 256>>>(out);
}

// round 5
// speedup vs baseline: 1.1279x; 1.1279x over previous
#include <cuda_runtime.h>
#include <cuda_bf16.h>
#include <math.h>
#include <stdint.h>

#define N_TOK 4096
#define DIM   1024
#define HID   768
#define NE    23
#define TOPK  3
#define NSLOT (N_TOK * TOPK)

#define TBM 128
#define TBN 64
#define TBK 32
#define A_STRIDE 80      // 64B data + 16B pad
#define B_STRIDE 144     // 128B data + 16B pad
#define AH_OFF 0
#define AL_OFF 10240
#define BH_OFF 20480
#define BL_OFF 25088
#define STG    29696
#define SMEM_SZ (2 * STG)   // 59392

// ---------------- scratch ----------------
__device__ float g_gw[(size_t)N_TOK * NE];
__device__ int   g_counts[NE];
__device__ int   g_list[(size_t)NE * N_TOK];
__device__ float g_tw[NSLOT];
__device__ float g_Hs[(size_t)N_TOK * HID];
__device__ float g_Hr[(size_t)NSLOT * HID];
__device__ float g_Yr[(size_t)NSLOT * DIM];

__device__ __forceinline__ float gelu_exact(float v) {
    return 0.5f * v * (1.0f + erff(v * 0.7071067811865476f));
}
__device__ __forceinline__ uint32_t smem_u32(const void* p) {
    uint32_t a;
    asm("{ .reg .u64 t; cvta.to.shared.u64 t, %1; cvt.u32.u64 %0, t; }" : "=r"(a) : "l"(p));
    return a;
}
__device__ __forceinline__ void ldsm_x4(uint32_t addr, uint32_t* r) {
    asm volatile("ldmatrix.sync.aligned.m8n8.x4.shared.b16 {%0,%1,%2,%3}, [%4];"
                 : "=r"(r[0]), "=r"(r[1]), "=r"(r[2]), "=r"(r[3]) : "r"(addr));
}
__device__ __forceinline__ void ldsm_x4_t(uint32_t addr, uint32_t* r) {
    asm volatile("ldmatrix.sync.aligned.m8n8.x4.trans.shared.b16 {%0,%1,%2,%3}, [%4];"
                 : "=r"(r[0]), "=r"(r[1]), "=r"(r[2]), "=r"(r[3]) : "r"(addr));
}
__device__ __forceinline__ void mma_bf16(float* c, const uint32_t* a, uint32_t b0, uint32_t b1) {
    asm volatile("mma.sync.aligned.m16n8k16.row.col.f32.bf16.bf16.f32 "
                 "{%0,%1,%2,%3}, {%4,%5,%6,%7}, {%8,%9}, {%0,%1,%2,%3};"
                 : "+f"(c[0]), "+f"(c[1]), "+f"(c[2]), "+f"(c[3])
                 : "r"(a[0]), "r"(a[1]), "r"(a[2]), "r"(a[3]), "r"(b0), "r"(b1));
}
__device__ __forceinline__ uint32_t pack2(__nv_bfloat16 a, __nv_bfloat16 b) {
    return (uint32_t)__bfloat16_as_ushort(a) | ((uint32_t)__bfloat16_as_ushort(b) << 16);
}
__device__ __forceinline__ void split4(float4 v, uint2& h, uint2& l) {
    float vv[4] = {v.x, v.y, v.z, v.w};
    __nv_bfloat16 hh[4], ll[4];
    #pragma unroll
    for (int q = 0; q < 4; q++) {
        hh[q] = __float2bfloat16(vv[q]);
        ll[q] = __float2bfloat16(vv[q] - __bfloat162float(hh[q]));
    }
    h = make_uint2(pack2(hh[0], hh[1]), pack2(hh[2], hh[3]));
    l = make_uint2(pack2(ll[0], ll[1]), pack2(ll[2], ll[3]));
}

// ---------------- init ----------------
__global__ void init_kernel() {
    int t = threadIdx.x;
    if (t < NE) g_counts[t] = 0;
}

// ---------------- gate (known-correct) ----------------
__global__ void gate_kernel(const float* __restrict__ x,
                            const float* __restrict__ gW,
                            const float* __restrict__ gb,
                            const float* __restrict__ rbias)
{
    __shared__ float xs[DIM];
    __shared__ float gv[NE];
    __shared__ float gsum_s;
    int n = blockIdx.x;
    int t = threadIdx.x;

    const float4* xv  = (const float4*)(x + (size_t)n * DIM);
    float4*       xsv = (float4*)xs;
    for (int i = t; i < DIM / 4; i += 128) xsv[i] = xv[i];
    __syncthreads();

    int e = t >> 2, j = t & 3;
    float acc = 0.f;
    if (e < NE) {
        for (int i = j; i < DIM; i += 4)
            acc += xs[i] * gW[i * NE + e];
    }
    acc += __shfl_xor_sync(0xffffffffu, acc, 1);
    acc += __shfl_xor_sync(0xffffffffu, acc, 2);
    if (e < NE && j == 0)
        gv[e] = 1.0f / (1.0f + expf(-(acc + gb[e])));
    __syncthreads();

    if (t == 0) {
        float s = 0.f;
        for (int q = 0; q < NE; q++) s += gv[q];
        gsum_s = s;
    }
    __syncthreads();

    if (t < NE) g_gw[(size_t)n * NE + t] = gv[t] / gsum_s;

    if (t == 0) {
        int   idx[TOPK];
        float w[TOPK];
        unsigned used = 0;
        for (int k = 0; k < TOPK; k++) {
            float best = -1e30f; int bi = 0;
            for (int q = 0; q < NE; q++) {
                if (used & (1u << q)) continue;
                float s = gv[q] + rbias[q];
                if (s > best) { best = s; bi = q; }
            }
            used |= (1u << bi);
            idx[k] = bi;
            w[k]   = gv[bi];
        }
        float ws = w[0] + w[1] + w[2];
        for (int k = 0; k < TOPK; k++) {
            int slot = n * TOPK + k;
            g_tw[slot] = w[k] / ws;
            int pos = atomicAdd(&g_counts[idx[k]], 1);
            g_list[(size_t)idx[k] * N_TOK + pos] = slot;
        }
    }
}

// ---------------- aux loss ----------------
__global__ void aux_kernel(float* __restrict__ out, int out_size)
{
    __shared__ float sm[256 * NE];
    int t = threadIdx.x;
    float loc[NE];
    #pragma unroll
    for (int e = 0; e < NE; e++) loc[e] = 0.f;
    for (int n = t; n < N_TOK; n += 256) {
        #pragma unroll
        for (int e = 0; e < NE; e++) loc[e] += g_gw[(size_t)n * NE + e];
    }
    for (int e = 0; e < NE; e++) sm[t * NE + e] = loc[e];
    __syncthreads();
    for (int s = 128; s > 0; s >>= 1) {
        if (t < s)
            for (int e = 0; e < NE; e++) sm[t * NE + e] += sm[(t + s) * NE + e];
        __syncthreads();
    }
    if (t == 0 && out_size > N_TOK * DIM) {
        float aux = 0.f;
        for (int e = 0; e < NE; e++) {
            float P = sm[e] / (float)N_TOK;
            float F = ((float)NE * (float)g_counts[e]) / ((float)TOPK * (float)N_TOK);
            aux += P * F;
        }
        out[(size_t)N_TOK * DIM] = aux;
    }
}

// ---------------- merged bf16 3-term split GEMM (128x64 tile, occ=2) ----------------
// blockIdx.z in [0, NE]: z<NE -> routed expert z; z==NE -> shared expert.
template<int KDIM, int NOUT, bool MLP1>
__global__ void __launch_bounds__(256, 2) mma_mlp(
    const float* __restrict__ Ar, const float* __restrict__ Ash,
    const float* __restrict__ Br, const float* __restrict__ Bsh,
    const float* __restrict__ biasR, const float* __restrict__ biasS,
    float* __restrict__ OutR, float* __restrict__ OutS)
{
    constexpr int NC = KDIM / TBK;

    int ez = blockIdx.z;
    bool sh = (ez == NE);
    int cnt = sh ? N_TOK : g_counts[ez];
    int m0  = blockIdx.x * TBM;
    if (m0 >= cnt) return;
    int n0  = blockIdx.y * TBN;

    extern __shared__ char smem[];
    uint32_t sbase = smem_u32(smem);

    int tid  = threadIdx.x;
    int wid  = tid >> 5;
    int lane = tid & 31;
    int wm   = wid >> 1;   // 0..3 : rows wm*32..+31
    int wn   = wid & 1;    // 0..1 : cols wn*32..+31

    const float* A    = sh ? Ash : Ar;
    const float* Bgz  = sh ? Bsh : (Br + (size_t)ez * KDIM * NOUT);
    const float* bias = sh ? biasS : (biasR + (size_t)ez * NOUT);

    // ---- loader setup ----
    // A: thread t -> row t>>1, k-half t&1 (16 floats)
    int arow = tid >> 1;
    int ah   = tid & 1;
    int gi_a = m0 + arow;
    int grow;
    if (sh) {
        grow = gi_a;
    } else {
        int gg   = (gi_a < cnt) ? gi_a : (cnt - 1);
        int slot = g_list[(size_t)ez * N_TOK + gg];
        grow = MLP1 ? (slot / TOPK) : slot;
    }
    const float* Aptr = A + (size_t)grow * KDIM + ah * 16;
    uint32_t aoff = (uint32_t)(arow * A_STRIDE + ah * 32);

    // B: thread t -> k-row t>>3 (0..31), col group t&7; 2 float4 (cols bc*4, bc*4+32)
    int bk = tid >> 3;
    int bc = tid & 7;
    const float* Bptr = Bgz + (size_t)bk * NOUT + n0 + bc * 4;
    uint32_t boff = (uint32_t)(bk * B_STRIDE + bc * 8);

    float4 fa[4], fb[2];
    #pragma unroll
    for (int q = 0; q < 4; q++) fa[q] = *(const float4*)(Aptr + q * 4);
    fb[0] = *(const float4*)(Bptr);
    fb[1] = *(const float4*)(Bptr + 32);

    // store chunk 0 -> stage 0
    {
        char* st = smem;
        #pragma unroll
        for (int q = 0; q < 4; q++) {
            uint2 h, l;
            split4(fa[q], h, l);
            *(uint2*)(st + AH_OFF + aoff + q * 8) = h;
            *(uint2*)(st + AL_OFF + aoff + q * 8) = l;
        }
        #pragma unroll
        for (int q = 0; q < 2; q++) {
            uint2 h, l;
            split4(fb[q], h, l);
            *(uint2*)(st + BH_OFF + boff + q * 64) = h;
            *(uint2*)(st + BL_OFF + boff + q * 64) = l;
        }
    }
    __syncthreads();
    // prefetch chunk 1
    if (NC > 1) {
        #pragma unroll
        for (int q = 0; q < 4; q++) fa[q] = *(const float4*)(Aptr + TBK + q * 4);
        fb[0] = *(const float4*)(Bptr + (size_t)TBK * NOUT);
        fb[1] = *(const float4*)(Bptr + (size_t)TBK * NOUT + 32);
    }

    float acc[2][4][4];
    #pragma unroll
    for (int i = 0; i < 2; i++)
        #pragma unroll
        for (int j = 0; j < 4; j++)
            #pragma unroll
            for (int q = 0; q < 4; q++) acc[i][j][q] = 0.f;

    uint32_t aAddr = sbase + AH_OFF + (uint32_t)((wm * 32 + (lane & 15)) * A_STRIDE + ((lane >> 4) << 4));
    uint32_t bAddr = sbase + BH_OFF + (uint32_t)((lane & 15) * B_STRIDE + ((wn * 32 + (lane >> 4) * 8) << 1));

    for (int c = 0; c < NC; c++) {
        int s = c & 1;
        // store prefetched chunk c+1 into other stage (overlaps with mma below)
        if (c + 1 < NC) {
            char* st = smem + (s ^ 1) * STG;
            #pragma unroll
            for (int q = 0; q < 4; q++) {
                uint2 h, l;
                split4(fa[q], h, l);
                *(uint2*)(st + AH_OFF + aoff + q * 8) = h;
                *(uint2*)(st + AL_OFF + aoff + q * 8) = l;
            }
            #pragma unroll
            for (int q = 0; q < 2; q++) {
                uint2 h, l;
                split4(fb[q], h, l);
                *(uint2*)(st + BH_OFF + boff + q * 64) = h;
                *(uint2*)(st + BL_OFF + boff + q * 64) = l;
            }
            // issue global prefetch for chunk c+2
            if (c + 2 < NC) {
                int k0 = (c + 2) * TBK;
                #pragma unroll
                for (int q = 0; q < 4; q++) fa[q] = *(const float4*)(Aptr + k0 + q * 4);
                fb[0] = *(const float4*)(Bptr + (size_t)k0 * NOUT);
                fb[1] = *(const float4*)(Bptr + (size_t)k0 * NOUT + 32);
            }
        }
        // compute from stage s
        uint32_t aS = aAddr + (uint32_t)(s * STG);
        uint32_t bS = bAddr + (uint32_t)(s * STG);
        #pragma unroll
        for (int ks = 0; ks < 2; ks++) {
            uint32_t ahF[2][4], alF[2][4];
            #pragma unroll
            for (int i = 0; i < 2; i++) {
                ldsm_x4(aS + ks * 32 + i * (16 * A_STRIDE), ahF[i]);
                ldsm_x4(aS + ks * 32 + i * (16 * A_STRIDE) + (AL_OFF - AH_OFF), alF[i]);
            }
            uint32_t bhF[2][4], blF[2][4];
            #pragma unroll
            for (int g = 0; g < 2; g++) {
                ldsm_x4_t(bS + ks * (16 * B_STRIDE) + g * 32, bhF[g]);
                ldsm_x4_t(bS + ks * (16 * B_STRIDE) + g * 32 + (BL_OFF - BH_OFF), blF[g]);
            }
            #pragma unroll
            for (int i = 0; i < 2; i++) {
                #pragma unroll
                for (int j = 0; j < 4; j++) {
                    int g = j >> 1, o = (j & 1) * 2;
                    mma_bf16(acc[i][j], ahF[i], bhF[g][o], bhF[g][o + 1]);
                    mma_bf16(acc[i][j], ahF[i], blF[g][o], blF[g][o + 1]);
                    mma_bf16(acc[i][j], alF[i], bhF[g][o], bhF[g][o + 1]);
                }
            }
        }
        __syncthreads();
    }

    // ---- epilogue: frags -> smem (128 x 68 fp32), then coalesced global ----
    float* epi = (float*)smem;
    {
        int rb = wm * 32 + (lane >> 2);
        int cb = wn * 32 + (lane & 3) * 2;
        #pragma unroll
        for (int i = 0; i < 2; i++) {
            #pragma unroll
            for (int j = 0; j < 4; j++) {
                int r = rb + i * 16;
                int cc = cb + j * 8;
                epi[r * 68 + cc]           = acc[i][j][0];
                epi[r * 68 + cc + 1]       = acc[i][j][1];
                epi[(r + 8) * 68 + cc]     = acc[i][j][2];
                epi[(r + 8) * 68 + cc + 1] = acc[i][j][3];
            }
        }
    }
    __syncthreads();

    for (int i = tid; i < TBM * (TBN / 4); i += 256) {
        int r  = i >> 4;
        int c4 = i & 15;
        int gi = m0 + r;
        if (gi >= cnt) continue;
        float4 v = *(float4*)&epi[r * 68 + c4 * 4];
        int col = n0 + c4 * 4;
        float4 b4 = *(const float4*)(bias + col);
        v.x += b4.x; v.y += b4.y; v.z += b4.z; v.w += b4.w;
        float* Out;
        size_t orow;
        if (sh) {
            Out = OutS; orow = (size_t)gi;
        } else {
            int slot = g_list[(size_t)ez * N_TOK + gi];
            Out = OutR; orow = (size_t)slot;
            if (!MLP1) {
                float w = g_tw[slot];
                v.x *= w; v.y *= w; v.z *= w; v.w *= w;
            }
        }
        if (MLP1) {
            v.x = gelu_exact(v.x); v.y = gelu_exact(v.y);
            v.z = gelu_exact(v.z); v.w = gelu_exact(v.w);
        }
        *(float4*)(Out + orow * NOUT + col) = v;
    }
}

// ---------------- combine ----------------
__global__ void combine_kernel(float* __restrict__ out)
{
    int idx = blockIdx.x * blockDim.x + threadIdx.x;
    if (idx >= N_TOK * (DIM / 4)) return;
    int n  = idx / (DIM / 4);
    int d4 = idx % (DIM / 4);
    float4 v = ((float4*)out)[idx];
    const float4* yr = (const float4*)g_Yr;
    #pragma unroll
    for (int k = 0; k < TOPK; k++) {
        float4 y = yr[(size_t)(n * TOPK + k) * (DIM / 4) + d4];
        v.x += y.x; v.y += y.y; v.z += y.z; v.w += y.w;
    }
    ((float4*)out)[idx] = v;
}

// ---------------- launch ----------------
extern "C" void kernel_launch(void* const* d_in, const int* in_sizes, int n_in,
                              void* d_out, int out_size)
{
    const float* x   = (const float*)d_in[0];
    const float* gW  = (const float*)d_in[1];
    const float* gb  = (const float*)d_in[2];
    const float* rb  = (const float*)d_in[3];
    const float* W1  = (const float*)d_in[4];
    const float* b1  = (const float*)d_in[5];
    const float* W2  = (const float*)d_in[6];
    const float* b2  = (const float*)d_in[7];
    const float* sW1 = (const float*)d_in[8];
    const float* sb1 = (const float*)d_in[9];
    const float* sW2 = (const float*)d_in[10];
    const float* sb2 = (const float*)d_in[11];
    float* out = (float*)d_out;

    void* p;
    cudaGetSymbolAddress(&p, g_Hs); float* Hs = (float*)p;
    cudaGetSymbolAddress(&p, g_Hr); float* Hr = (float*)p;
    cudaGetSymbolAddress(&p, g_Yr); float* Yr = (float*)p;

    cudaFuncSetAttribute(mma_mlp<DIM, HID, true >, cudaFuncAttributeMaxDynamicSharedMemorySize, SMEM_SZ);
    cudaFuncSetAttribute(mma_mlp<HID, DIM, false>, cudaFuncAttributeMaxDynamicSharedMemorySize, SMEM_SZ);

    init_kernel<<<1, 32>>>();
    gate_kernel<<<N_TOK, 128>>>(x, gW, gb, rb);
    aux_kernel<<<1, 256>>>(out, out_size);

    // MLP1 (merged routed + shared): x -> Hr (slots, gelu), Hs (tokens, gelu)
    mma_mlp<DIM, HID, true ><<<dim3(N_TOK / TBM, HID / TBN, NE + 1), 256, SMEM_SZ>>>(
        x, x, W1, sW1, b1, sb1, Hr, Hs);
    // MLP2 (merged): Hr -> Yr (*tw), Hs -> out
    mma_mlp<HID, DIM, false><<<dim3(N_TOK / TBM, DIM / TBN, NE + 1), 256, SMEM_SZ>>>(
        Hr, Hs, W2, sW2, b2, sb2, Yr, out);

    combine_kernel<<<(N_TOK * (DIM / 4) + 255) / 256, 256>>>(out);
}

// round 6
// speedup vs baseline: 1.1733x; 1.0403x over previous
#include <cuda_runtime.h>
#include <cuda_bf16.h>
#include <math.h>
#include <stdint.h>

#define N_TOK 4096
#define DIM   1024
#define HID   768
#define NE    23
#define TOPK  3
#define NSLOT (N_TOK * TOPK)

#define TBM 128
#define TBN 64
#define TBK 32
#define A_STRIDE 80      // 64B data + 16B pad
#define B_STRIDE 144     // 128B data + 16B pad
#define AH_OFF 0
#define AL_OFF 10240
#define BH_OFF 20480
#define BL_OFF 25088
#define STG    29696
#define NSTAGE 3
#define SMEM_SZ (NSTAGE * STG)   // 89088

// ---------------- scratch ----------------
__device__ float g_gw[(size_t)N_TOK * NE];
__device__ int   g_counts[NE];
__device__ int   g_list[(size_t)NE * N_TOK];
__device__ float g_tw[NSLOT];
__device__ float g_Yr[(size_t)NSLOT * DIM];

// pre-split bf16 operands
__device__ __nv_bfloat16 g_xh[(size_t)N_TOK * DIM];
__device__ __nv_bfloat16 g_xl[(size_t)N_TOK * DIM];
__device__ __nv_bfloat16 g_W1h[(size_t)NE * DIM * HID];
__device__ __nv_bfloat16 g_W1l[(size_t)NE * DIM * HID];
__device__ __nv_bfloat16 g_W2h[(size_t)NE * HID * DIM];
__device__ __nv_bfloat16 g_W2l[(size_t)NE * HID * DIM];
__device__ __nv_bfloat16 g_sW1h[(size_t)DIM * HID];
__device__ __nv_bfloat16 g_sW1l[(size_t)DIM * HID];
__device__ __nv_bfloat16 g_sW2h[(size_t)HID * DIM];
__device__ __nv_bfloat16 g_sW2l[(size_t)HID * DIM];
__device__ __nv_bfloat16 g_Hsh[(size_t)N_TOK * HID];
__device__ __nv_bfloat16 g_Hsl[(size_t)N_TOK * HID];
__device__ __nv_bfloat16 g_Hrh[(size_t)NSLOT * HID];
__device__ __nv_bfloat16 g_Hrl[(size_t)NSLOT * HID];

__device__ __forceinline__ float gelu_exact(float v) {
    return 0.5f * v * (1.0f + erff(v * 0.7071067811865476f));
}
__device__ __forceinline__ uint32_t smem_u32(const void* p) {
    uint32_t a;
    asm("{ .reg .u64 t; cvta.to.shared.u64 t, %1; cvt.u32.u64 %0, t; }" : "=r"(a) : "l"(p));
    return a;
}
__device__ __forceinline__ void ldsm_x4(uint32_t addr, uint32_t* r) {
    asm volatile("ldmatrix.sync.aligned.m8n8.x4.shared.b16 {%0,%1,%2,%3}, [%4];"
                 : "=r"(r[0]), "=r"(r[1]), "=r"(r[2]), "=r"(r[3]) : "r"(addr));
}
__device__ __forceinline__ void ldsm_x4_t(uint32_t addr, uint32_t* r) {
    asm volatile("ldmatrix.sync.aligned.m8n8.x4.trans.shared.b16 {%0,%1,%2,%3}, [%4];"
                 : "=r"(r[0]), "=r"(r[1]), "=r"(r[2]), "=r"(r[3]) : "r"(addr));
}
__device__ __forceinline__ void mma_bf16(float* c, const uint32_t* a, uint32_t b0, uint32_t b1) {
    asm volatile("mma.sync.aligned.m16n8k16.row.col.f32.bf16.bf16.f32 "
                 "{%0,%1,%2,%3}, {%4,%5,%6,%7}, {%8,%9}, {%0,%1,%2,%3};"
                 : "+f"(c[0]), "+f"(c[1]), "+f"(c[2]), "+f"(c[3])
                 : "r"(a[0]), "r"(a[1]), "r"(a[2]), "r"(a[3]), "r"(b0), "r"(b1));
}
__device__ __forceinline__ void cpa16(uint32_t dst, const void* src) {
    asm volatile("cp.async.cg.shared.global [%0], [%1], 16;" :: "r"(dst), "l"(src));
}
__device__ __forceinline__ void cpa_commit() {
    asm volatile("cp.async.commit_group;");
}
template<int N> __device__ __forceinline__ void cpa_wait() {
    asm volatile("cp.async.wait_group %0;" :: "n"(N));
}
__device__ __forceinline__ uint32_t pack2(__nv_bfloat16 a, __nv_bfloat16 b) {
    return (uint32_t)__bfloat16_as_ushort(a) | ((uint32_t)__bfloat16_as_ushort(b) << 16);
}
__device__ __forceinline__ void split4(float4 v, uint2& h, uint2& l) {
    float vv[4] = {v.x, v.y, v.z, v.w};
    __nv_bfloat16 hh[4], ll[4];
    #pragma unroll
    for (int q = 0; q < 4; q++) {
        hh[q] = __float2bfloat16(vv[q]);
        ll[q] = __float2bfloat16(vv[q] - __bfloat162float(hh[q]));
    }
    h = make_uint2(pack2(hh[0], hh[1]), pack2(hh[2], hh[3]));
    l = make_uint2(pack2(ll[0], ll[1]), pack2(ll[2], ll[3]));
}

// ---------------- prep: elementwise fp32 -> bf16 hi/lo ----------------
__global__ void split_kernel(const float4* __restrict__ src,
                             uint2* __restrict__ h, uint2* __restrict__ l, int n4)
{
    int i = blockIdx.x * 256 + threadIdx.x;
    if (i < n4) {
        uint2 hh, ll;
        split4(src[i], hh, ll);
        h[i] = hh;
        l[i] = ll;
    }
}

// ---------------- init ----------------
__global__ void init_kernel() {
    int t = threadIdx.x;
    if (t < NE) g_counts[t] = 0;
}

// ---------------- gate (known-correct) ----------------
__global__ void gate_kernel(const float* __restrict__ x,
                            const float* __restrict__ gW,
                            const float* __restrict__ gb,
                            const float* __restrict__ rbias)
{
    __shared__ float xs[DIM];
    __shared__ float gv[NE];
    __shared__ float gsum_s;
    int n = blockIdx.x;
    int t = threadIdx.x;

    const float4* xv  = (const float4*)(x + (size_t)n * DIM);
    float4*       xsv = (float4*)xs;
    for (int i = t; i < DIM / 4; i += 128) xsv[i] = xv[i];
    __syncthreads();

    int e = t >> 2, j = t & 3;
    float acc = 0.f;
    if (e < NE) {
        for (int i = j; i < DIM; i += 4)
            acc += xs[i] * gW[i * NE + e];
    }
    acc += __shfl_xor_sync(0xffffffffu, acc, 1);
    acc += __shfl_xor_sync(0xffffffffu, acc, 2);
    if (e < NE && j == 0)
        gv[e] = 1.0f / (1.0f + expf(-(acc + gb[e])));
    __syncthreads();

    if (t == 0) {
        float s = 0.f;
        for (int q = 0; q < NE; q++) s += gv[q];
        gsum_s = s;
    }
    __syncthreads();

    if (t < NE) g_gw[(size_t)n * NE + t] = gv[t] / gsum_s;

    if (t == 0) {
        int   idx[TOPK];
        float w[TOPK];
        unsigned used = 0;
        for (int k = 0; k < TOPK; k++) {
            float best = -1e30f; int bi = 0;
            for (int q = 0; q < NE; q++) {
                if (used & (1u << q)) continue;
                float s = gv[q] + rbias[q];
                if (s > best) { best = s; bi = q; }
            }
            used |= (1u << bi);
            idx[k] = bi;
            w[k]   = gv[bi];
        }
        float ws = w[0] + w[1] + w[2];
        for (int k = 0; k < TOPK; k++) {
            int slot = n * TOPK + k;
            g_tw[slot] = w[k] / ws;
            int pos = atomicAdd(&g_counts[idx[k]], 1);
            g_list[(size_t)idx[k] * N_TOK + pos] = slot;
        }
    }
}

// ---------------- aux loss ----------------
__global__ void aux_kernel(float* __restrict__ out, int out_size)
{
    __shared__ float sm[256 * NE];
    int t = threadIdx.x;
    float loc[NE];
    #pragma unroll
    for (int e = 0; e < NE; e++) loc[e] = 0.f;
    for (int n = t; n < N_TOK; n += 256) {
        #pragma unroll
        for (int e = 0; e < NE; e++) loc[e] += g_gw[(size_t)n * NE + e];
    }
    for (int e = 0; e < NE; e++) sm[t * NE + e] = loc[e];
    __syncthreads();
    for (int s = 128; s > 0; s >>= 1) {
        if (t < s)
            for (int e = 0; e < NE; e++) sm[t * NE + e] += sm[(t + s) * NE + e];
        __syncthreads();
    }
    if (t == 0 && out_size > N_TOK * DIM) {
        float aux = 0.f;
        for (int e = 0; e < NE; e++) {
            float P = sm[e] / (float)N_TOK;
            float F = ((float)NE * (float)g_counts[e]) / ((float)TOPK * (float)N_TOK);
            aux += P * F;
        }
        out[(size_t)N_TOK * DIM] = aux;
    }
}

// ---------------- cp.async 3-stage bf16 3-term split GEMM ----------------
// blockIdx.z in [0, NE]: z<NE -> routed expert z; z==NE -> shared expert.
// MLP1P: Out = gelu(D+bias) -> bf16 hi/lo; else Out = (D+bias)[*tw] fp32
template<int KDIM, int NOUT, bool MLP1P>
__global__ void __launch_bounds__(256, 2) mma_mlp(
    const __nv_bfloat16* __restrict__ ArH, const __nv_bfloat16* __restrict__ ArL,
    const __nv_bfloat16* __restrict__ AsH, const __nv_bfloat16* __restrict__ AsL,
    const __nv_bfloat16* __restrict__ BrH, const __nv_bfloat16* __restrict__ BrL,
    const __nv_bfloat16* __restrict__ BsH, const __nv_bfloat16* __restrict__ BsL,
    const float* __restrict__ biasR, const float* __restrict__ biasS,
    float* __restrict__ OutRF, float* __restrict__ OutSF,
    __nv_bfloat16* __restrict__ OutRH, __nv_bfloat16* __restrict__ OutRL,
    __nv_bfloat16* __restrict__ OutSH, __nv_bfloat16* __restrict__ OutSL)
{
    constexpr int NC = KDIM / TBK;

    int ez = blockIdx.z;
    bool sh = (ez == NE);
    int cnt = sh ? N_TOK : g_counts[ez];
    int m0  = blockIdx.x * TBM;
    if (m0 >= cnt) return;
    int n0  = blockIdx.y * TBN;

    extern __shared__ char smem[];
    uint32_t sbase = smem_u32(smem);

    int tid  = threadIdx.x;
    int wid  = tid >> 5;
    int lane = tid & 31;
    int wm   = wid >> 1;   // 0..3
    int wn   = wid & 1;    // 0..1

    const __nv_bfloat16* AH = sh ? AsH : ArH;
    const __nv_bfloat16* AL = sh ? AsL : ArL;
    const __nv_bfloat16* BH = sh ? BsH : (BrH + (size_t)ez * KDIM * NOUT);
    const __nv_bfloat16* BL = sh ? BsL : (BrL + (size_t)ez * KDIM * NOUT);
    const float* bias = sh ? biasS : (biasR + (size_t)ez * NOUT);

    // ---- loader setup ----
    // A: thread t -> row t>>1, k-half t&1 (16 elems = 2x16B)
    int arow = tid >> 1;
    int au   = tid & 1;
    int gi_a = m0 + arow;
    int grow;
    if (sh) {
        grow = gi_a;
    } else {
        int gg   = (gi_a < cnt) ? gi_a : (cnt - 1);
        int slot = g_list[(size_t)ez * N_TOK + gg];
        grow = MLP1P ? (slot / TOPK) : slot;
    }
    const __nv_bfloat16* ApH = AH + (size_t)grow * KDIM + au * 16;
    const __nv_bfloat16* ApL = AL + (size_t)grow * KDIM + au * 16;
    uint32_t aoff = (uint32_t)(arow * A_STRIDE + au * 32);

    // B: thread t -> k-row t>>3 (0..31), 16B col unit t&7
    int bk = tid >> 3;
    int bc = tid & 7;
    const __nv_bfloat16* BpH = BH + (size_t)bk * NOUT + n0 + bc * 8;
    const __nv_bfloat16* BpL = BL + (size_t)bk * NOUT + n0 + bc * 8;
    uint32_t boff = (uint32_t)(bk * B_STRIDE + bc * 16);

    auto issue_chunk = [&](int c, int st) {
        uint32_t sB = sbase + (uint32_t)(st * STG);
        int k0 = c * TBK;
        cpa16(sB + AH_OFF + aoff,      ApH + k0);
        cpa16(sB + AH_OFF + aoff + 16, ApH + k0 + 8);
        cpa16(sB + AL_OFF + aoff,      ApL + k0);
        cpa16(sB + AL_OFF + aoff + 16, ApL + k0 + 8);
        cpa16(sB + BH_OFF + boff,      BpH + (size_t)k0 * NOUT);
        cpa16(sB + BL_OFF + boff,      BpL + (size_t)k0 * NOUT);
        cpa_commit();
    };

    issue_chunk(0, 0);
    if (NC > 1) issue_chunk(1, 1);

    float acc[2][4][4];
    #pragma unroll
    for (int i = 0; i < 2; i++)
        #pragma unroll
        for (int j = 0; j < 4; j++)
            #pragma unroll
            for (int q = 0; q < 4; q++) acc[i][j][q] = 0.f;

    uint32_t aAddr = sbase + AH_OFF + (uint32_t)((wm * 32 + (lane & 15)) * A_STRIDE + ((lane >> 4) << 4));
    uint32_t bAddr = sbase + BH_OFF + (uint32_t)((lane & 15) * B_STRIDE + ((wn * 32 + (lane >> 4) * 8) << 1));

    int st = 0;
    for (int c = 0; c < NC; c++) {
        if (c + 1 < NC) cpa_wait<1>(); else cpa_wait<0>();
        __syncthreads();
        if (c + 2 < NC) {
            int st2 = st + 2; if (st2 >= NSTAGE) st2 -= NSTAGE;
            issue_chunk(c + 2, st2);
        }
        uint32_t aS = aAddr + (uint32_t)(st * STG);
        uint32_t bS = bAddr + (uint32_t)(st * STG);
        #pragma unroll
        for (int ks = 0; ks < 2; ks++) {
            uint32_t ahF[2][4], alF[2][4];
            #pragma unroll
            for (int i = 0; i < 2; i++) {
                ldsm_x4(aS + ks * 32 + i * (16 * A_STRIDE), ahF[i]);
                ldsm_x4(aS + ks * 32 + i * (16 * A_STRIDE) + (AL_OFF - AH_OFF), alF[i]);
            }
            uint32_t bhF[2][4], blF[2][4];
            #pragma unroll
            for (int g = 0; g < 2; g++) {
                ldsm_x4_t(bS + ks * (16 * B_STRIDE) + g * 32, bhF[g]);
                ldsm_x4_t(bS + ks * (16 * B_STRIDE) + g * 32 + (BL_OFF - BH_OFF), blF[g]);
            }
            #pragma unroll
            for (int i = 0; i < 2; i++) {
                #pragma unroll
                for (int j = 0; j < 4; j++) {
                    int g = j >> 1, o = (j & 1) * 2;
                    mma_bf16(acc[i][j], ahF[i], bhF[g][o], bhF[g][o + 1]);
                    mma_bf16(acc[i][j], ahF[i], blF[g][o], blF[g][o + 1]);
                    mma_bf16(acc[i][j], alF[i], bhF[g][o], bhF[g][o + 1]);
                }
            }
        }
        if (++st == NSTAGE) st = 0;
        __syncthreads();
    }

    // ---- epilogue: frags -> smem (128 x 68 fp32), then coalesced global ----
    float* epi = (float*)smem;
    {
        int rb = wm * 32 + (lane >> 2);
        int cb = wn * 32 + (lane & 3) * 2;
        #pragma unroll
        for (int i = 0; i < 2; i++) {
            #pragma unroll
            for (int j = 0; j < 4; j++) {
                int r = rb + i * 16;
                int cc = cb + j * 8;
                epi[r * 68 + cc]           = acc[i][j][0];
                epi[r * 68 + cc + 1]       = acc[i][j][1];
                epi[(r + 8) * 68 + cc]     = acc[i][j][2];
                epi[(r + 8) * 68 + cc + 1] = acc[i][j][3];
            }
        }
    }
    __syncthreads();

    for (int i = tid; i < TBM * (TBN / 4); i += 256) {
        int r  = i >> 4;
        int c4 = i & 15;
        int gi = m0 + r;
        if (gi >= cnt) continue;
        float4 v = *(float4*)&epi[r * 68 + c4 * 4];
        int col = n0 + c4 * 4;
        float4 b4 = *(const float4*)(bias + col);
        v.x += b4.x; v.y += b4.y; v.z += b4.z; v.w += b4.w;
        if (MLP1P) {
            v.x = gelu_exact(v.x); v.y = gelu_exact(v.y);
            v.z = gelu_exact(v.z); v.w = gelu_exact(v.w);
            uint2 h, l;
            split4(v, h, l);
            size_t orow;
            __nv_bfloat16 *OH, *OL;
            if (sh) { orow = (size_t)gi; OH = OutSH; OL = OutSL; }
            else    { orow = (size_t)g_list[(size_t)ez * N_TOK + gi]; OH = OutRH; OL = OutRL; }
            *(uint2*)(OH + orow * NOUT + col) = h;
            *(uint2*)(OL + orow * NOUT + col) = l;
        } else {
            float* Out;
            size_t orow;
            if (sh) {
                Out = OutSF; orow = (size_t)gi;
            } else {
                int slot = g_list[(size_t)ez * N_TOK + gi];
                Out = OutRF; orow = (size_t)slot;
                float w = g_tw[slot];
                v.x *= w; v.y *= w; v.z *= w; v.w *= w;
            }
            *(float4*)(Out + orow * NOUT + col) = v;
        }
    }
}

// ---------------- combine ----------------
__global__ void combine_kernel(float* __restrict__ out)
{
    int idx = blockIdx.x * blockDim.x + threadIdx.x;
    if (idx >= N_TOK * (DIM / 4)) return;
    int n  = idx / (DIM / 4);
    int d4 = idx % (DIM / 4);
    float4 v = ((float4*)out)[idx];
    const float4* yr = (const float4*)g_Yr;
    #pragma unroll
    for (int k = 0; k < TOPK; k++) {
        float4 y = yr[(size_t)(n * TOPK + k) * (DIM / 4) + d4];
        v.x += y.x; v.y += y.y; v.z += y.z; v.w += y.w;
    }
    ((float4*)out)[idx] = v;
}

// ---------------- launch ----------------
extern "C" void kernel_launch(void* const* d_in, const int* in_sizes, int n_in,
                              void* d_out, int out_size)
{
    const float* x   = (const float*)d_in[0];
    const float* gW  = (const float*)d_in[1];
    const float* gb  = (const float*)d_in[2];
    const float* rb  = (const float*)d_in[3];
    const float* W1  = (const float*)d_in[4];
    const float* b1  = (const float*)d_in[5];
    const float* W2  = (const float*)d_in[6];
    const float* b2  = (const float*)d_in[7];
    const float* sW1 = (const float*)d_in[8];
    const float* sb1 = (const float*)d_in[9];
    const float* sW2 = (const float*)d_in[10];
    const float* sb2 = (const float*)d_in[11];
    float* out = (float*)d_out;

    void* p;
    cudaGetSymbolAddress(&p, g_xh);   __nv_bfloat16* xh   = (__nv_bfloat16*)p;
    cudaGetSymbolAddress(&p, g_xl);   __nv_bfloat16* xl   = (__nv_bfloat16*)p;
    cudaGetSymbolAddress(&p, g_W1h);  __nv_bfloat16* W1h  = (__nv_bfloat16*)p;
    cudaGetSymbolAddress(&p, g_W1l);  __nv_bfloat16* W1l  = (__nv_bfloat16*)p;
    cudaGetSymbolAddress(&p, g_W2h);  __nv_bfloat16* W2h  = (__nv_bfloat16*)p;
    cudaGetSymbolAddress(&p, g_W2l);  __nv_bfloat16* W2l  = (__nv_bfloat16*)p;
    cudaGetSymbolAddress(&p, g_sW1h); __nv_bfloat16* sW1h = (__nv_bfloat16*)p;
    cudaGetSymbolAddress(&p, g_sW1l); __nv_bfloat16* sW1l = (__nv_bfloat16*)p;
    cudaGetSymbolAddress(&p, g_sW2h); __nv_bfloat16* sW2h = (__nv_bfloat16*)p;
    cudaGetSymbolAddress(&p, g_sW2l); __nv_bfloat16* sW2l = (__nv_bfloat16*)p;
    cudaGetSymbolAddress(&p, g_Hsh);  __nv_bfloat16* Hsh  = (__nv_bfloat16*)p;
    cudaGetSymbolAddress(&p, g_Hsl);  __nv_bfloat16* Hsl  = (__nv_bfloat16*)p;
    cudaGetSymbolAddress(&p, g_Hrh);  __nv_bfloat16* Hrh  = (__nv_bfloat16*)p;
    cudaGetSymbolAddress(&p, g_Hrl);  __nv_bfloat16* Hrl  = (__nv_bfloat16*)p;
    cudaGetSymbolAddress(&p, g_Yr);   float* Yr = (float*)p;

    cudaFuncSetAttribute(mma_mlp<DIM, HID, true >, cudaFuncAttributeMaxDynamicSharedMemorySize, SMEM_SZ);
    cudaFuncSetAttribute(mma_mlp<HID, DIM, false>, cudaFuncAttributeMaxDynamicSharedMemorySize, SMEM_SZ);

    init_kernel<<<1, 32>>>();
    gate_kernel<<<N_TOK, 128>>>(x, gW, gb, rb);
    aux_kernel<<<1, 256>>>(out, out_size);

    // prep: split everything to bf16 hi/lo
    {
        int n4;
        n4 = N_TOK * DIM / 4;
        split_kernel<<<(n4 + 255) / 256, 256>>>((const float4*)x, (uint2*)xh, (uint2*)xl, n4);
        n4 = NE * DIM * HID / 4;
        split_kernel<<<(n4 + 255) / 256, 256>>>((const float4*)W1, (uint2*)W1h, (uint2*)W1l, n4);
        n4 = NE * HID * DIM / 4;
        split_kernel<<<(n4 + 255) / 256, 256>>>((const float4*)W2, (uint2*)W2h, (uint2*)W2l, n4);
        n4 = DIM * HID / 4;
        split_kernel<<<(n4 + 255) / 256, 256>>>((const float4*)sW1, (uint2*)sW1h, (uint2*)sW1l, n4);
        n4 = HID * DIM / 4;
        split_kernel<<<(n4 + 255) / 256, 256>>>((const float4*)sW2, (uint2*)sW2h, (uint2*)sW2l, n4);
    }

    // MLP1 (merged routed + shared): x -> Hr (slots, gelu, bf16 hi/lo), Hs (tokens)
    mma_mlp<DIM, HID, true ><<<dim3(N_TOK / TBM, HID / TBN, NE + 1), 256, SMEM_SZ>>>(
        xh, xl, xh, xl, W1h, W1l, sW1h, sW1l, b1, sb1,
        nullptr, nullptr, Hrh, Hrl, Hsh, Hsl);
    // MLP2 (merged): Hr -> Yr (*tw), Hs -> out
    mma_mlp<HID, DIM, false><<<dim3(N_TOK / TBM, DIM / TBN, NE + 1), 256, SMEM_SZ>>>(
        Hrh, Hrl, Hsh, Hsl, W2h, W2l, sW2h, sW2l, b2, sb2,
        Yr, out, nullptr, nullptr, nullptr, nullptr);

    combine_kernel<<<(N_TOK * (DIM / 4) + 255) / 256, 256>>>(out);
}

// round 7
// speedup vs baseline: 1.3276x; 1.1315x over previous
#include <cuda_runtime.h>
#include <cuda_fp16.h>
#include <math.h>
#include <stdint.h>

#define N_TOK 4096
#define DIM   1024
#define HID   768
#define NE    23
#define TOPK  3
#define NSLOT (N_TOK * TOPK)

#define TBM 128
#define TBN 64
#define TBK 32
#define A_STRIDE 80      // 64B data + 16B pad
#define B_STRIDE 144     // 128B data + 16B pad
#define AH_OFF 0
#define AL_OFF 10240
#define BH_OFF 20480
#define STG    25088
#define NSTAGE 4
#define SMEM_SZ (NSTAGE * STG)   // 100352

// ---------------- scratch ----------------
__device__ float g_gw[(size_t)N_TOK * NE];
__device__ int   g_counts[NE];
__device__ int   g_list[(size_t)NE * N_TOK];
__device__ float g_tw[NSLOT];
__device__ float g_Yr[(size_t)NSLOT * DIM];

// fp16 operands: activations split hi/lo, weights rounded (hi only)
__device__ __half g_xh[(size_t)N_TOK * DIM];
__device__ __half g_xl[(size_t)N_TOK * DIM];
__device__ __half g_W1h[(size_t)NE * DIM * HID];
__device__ __half g_W2h[(size_t)NE * HID * DIM];
__device__ __half g_sW1h[(size_t)DIM * HID];
__device__ __half g_sW2h[(size_t)HID * DIM];
__device__ __half g_Hsh[(size_t)N_TOK * HID];
__device__ __half g_Hsl[(size_t)N_TOK * HID];
__device__ __half g_Hrh[(size_t)NSLOT * HID];
__device__ __half g_Hrl[(size_t)NSLOT * HID];

__device__ __forceinline__ float gelu_exact(float v) {
    return 0.5f * v * (1.0f + erff(v * 0.7071067811865476f));
}
__device__ __forceinline__ uint32_t smem_u32(const void* p) {
    uint32_t a;
    asm("{ .reg .u64 t; cvta.to.shared.u64 t, %1; cvt.u32.u64 %0, t; }" : "=r"(a) : "l"(p));
    return a;
}
__device__ __forceinline__ void ldsm_x4(uint32_t addr, uint32_t* r) {
    asm volatile("ldmatrix.sync.aligned.m8n8.x4.shared.b16 {%0,%1,%2,%3}, [%4];"
                 : "=r"(r[0]), "=r"(r[1]), "=r"(r[2]), "=r"(r[3]) : "r"(addr));
}
__device__ __forceinline__ void ldsm_x4_t(uint32_t addr, uint32_t* r) {
    asm volatile("ldmatrix.sync.aligned.m8n8.x4.trans.shared.b16 {%0,%1,%2,%3}, [%4];"
                 : "=r"(r[0]), "=r"(r[1]), "=r"(r[2]), "=r"(r[3]) : "r"(addr));
}
__device__ __forceinline__ void mma_f16(float* c, const uint32_t* a, uint32_t b0, uint32_t b1) {
    asm volatile("mma.sync.aligned.m16n8k16.row.col.f32.f16.f16.f32 "
                 "{%0,%1,%2,%3}, {%4,%5,%6,%7}, {%8,%9}, {%0,%1,%2,%3};"
                 : "+f"(c[0]), "+f"(c[1]), "+f"(c[2]), "+f"(c[3])
                 : "r"(a[0]), "r"(a[1]), "r"(a[2]), "r"(a[3]), "r"(b0), "r"(b1));
}
__device__ __forceinline__ void cpa16(uint32_t dst, const void* src) {
    asm volatile("cp.async.cg.shared.global [%0], [%1], 16;" :: "r"(dst), "l"(src));
}
__device__ __forceinline__ void cpa_commit() {
    asm volatile("cp.async.commit_group;");
}
template<int N> __device__ __forceinline__ void cpa_wait() {
    asm volatile("cp.async.wait_group %0;" :: "n"(N));
}
__device__ __forceinline__ uint32_t pack2h(__half a, __half b) {
    return (uint32_t)__half_as_ushort(a) | ((uint32_t)__half_as_ushort(b) << 16);
}
// split float4 into fp16 hi/lo packed uint2s
__device__ __forceinline__ void split4h(float4 v, uint2& h, uint2& l) {
    float vv[4] = {v.x, v.y, v.z, v.w};
    __half hh[4], ll[4];
    #pragma unroll
    for (int q = 0; q < 4; q++) {
        hh[q] = __float2half_rn(vv[q]);
        ll[q] = __float2half_rn(vv[q] - __half2float(hh[q]));
    }
    h = make_uint2(pack2h(hh[0], hh[1]), pack2h(hh[2], hh[3]));
    l = make_uint2(pack2h(ll[0], ll[1]), pack2h(ll[2], ll[3]));
}

// ---------------- prep kernels ----------------
__global__ void split_kernel(const float4* __restrict__ src,
                             uint2* __restrict__ h, uint2* __restrict__ l, int n4)
{
    int i = blockIdx.x * 256 + threadIdx.x;
    if (i < n4) {
        uint2 hh, ll;
        split4h(src[i], hh, ll);
        h[i] = hh;
        l[i] = ll;
    }
}
__global__ void cvt_kernel(const float4* __restrict__ src, uint2* __restrict__ h, int n4)
{
    int i = blockIdx.x * 256 + threadIdx.x;
    if (i < n4) {
        float4 v = src[i];
        h[i] = make_uint2(pack2h(__float2half_rn(v.x), __float2half_rn(v.y)),
                          pack2h(__float2half_rn(v.z), __float2half_rn(v.w)));
    }
}

// ---------------- init ----------------
__global__ void init_kernel() {
    int t = threadIdx.x;
    if (t < NE) g_counts[t] = 0;
}

// ---------------- gate (known-correct) ----------------
__global__ void gate_kernel(const float* __restrict__ x,
                            const float* __restrict__ gW,
                            const float* __restrict__ gb,
                            const float* __restrict__ rbias)
{
    __shared__ float xs[DIM];
    __shared__ float gv[NE];
    __shared__ float gsum_s;
    int n = blockIdx.x;
    int t = threadIdx.x;

    const float4* xv  = (const float4*)(x + (size_t)n * DIM);
    float4*       xsv = (float4*)xs;
    for (int i = t; i < DIM / 4; i += 128) xsv[i] = xv[i];
    __syncthreads();

    int e = t >> 2, j = t & 3;
    float acc = 0.f;
    if (e < NE) {
        for (int i = j; i < DIM; i += 4)
            acc += xs[i] * gW[i * NE + e];
    }
    acc += __shfl_xor_sync(0xffffffffu, acc, 1);
    acc += __shfl_xor_sync(0xffffffffu, acc, 2);
    if (e < NE && j == 0)
        gv[e] = 1.0f / (1.0f + expf(-(acc + gb[e])));
    __syncthreads();

    if (t == 0) {
        float s = 0.f;
        for (int q = 0; q < NE; q++) s += gv[q];
        gsum_s = s;
    }
    __syncthreads();

    if (t < NE) g_gw[(size_t)n * NE + t] = gv[t] / gsum_s;

    if (t == 0) {
        int   idx[TOPK];
        float w[TOPK];
        unsigned used = 0;
        for (int k = 0; k < TOPK; k++) {
            float best = -1e30f; int bi = 0;
            for (int q = 0; q < NE; q++) {
                if (used & (1u << q)) continue;
                float s = gv[q] + rbias[q];
                if (s > best) { best = s; bi = q; }
            }
            used |= (1u << bi);
            idx[k] = bi;
            w[k]   = gv[bi];
        }
        float ws = w[0] + w[1] + w[2];
        for (int k = 0; k < TOPK; k++) {
            int slot = n * TOPK + k;
            g_tw[slot] = w[k] / ws;
            int pos = atomicAdd(&g_counts[idx[k]], 1);
            g_list[(size_t)idx[k] * N_TOK + pos] = slot;
        }
    }
}

// ---------------- aux loss ----------------
__global__ void aux_kernel(float* __restrict__ out, int out_size)
{
    __shared__ float sm[256 * NE];
    int t = threadIdx.x;
    float loc[NE];
    #pragma unroll
    for (int e = 0; e < NE; e++) loc[e] = 0.f;
    for (int n = t; n < N_TOK; n += 256) {
        #pragma unroll
        for (int e = 0; e < NE; e++) loc[e] += g_gw[(size_t)n * NE + e];
    }
    for (int e = 0; e < NE; e++) sm[t * NE + e] = loc[e];
    __syncthreads();
    for (int s = 128; s > 0; s >>= 1) {
        if (t < s)
            for (int e = 0; e < NE; e++) sm[t * NE + e] += sm[(t + s) * NE + e];
        __syncthreads();
    }
    if (t == 0 && out_size > N_TOK * DIM) {
        float aux = 0.f;
        for (int e = 0; e < NE; e++) {
            float P = sm[e] / (float)N_TOK;
            float F = ((float)NE * (float)g_counts[e]) / ((float)TOPK * (float)N_TOK);
            aux += P * F;
        }
        out[(size_t)N_TOK * DIM] = aux;
    }
}

// ---------------- fp16 2-term GEMM, cp.async 4-stage ----------------
// D = (Ah+Al) @ Bh ; blockIdx.z: z<NE routed expert z, z==NE shared.
// MLP1P: Out = gelu(D+bias) -> fp16 hi/lo; else Out = (D+bias)[*tw] fp32
template<int KDIM, int NOUT, bool MLP1P>
__global__ void __launch_bounds__(256, 2) mma_mlp(
    const __half* __restrict__ ArH, const __half* __restrict__ ArL,
    const __half* __restrict__ AsH, const __half* __restrict__ AsL,
    const __half* __restrict__ BrH, const __half* __restrict__ BsH,
    const float* __restrict__ biasR, const float* __restrict__ biasS,
    float* __restrict__ OutRF, float* __restrict__ OutSF,
    __half* __restrict__ OutRH, __half* __restrict__ OutRL,
    __half* __restrict__ OutSH, __half* __restrict__ OutSL)
{
    constexpr int NC = KDIM / TBK;

    int ez = blockIdx.z;
    bool sh = (ez == NE);
    int cnt = sh ? N_TOK : g_counts[ez];
    int m0  = blockIdx.x * TBM;
    if (m0 >= cnt) return;
    int n0  = blockIdx.y * TBN;

    extern __shared__ char smem[];
    uint32_t sbase = smem_u32(smem);

    int tid  = threadIdx.x;
    int wid  = tid >> 5;
    int lane = tid & 31;
    int wm   = wid >> 1;   // 0..3
    int wn   = wid & 1;    // 0..1

    const __half* AH = sh ? AsH : ArH;
    const __half* AL = sh ? AsL : ArL;
    const __half* BH = sh ? BsH : (BrH + (size_t)ez * KDIM * NOUT);
    const float* bias = sh ? biasS : (biasR + (size_t)ez * NOUT);

    // A: thread t -> row t>>1, k-half t&1 (16 elems = 2x16B)
    int arow = tid >> 1;
    int au   = tid & 1;
    int gi_a = m0 + arow;
    int grow;
    if (sh) {
        grow = gi_a;
    } else {
        int gg   = (gi_a < cnt) ? gi_a : (cnt - 1);
        int slot = g_list[(size_t)ez * N_TOK + gg];
        grow = MLP1P ? (slot / TOPK) : slot;
    }
    const __half* ApH = AH + (size_t)grow * KDIM + au * 16;
    const __half* ApL = AL + (size_t)grow * KDIM + au * 16;
    uint32_t aoff = (uint32_t)(arow * A_STRIDE + au * 32);

    // B: thread t -> k-row t>>3 (0..31), 16B unit t&7
    int bk = tid >> 3;
    int bc = tid & 7;
    const __half* BpH = BH + (size_t)bk * NOUT + n0 + bc * 8;
    uint32_t boff = (uint32_t)(bk * B_STRIDE + bc * 16);

    auto issue_chunk = [&](int c, int st) {
        uint32_t sB = sbase + (uint32_t)(st * STG);
        int k0 = c * TBK;
        cpa16(sB + AH_OFF + aoff,      ApH + k0);
        cpa16(sB + AH_OFF + aoff + 16, ApH + k0 + 8);
        cpa16(sB + AL_OFF + aoff,      ApL + k0);
        cpa16(sB + AL_OFF + aoff + 16, ApL + k0 + 8);
        cpa16(sB + BH_OFF + boff,      BpH + (size_t)k0 * NOUT);
        cpa_commit();
    };

    issue_chunk(0, 0);
    if (NC > 1) issue_chunk(1, 1);
    if (NC > 2) issue_chunk(2, 2);

    float acc[2][4][4];
    #pragma unroll
    for (int i = 0; i < 2; i++)
        #pragma unroll
        for (int j = 0; j < 4; j++)
            #pragma unroll
            for (int q = 0; q < 4; q++) acc[i][j][q] = 0.f;

    uint32_t aAddr = sbase + AH_OFF + (uint32_t)((wm * 32 + (lane & 15)) * A_STRIDE + ((lane >> 4) << 4));
    uint32_t bAddr = sbase + BH_OFF + (uint32_t)((lane & 15) * B_STRIDE + ((wn * 32 + (lane >> 4) * 8) << 1));

    int st = 0;
    for (int c = 0; c < NC; c++) {
        // chunk c complete when pending groups <= (issued-so-far - (c+1))
        if (c + 3 <= NC)      cpa_wait<2>();
        else if (c + 2 == NC) cpa_wait<1>();
        else                  cpa_wait<0>();
        __syncthreads();
        if (c + 3 < NC) {
            int st3 = st + 3; if (st3 >= NSTAGE) st3 -= NSTAGE;
            issue_chunk(c + 3, st3);
        }
        uint32_t aS = aAddr + (uint32_t)(st * STG);
        uint32_t bS = bAddr + (uint32_t)(st * STG);
        #pragma unroll
        for (int ks = 0; ks < 2; ks++) {
            uint32_t ahF[2][4], alF[2][4];
            #pragma unroll
            for (int i = 0; i < 2; i++) {
                ldsm_x4(aS + ks * 32 + i * (16 * A_STRIDE), ahF[i]);
                ldsm_x4(aS + ks * 32 + i * (16 * A_STRIDE) + (AL_OFF - AH_OFF), alF[i]);
            }
            uint32_t bhF[2][4];
            #pragma unroll
            for (int g = 0; g < 2; g++)
                ldsm_x4_t(bS + ks * (16 * B_STRIDE) + g * 32, bhF[g]);
            #pragma unroll
            for (int i = 0; i < 2; i++) {
                #pragma unroll
                for (int j = 0; j < 4; j++) {
                    int g = j >> 1, o = (j & 1) * 2;
                    mma_f16(acc[i][j], ahF[i], bhF[g][o], bhF[g][o + 1]);
                    mma_f16(acc[i][j], alF[i], bhF[g][o], bhF[g][o + 1]);
                }
            }
        }
        if (++st == NSTAGE) st = 0;
        __syncthreads();
    }

    // ---- epilogue: frags -> smem (128 x 68 fp32), then coalesced global ----
    float* epi = (float*)smem;
    {
        int rb = wm * 32 + (lane >> 2);
        int cb = wn * 32 + (lane & 3) * 2;
        #pragma unroll
        for (int i = 0; i < 2; i++) {
            #pragma unroll
            for (int j = 0; j < 4; j++) {
                int r = rb + i * 16;
                int cc = cb + j * 8;
                epi[r * 68 + cc]           = acc[i][j][0];
                epi[r * 68 + cc + 1]       = acc[i][j][1];
                epi[(r + 8) * 68 + cc]     = acc[i][j][2];
                epi[(r + 8) * 68 + cc + 1] = acc[i][j][3];
            }
        }
    }
    __syncthreads();

    for (int i = tid; i < TBM * (TBN / 4); i += 256) {
        int r  = i >> 4;
        int c4 = i & 15;
        int gi = m0 + r;
        if (gi >= cnt) continue;
        float4 v = *(float4*)&epi[r * 68 + c4 * 4];
        int col = n0 + c4 * 4;
        float4 b4 = *(const float4*)(bias + col);
        v.x += b4.x; v.y += b4.y; v.z += b4.z; v.w += b4.w;
        if (MLP1P) {
            v.x = gelu_exact(v.x); v.y = gelu_exact(v.y);
            v.z = gelu_exact(v.z); v.w = gelu_exact(v.w);
            uint2 h, l;
            split4h(v, h, l);
            size_t orow;
            __half *OH, *OL;
            if (sh) { orow = (size_t)gi; OH = OutSH; OL = OutSL; }
            else    { orow = (size_t)g_list[(size_t)ez * N_TOK + gi]; OH = OutRH; OL = OutRL; }
            *(uint2*)(OH + orow * NOUT + col) = h;
            *(uint2*)(OL + orow * NOUT + col) = l;
        } else {
            float* Out;
            size_t orow;
            if (sh) {
                Out = OutSF; orow = (size_t)gi;
            } else {
                int slot = g_list[(size_t)ez * N_TOK + gi];
                Out = OutRF; orow = (size_t)slot;
                float w = g_tw[slot];
                v.x *= w; v.y *= w; v.z *= w; v.w *= w;
            }
            *(float4*)(Out + orow * NOUT + col) = v;
        }
    }
}

// ---------------- combine ----------------
__global__ void combine_kernel(float* __restrict__ out)
{
    int idx = blockIdx.x * blockDim.x + threadIdx.x;
    if (idx >= N_TOK * (DIM / 4)) return;
    int n  = idx / (DIM / 4);
    int d4 = idx % (DIM / 4);
    float4 v = ((float4*)out)[idx];
    const float4* yr = (const float4*)g_Yr;
    #pragma unroll
    for (int k = 0; k < TOPK; k++) {
        float4 y = yr[(size_t)(n * TOPK + k) * (DIM / 4) + d4];
        v.x += y.x; v.y += y.y; v.z += y.z; v.w += y.w;
    }
    ((float4*)out)[idx] = v;
}

// ---------------- launch ----------------
extern "C" void kernel_launch(void* const* d_in, const int* in_sizes, int n_in,
                              void* d_out, int out_size)
{
    const float* x   = (const float*)d_in[0];
    const float* gW  = (const float*)d_in[1];
    const float* gb  = (const float*)d_in[2];
    const float* rb  = (const float*)d_in[3];
    const float* W1  = (const float*)d_in[4];
    const float* b1  = (const float*)d_in[5];
    const float* W2  = (const float*)d_in[6];
    const float* b2  = (const float*)d_in[7];
    const float* sW1 = (const float*)d_in[8];
    const float* sb1 = (const float*)d_in[9];
    const float* sW2 = (const float*)d_in[10];
    const float* sb2 = (const float*)d_in[11];
    float* out = (float*)d_out;

    void* p;
    cudaGetSymbolAddress(&p, g_xh);   __half* xh   = (__half*)p;
    cudaGetSymbolAddress(&p, g_xl);   __half* xl   = (__half*)p;
    cudaGetSymbolAddress(&p, g_W1h);  __half* W1h  = (__half*)p;
    cudaGetSymbolAddress(&p, g_W2h);  __half* W2h  = (__half*)p;
    cudaGetSymbolAddress(&p, g_sW1h); __half* sW1h = (__half*)p;
    cudaGetSymbolAddress(&p, g_sW2h); __half* sW2h = (__half*)p;
    cudaGetSymbolAddress(&p, g_Hsh);  __half* Hsh  = (__half*)p;
    cudaGetSymbolAddress(&p, g_Hsl);  __half* Hsl  = (__half*)p;
    cudaGetSymbolAddress(&p, g_Hrh);  __half* Hrh  = (__half*)p;
    cudaGetSymbolAddress(&p, g_Hrl);  __half* Hrl  = (__half*)p;
    cudaGetSymbolAddress(&p, g_Yr);   float* Yr = (float*)p;

    cudaFuncSetAttribute(mma_mlp<DIM, HID, true >, cudaFuncAttributeMaxDynamicSharedMemorySize, SMEM_SZ);
    cudaFuncSetAttribute(mma_mlp<HID, DIM, false>, cudaFuncAttributeMaxDynamicSharedMemorySize, SMEM_SZ);

    init_kernel<<<1, 32>>>();
    gate_kernel<<<N_TOK, 128>>>(x, gW, gb, rb);
    aux_kernel<<<1, 256>>>(out, out_size);

    // prep: x -> fp16 hi/lo ; weights -> fp16 (single)
    {
        int n4;
        n4 = N_TOK * DIM / 4;
        split_kernel<<<(n4 + 255) / 256, 256>>>((const float4*)x, (uint2*)xh, (uint2*)xl, n4);
        n4 = NE * DIM * HID / 4;
        cvt_kernel<<<(n4 + 255) / 256, 256>>>((const float4*)W1, (uint2*)W1h, n4);
        n4 = NE * HID * DIM / 4;
        cvt_kernel<<<(n4 + 255) / 256, 256>>>((const float4*)W2, (uint2*)W2h, n4);
        n4 = DIM * HID / 4;
        cvt_kernel<<<(n4 + 255) / 256, 256>>>((const float4*)sW1, (uint2*)sW1h, n4);
        n4 = HID * DIM / 4;
        cvt_kernel<<<(n4 + 255) / 256, 256>>>((const float4*)sW2, (uint2*)sW2h, n4);
    }

    // MLP1 (merged routed + shared): x -> Hr (slots, gelu, fp16 hi/lo), Hs (tokens)
    mma_mlp<DIM, HID, true ><<<dim3(N_TOK / TBM, HID / TBN, NE + 1), 256, SMEM_SZ>>>(
        xh, xl, xh, xl, W1h, sW1h, b1, sb1,
        nullptr, nullptr, Hrh, Hrl, Hsh, Hsl);
    // MLP2 (merged): Hr -> Yr (*tw), Hs -> out
    mma_mlp<HID, DIM, false><<<dim3(N_TOK / TBM, DIM / TBN, NE + 1), 256, SMEM_SZ>>>(
        Hrh, Hrl, Hsh, Hsl, W2h, sW2h, b2, sb2,
        Yr, out, nullptr, nullptr, nullptr, nullptr);

    combine_kernel<<<(N_TOK * (DIM / 4) + 255) / 256, 256>>>(out);
}

// round 9
// speedup vs baseline: 2.0872x; 1.5721x over previous
#include <cuda_runtime.h>
#include <cuda_fp16.h>
#include <math.h>
#include <stdint.h>

#define N_TOK 4096
#define DIM   1024
#define HID   768
#define NE    23
#define TOPK  3
#define NSLOT (N_TOK * TOPK)

#define TBM 128
#define TBN 64
#define TBK 32
#define A_STRIDE 80      // 64B data + 16B pad
#define B_STRIDE 144     // 128B data + 16B pad
#define AH_OFF 0
#define BH_OFF 10240
#define STG    14848
#define NSTAGE 5
#define SMEM_SZ (NSTAGE * STG)   // 74240

// ---------------- scratch ----------------
__device__ float g_gw[(size_t)N_TOK * NE];
__device__ int   g_counts[NE];
__device__ int   g_list[(size_t)NE * N_TOK];
__device__ float g_tw[NSLOT];
__device__ float g_Yr[(size_t)NSLOT * DIM];

// fp16 operands (single-rounded)
__device__ __half g_xh[(size_t)N_TOK * DIM];
__device__ __half g_W1h[(size_t)NE * DIM * HID];
__device__ __half g_W2h[(size_t)NE * HID * DIM];
__device__ __half g_sW1h[(size_t)DIM * HID];
__device__ __half g_sW2h[(size_t)HID * DIM];
__device__ __half g_Hsh[(size_t)N_TOK * HID];
__device__ __half g_Hrh[(size_t)NSLOT * HID];

__device__ __forceinline__ float gelu_exact(float v) {
    return 0.5f * v * (1.0f + erff(v * 0.7071067811865476f));
}
__device__ __forceinline__ uint32_t smem_u32(const void* p) {
    uint32_t a;
    asm("{ .reg .u64 t; cvta.to.shared.u64 t, %1; cvt.u32.u64 %0, t; }" : "=r"(a) : "l"(p));
    return a;
}
__device__ __forceinline__ void ldsm_x4(uint32_t addr, uint32_t* r) {
    asm volatile("ldmatrix.sync.aligned.m8n8.x4.shared.b16 {%0,%1,%2,%3}, [%4];"
                 : "=r"(r[0]), "=r"(r[1]), "=r"(r[2]), "=r"(r[3]) : "r"(addr));
}
__device__ __forceinline__ void ldsm_x4_t(uint32_t addr, uint32_t* r) {
    asm volatile("ldmatrix.sync.aligned.m8n8.x4.trans.shared.b16 {%0,%1,%2,%3}, [%4];"
                 : "=r"(r[0]), "=r"(r[1]), "=r"(r[2]), "=r"(r[3]) : "r"(addr));
}
__device__ __forceinline__ void mma_f16(float* c, const uint32_t* a, uint32_t b0, uint32_t b1) {
    asm volatile("mma.sync.aligned.m16n8k16.row.col.f32.f16.f16.f32 "
                 "{%0,%1,%2,%3}, {%4,%5,%6,%7}, {%8,%9}, {%0,%1,%2,%3};"
                 : "+f"(c[0]), "+f"(c[1]), "+f"(c[2]), "+f"(c[3])
                 : "r"(a[0]), "r"(a[1]), "r"(a[2]), "r"(a[3]), "r"(b0), "r"(b1));
}
__device__ __forceinline__ void cpa16(uint32_t dst, const void* src) {
    asm volatile("cp.async.cg.shared.global [%0], [%1], 16;" :: "r"(dst), "l"(src));
}
__device__ __forceinline__ void cpa_commit() {
    asm volatile("cp.async.commit_group;");
}
template<int N> __device__ __forceinline__ void cpa_wait() {
    asm volatile("cp.async.wait_group %0;" :: "n"(N));
}
__device__ __forceinline__ uint32_t pack2h(__half a, __half b) {
    return (uint32_t)__half_as_ushort(a) | ((uint32_t)__half_as_ushort(b) << 16);
}

// ---------------- prep: fp32 -> fp16, 8 elems/thread ----------------
__global__ void cvt8_kernel(const float4* __restrict__ src, uint4* __restrict__ dst, int n8)
{
    int i = blockIdx.x * 256 + threadIdx.x;
    if (i < n8) {
        float4 a = src[2 * i];
        float4 b = src[2 * i + 1];
        uint4 o;
        o.x = pack2h(__float2half_rn(a.x), __float2half_rn(a.y));
        o.y = pack2h(__float2half_rn(a.z), __float2half_rn(a.w));
        o.z = pack2h(__float2half_rn(b.x), __float2half_rn(b.y));
        o.w = pack2h(__float2half_rn(b.z), __float2half_rn(b.w));
        dst[i] = o;
    }
}

// ---------------- init ----------------
__global__ void init_kernel() {
    int t = threadIdx.x;
    if (t < NE) g_counts[t] = 0;
}

// ---------------- gate (known-correct) ----------------
__global__ void gate_kernel(const float* __restrict__ x,
                            const float* __restrict__ gW,
                            const float* __restrict__ gb,
                            const float* __restrict__ rbias)
{
    __shared__ float xs[DIM];
    __shared__ float gv[NE];
    __shared__ float gsum_s;
    int n = blockIdx.x;
    int t = threadIdx.x;

    const float4* xv  = (const float4*)(x + (size_t)n * DIM);
    float4*       xsv = (float4*)xs;
    for (int i = t; i < DIM / 4; i += 128) xsv[i] = xv[i];
    __syncthreads();

    int e = t >> 2, j = t & 3;
    float acc = 0.f;
    if (e < NE) {
        for (int i = j; i < DIM; i += 4)
            acc += xs[i] * gW[i * NE + e];
    }
    acc += __shfl_xor_sync(0xffffffffu, acc, 1);
    acc += __shfl_xor_sync(0xffffffffu, acc, 2);
    if (e < NE && j == 0)
        gv[e] = 1.0f / (1.0f + expf(-(acc + gb[e])));
    __syncthreads();

    if (t == 0) {
        float s = 0.f;
        for (int q = 0; q < NE; q++) s += gv[q];
        gsum_s = s;
    }
    __syncthreads();

    if (t < NE) g_gw[(size_t)n * NE + t] = gv[t] / gsum_s;

    if (t == 0) {
        int   idx[TOPK];
        float w[TOPK];
        unsigned used = 0;
        for (int k = 0; k < TOPK; k++) {
            float best = -1e30f; int bi = 0;
            for (int q = 0; q < NE; q++) {
                if (used & (1u << q)) continue;
                float s = gv[q] + rbias[q];
                if (s > best) { best = s; bi = q; }
            }
            used |= (1u << bi);
            idx[k] = bi;
            w[k]   = gv[bi];
        }
        float ws = w[0] + w[1] + w[2];
        for (int k = 0; k < TOPK; k++) {
            int slot = n * TOPK + k;
            g_tw[slot] = w[k] / ws;
            int pos = atomicAdd(&g_counts[idx[k]], 1);
            g_list[(size_t)idx[k] * N_TOK + pos] = slot;
        }
    }
}

// ---------------- aux loss ----------------
__global__ void aux_kernel(float* __restrict__ out, int out_size)
{
    __shared__ float sm[256 * NE];
    int t = threadIdx.x;
    float loc[NE];
    #pragma unroll
    for (int e = 0; e < NE; e++) loc[e] = 0.f;
    for (int n = t; n < N_TOK; n += 256) {
        #pragma unroll
        for (int e = 0; e < NE; e++) loc[e] += g_gw[(size_t)n * NE + e];
    }
    for (int e = 0; e < NE; e++) sm[t * NE + e] = loc[e];
    __syncthreads();
    for (int s = 128; s > 0; s >>= 1) {
        if (t < s)
            for (int e = 0; e < NE; e++) sm[t * NE + e] += sm[(t + s) * NE + e];
        __syncthreads();
    }
    if (t == 0 && out_size > N_TOK * DIM) {
        float aux = 0.f;
        for (int e = 0; e < NE; e++) {
            float P = sm[e] / (float)N_TOK;
            float F = ((float)NE * (float)g_counts[e]) / ((float)TOPK * (float)N_TOK);
            aux += P * F;
        }
        out[(size_t)N_TOK * DIM] = aux;
    }
}

// ---------------- pure fp16 GEMM, cp.async 5-stage ----------------
// blockIdx.z: z<NE routed expert z, z==NE shared.
// MLP1P: Out = gelu(D+bias) -> fp16; else Out = (D+bias)[*tw] fp32
template<int KDIM, int NOUT, bool MLP1P>
__global__ void __launch_bounds__(256, 2) mma_mlp(
    const __half* __restrict__ ArH, const __half* __restrict__ AsH,
    const __half* __restrict__ BrH, const __half* __restrict__ BsH,
    const float* __restrict__ biasR, const float* __restrict__ biasS,
    float* __restrict__ OutRF, float* __restrict__ OutSF,
    __half* __restrict__ OutRH, __half* __restrict__ OutSH)
{
    constexpr int NC = KDIM / TBK;

    int ez = blockIdx.z;
    bool sh = (ez == NE);
    int cnt = sh ? N_TOK : g_counts[ez];
    int m0  = blockIdx.x * TBM;
    if (m0 >= cnt) return;
    int n0  = blockIdx.y * TBN;

    extern __shared__ char smem[];
    uint32_t sbase = smem_u32(smem);

    int tid  = threadIdx.x;
    int wid  = tid >> 5;
    int lane = tid & 31;
    int wm   = wid >> 1;   // 0..3
    int wn   = wid & 1;    // 0..1

    const __half* AH = sh ? AsH : ArH;
    const __half* BH = sh ? BsH : (BrH + (size_t)ez * KDIM * NOUT);
    const float* bias = sh ? biasS : (biasR + (size_t)ez * NOUT);

    // A: thread t -> row t>>1, half t&1 (16 elems = 2x16B units)
    int arow = tid >> 1;
    int au   = tid & 1;
    int gi_a = m0 + arow;
    int grow;
    if (sh) {
        grow = gi_a;
    } else {
        int gg   = (gi_a < cnt) ? gi_a : (cnt - 1);
        int slot = g_list[(size_t)ez * N_TOK + gg];
        grow = MLP1P ? (slot / TOPK) : slot;
    }
    const __half* ApH = AH + (size_t)grow * KDIM + au * 16;
    uint32_t aoff = (uint32_t)(arow * A_STRIDE + au * 32);

    // B: thread t -> k-row t>>3 (0..31), 16B unit t&7
    int bk = tid >> 3;
    int bc = tid & 7;
    const __half* BpH = BH + (size_t)bk * NOUT + n0 + bc * 8;
    uint32_t boff = (uint32_t)(bk * B_STRIDE + bc * 16);

    auto issue_chunk = [&](int c, int st) {
        uint32_t sB = sbase + (uint32_t)(st * STG);
        int k0 = c * TBK;
        cpa16(sB + AH_OFF + aoff,      ApH + k0);
        cpa16(sB + AH_OFF + aoff + 16, ApH + k0 + 8);
        cpa16(sB + BH_OFF + boff,      BpH + (size_t)k0 * NOUT);
        cpa_commit();
    };

    issue_chunk(0, 0);
    if (NC > 1) issue_chunk(1, 1);
    if (NC > 2) issue_chunk(2, 2);
    if (NC > 3) issue_chunk(3, 3);

    float acc[2][4][4];
    #pragma unroll
    for (int i = 0; i < 2; i++)
        #pragma unroll
        for (int j = 0; j < 4; j++)
            #pragma unroll
            for (int q = 0; q < 4; q++) acc[i][j][q] = 0.f;

    uint32_t aAddr = sbase + AH_OFF + (uint32_t)((wm * 32 + (lane & 15)) * A_STRIDE + ((lane >> 4) << 4));
    uint32_t bAddr = sbase + BH_OFF + (uint32_t)((lane & 15) * B_STRIDE + ((wn * 32 + (lane >> 4) * 8) << 1));

    int st = 0;
    for (int c = 0; c < NC; c++) {
        if (c + 4 <= NC)      cpa_wait<3>();
        else if (c + 3 == NC) cpa_wait<2>();
        else if (c + 2 == NC) cpa_wait<1>();
        else                  cpa_wait<0>();
        __syncthreads();
        if (c + 4 < NC) {
            int st4 = st + 4; if (st4 >= NSTAGE) st4 -= NSTAGE;
            issue_chunk(c + 4, st4);
        }
        uint32_t aS = aAddr + (uint32_t)(st * STG);
        uint32_t bS = bAddr + (uint32_t)(st * STG);
        #pragma unroll
        for (int ks = 0; ks < 2; ks++) {
            uint32_t ahF[2][4];
            #pragma unroll
            for (int i = 0; i < 2; i++)
                ldsm_x4(aS + ks * 32 + i * (16 * A_STRIDE), ahF[i]);
            uint32_t bhF[2][4];
            #pragma unroll
            for (int g = 0; g < 2; g++)
                ldsm_x4_t(bS + ks * (16 * B_STRIDE) + g * 32, bhF[g]);
            #pragma unroll
            for (int i = 0; i < 2; i++) {
                #pragma unroll
                for (int j = 0; j < 4; j++) {
                    int g = j >> 1, o = (j & 1) * 2;
                    mma_f16(acc[i][j], ahF[i], bhF[g][o], bhF[g][o + 1]);
                }
            }
        }
        if (++st == NSTAGE) st = 0;
        __syncthreads();
    }

    // ---- epilogue: frags -> smem (128 x 68 fp32), then coalesced global ----
    float* epi = (float*)smem;
    {
        int rb = wm * 32 + (lane >> 2);
        int cb = wn * 32 + (lane & 3) * 2;
        #pragma unroll
        for (int i = 0; i < 2; i++) {
            #pragma unroll
            for (int j = 0; j < 4; j++) {
                int r = rb + i * 16;
                int cc = cb + j * 8;
                epi[r * 68 + cc]           = acc[i][j][0];
                epi[r * 68 + cc + 1]       = acc[i][j][1];
                epi[(r + 8) * 68 + cc]     = acc[i][j][2];
                epi[(r + 8) * 68 + cc + 1] = acc[i][j][3];
            }
        }
    }
    __syncthreads();

    for (int i = tid; i < TBM * (TBN / 4); i += 256) {
        int r  = i >> 4;
        int c4 = i & 15;
        int gi = m0 + r;
        if (gi >= cnt) continue;
        float4 v = *(float4*)&epi[r * 68 + c4 * 4];
        int col = n0 + c4 * 4;
        float4 b4 = *(const float4*)(bias + col);
        v.x += b4.x; v.y += b4.y; v.z += b4.z; v.w += b4.w;
        if (MLP1P) {
            v.x = gelu_exact(v.x); v.y = gelu_exact(v.y);
            v.z = gelu_exact(v.z); v.w = gelu_exact(v.w);
            uint2 h;
            h.x = pack2h(__float2half_rn(v.x), __float2half_rn(v.y));
            h.y = pack2h(__float2half_rn(v.z), __float2half_rn(v.w));
            size_t orow;
            __half* OH;
            if (sh) { orow = (size_t)gi; OH = OutSH; }
            else    { orow = (size_t)g_list[(size_t)ez * N_TOK + gi]; OH = OutRH; }
            *(uint2*)(OH + orow * NOUT + col) = h;
        } else {
            float* Out;
            size_t orow;
            if (sh) {
                Out = OutSF; orow = (size_t)gi;
            } else {
                int slot = g_list[(size_t)ez * N_TOK + gi];
                Out = OutRF; orow = (size_t)slot;
                float w = g_tw[slot];
                v.x *= w; v.y *= w; v.z *= w; v.w *= w;
            }
            *(float4*)(Out + orow * NOUT + col) = v;
        }
    }
}

// ---------------- combine ----------------
__global__ void combine_kernel(float* __restrict__ out)
{
    int idx = blockIdx.x * blockDim.x + threadIdx.x;
    if (idx >= N_TOK * (DIM / 4)) return;
    int n  = idx / (DIM / 4);
    int d4 = idx % (DIM / 4);
    float4 v = ((float4*)out)[idx];
    const float4* yr = (const float4*)g_Yr;
    #pragma unroll
    for (int k = 0; k < TOPK; k++) {
        float4 y = yr[(size_t)(n * TOPK + k) * (DIM / 4) + d4];
        v.x += y.x; v.y += y.y; v.z += y.z; v.w += y.w;
    }
    ((float4*)out)[idx] = v;
}

// ---------------- launch ----------------
extern "C" void kernel_launch(void* const* d_in, const int* in_sizes, int n_in,
                              void* d_out, int out_size)
{
    const float* x   = (const float*)d_in[0];
    const float* gW  = (const float*)d_in[1];
    const float* gb  = (const float*)d_in[2];
    const float* rb  = (const float*)d_in[3];
    const float* W1  = (const float*)d_in[4];
    const float* b1  = (const float*)d_in[5];
    const float* W2  = (const float*)d_in[6];
    const float* b2  = (const float*)d_in[7];
    const float* sW1 = (const float*)d_in[8];
    const float* sb1 = (const float*)d_in[9];
    const float* sW2 = (const float*)d_in[10];
    const float* sb2 = (const float*)d_in[11];
    float* out = (float*)d_out;

    void* p;
    cudaGetSymbolAddress(&p, g_xh);   __half* xh   = (__half*)p;
    cudaGetSymbolAddress(&p, g_W1h);  __half* W1h  = (__half*)p;
    cudaGetSymbolAddress(&p, g_W2h);  __half* W2h  = (__half*)p;
    cudaGetSymbolAddress(&p, g_sW1h); __half* sW1h = (__half*)p;
    cudaGetSymbolAddress(&p, g_sW2h); __half* sW2h = (__half*)p;
    cudaGetSymbolAddress(&p, g_Hsh);  __half* Hsh  = (__half*)p;
    cudaGetSymbolAddress(&p, g_Hrh);  __half* Hrh  = (__half*)p;
    cudaGetSymbolAddress(&p, g_Yr);   float* Yr = (float*)p;

    cudaFuncSetAttribute(mma_mlp<DIM, HID, true >, cudaFuncAttributeMaxDynamicSharedMemorySize, SMEM_SZ);
    cudaFuncSetAttribute(mma_mlp<HID, DIM, false>, cudaFuncAttributeMaxDynamicSharedMemorySize, SMEM_SZ);

    init_kernel<<<1, 32>>>();
    gate_kernel<<<N_TOK, 128>>>(x, gW, gb, rb);
    aux_kernel<<<1, 256>>>(out, out_size);

    // prep: everything -> fp16 (single rounding), 8 elems/thread
    {
        int n8;
        n8 = N_TOK * DIM / 8;
        cvt8_kernel<<<(n8 + 255) / 256, 256>>>((const float4*)x, (uint4*)xh, n8);
        n8 = NE * DIM * HID / 8;
        cvt8_kernel<<<(n8 + 255) / 256, 256>>>((const float4*)W1, (uint4*)W1h, n8);
        n8 = NE * HID * DIM / 8;
        cvt8_kernel<<<(n8 + 255) / 256, 256>>>((const float4*)W2, (uint4*)W2h, n8);
        n8 = DIM * HID / 8;
        cvt8_kernel<<<(n8 + 255) / 256, 256>>>((const float4*)sW1, (uint4*)sW1h, n8);
        n8 = HID * DIM / 8;
        cvt8_kernel<<<(n8 + 255) / 256, 256>>>((const float4*)sW2, (uint4*)sW2h, n8);
    }

    // MLP1 (merged routed + shared): x -> Hr (slots, gelu, fp16), Hs (tokens)
    mma_mlp<DIM, HID, true ><<<dim3(N_TOK / TBM, HID / TBN, NE + 1), 256, SMEM_SZ>>>(
        xh, xh, W1h, sW1h, b1, sb1,
        nullptr, nullptr, Hrh, Hsh);
    // MLP2 (merged): Hr -> Yr (*tw), Hs -> out
    mma_mlp<HID, DIM, false><<<dim3(N_TOK / TBM, DIM / TBN, NE + 1), 256, SMEM_SZ>>>(
        Hrh, Hsh, W2h, sW2h, b2, sb2,
        Yr, out, nullptr, nullptr);

    combine_kernel<<<(N_TOK * (DIM / 4) + 255) / 256, 256>>>(out);
}

// round 10
// speedup vs baseline: 2.2778x; 1.0913x over previous
#include <cuda_runtime.h>
#include <cuda_fp16.h>
#include <math.h>
#include <stdint.h>

#define N_TOK 4096
#define DIM   1024
#define HID   768
#define NE    23
#define TOPK  3
#define NSLOT (N_TOK * TOPK)

#define TBM 128
#define TBN 128
#define TBK 32
#define A_STRIDE 80      // 64B data + 16B pad
#define B_STRIDE 272     // 256B data + 16B pad
#define AH_OFF 0
#define BH_OFF 10240
#define STG    18944     // 10240 + 32*272
#define NSTAGE 4
#define SMEM_SZ (NSTAGE * STG)   // 75776

// ---------------- scratch ----------------
__device__ float g_gw[(size_t)N_TOK * NE];
__device__ int   g_counts[NE];
__device__ int   g_list[(size_t)NE * N_TOK];
__device__ float g_tw[NSLOT];
__device__ float g_Yr[(size_t)NSLOT * DIM];

// fp16 operands (single-rounded)
__device__ __half g_xh[(size_t)N_TOK * DIM];
__device__ __half g_W1h[(size_t)NE * DIM * HID];
__device__ __half g_W2h[(size_t)NE * HID * DIM];
__device__ __half g_sW1h[(size_t)DIM * HID];
__device__ __half g_sW2h[(size_t)HID * DIM];
__device__ __half g_Hsh[(size_t)N_TOK * HID];
__device__ __half g_Hrh[(size_t)NSLOT * HID];

__device__ __forceinline__ float gelu_exact(float v) {
    return 0.5f * v * (1.0f + erff(v * 0.7071067811865476f));
}
__device__ __forceinline__ uint32_t smem_u32(const void* p) {
    uint32_t a;
    asm("{ .reg .u64 t; cvta.to.shared.u64 t, %1; cvt.u32.u64 %0, t; }" : "=r"(a) : "l"(p));
    return a;
}
__device__ __forceinline__ void ldsm_x4(uint32_t addr, uint32_t* r) {
    asm volatile("ldmatrix.sync.aligned.m8n8.x4.shared.b16 {%0,%1,%2,%3}, [%4];"
                 : "=r"(r[0]), "=r"(r[1]), "=r"(r[2]), "=r"(r[3]) : "r"(addr));
}
__device__ __forceinline__ void ldsm_x4_t(uint32_t addr, uint32_t* r) {
    asm volatile("ldmatrix.sync.aligned.m8n8.x4.trans.shared.b16 {%0,%1,%2,%3}, [%4];"
                 : "=r"(r[0]), "=r"(r[1]), "=r"(r[2]), "=r"(r[3]) : "r"(addr));
}
__device__ __forceinline__ void mma_f16(float* c, const uint32_t* a, uint32_t b0, uint32_t b1) {
    asm volatile("mma.sync.aligned.m16n8k16.row.col.f32.f16.f16.f32 "
                 "{%0,%1,%2,%3}, {%4,%5,%6,%7}, {%8,%9}, {%0,%1,%2,%3};"
                 : "+f"(c[0]), "+f"(c[1]), "+f"(c[2]), "+f"(c[3])
                 : "r"(a[0]), "r"(a[1]), "r"(a[2]), "r"(a[3]), "r"(b0), "r"(b1));
}
__device__ __forceinline__ void cpa16(uint32_t dst, const void* src) {
    asm volatile("cp.async.cg.shared.global [%0], [%1], 16;" :: "r"(dst), "l"(src));
}
__device__ __forceinline__ void cpa_commit() {
    asm volatile("cp.async.commit_group;");
}
template<int N> __device__ __forceinline__ void cpa_wait() {
    asm volatile("cp.async.wait_group %0;" :: "n"(N));
}
__device__ __forceinline__ uint32_t pack2h(__half a, __half b) {
    return (uint32_t)__half_as_ushort(a) | ((uint32_t)__half_as_ushort(b) << 16);
}

// ---------------- prep: fp32 -> fp16, 16 elems/thread ----------------
__global__ void cvt16_kernel(const float4* __restrict__ src, uint4* __restrict__ dst, int n16)
{
    int i = blockIdx.x * 256 + threadIdx.x;
    if (i < n16) {
        float4 a = src[4 * i];
        float4 b = src[4 * i + 1];
        float4 c = src[4 * i + 2];
        float4 d = src[4 * i + 3];
        uint4 o0, o1;
        o0.x = pack2h(__float2half_rn(a.x), __float2half_rn(a.y));
        o0.y = pack2h(__float2half_rn(a.z), __float2half_rn(a.w));
        o0.z = pack2h(__float2half_rn(b.x), __float2half_rn(b.y));
        o0.w = pack2h(__float2half_rn(b.z), __float2half_rn(b.w));
        o1.x = pack2h(__float2half_rn(c.x), __float2half_rn(c.y));
        o1.y = pack2h(__float2half_rn(c.z), __float2half_rn(c.w));
        o1.z = pack2h(__float2half_rn(d.x), __float2half_rn(d.y));
        o1.w = pack2h(__float2half_rn(d.z), __float2half_rn(d.w));
        dst[2 * i]     = o0;
        dst[2 * i + 1] = o1;
    }
}

// ---------------- init ----------------
__global__ void init_kernel() {
    int t = threadIdx.x;
    if (t < NE) g_counts[t] = 0;
}

// ---------------- gate (known-correct) ----------------
__global__ void gate_kernel(const float* __restrict__ x,
                            const float* __restrict__ gW,
                            const float* __restrict__ gb,
                            const float* __restrict__ rbias)
{
    __shared__ float xs[DIM];
    __shared__ float gv[NE];
    __shared__ float gsum_s;
    int n = blockIdx.x;
    int t = threadIdx.x;

    const float4* xv  = (const float4*)(x + (size_t)n * DIM);
    float4*       xsv = (float4*)xs;
    for (int i = t; i < DIM / 4; i += 128) xsv[i] = xv[i];
    __syncthreads();

    int e = t >> 2, j = t & 3;
    float acc = 0.f;
    if (e < NE) {
        for (int i = j; i < DIM; i += 4)
            acc += xs[i] * gW[i * NE + e];
    }
    acc += __shfl_xor_sync(0xffffffffu, acc, 1);
    acc += __shfl_xor_sync(0xffffffffu, acc, 2);
    if (e < NE && j == 0)
        gv[e] = 1.0f / (1.0f + expf(-(acc + gb[e])));
    __syncthreads();

    if (t == 0) {
        float s = 0.f;
        for (int q = 0; q < NE; q++) s += gv[q];
        gsum_s = s;
    }
    __syncthreads();

    if (t < NE) g_gw[(size_t)n * NE + t] = gv[t] / gsum_s;

    if (t == 0) {
        int   idx[TOPK];
        float w[TOPK];
        unsigned used = 0;
        for (int k = 0; k < TOPK; k++) {
            float best = -1e30f; int bi = 0;
            for (int q = 0; q < NE; q++) {
                if (used & (1u << q)) continue;
                float s = gv[q] + rbias[q];
                if (s > best) { best = s; bi = q; }
            }
            used |= (1u << bi);
            idx[k] = bi;
            w[k]   = gv[bi];
        }
        float ws = w[0] + w[1] + w[2];
        for (int k = 0; k < TOPK; k++) {
            int slot = n * TOPK + k;
            g_tw[slot] = w[k] / ws;
            int pos = atomicAdd(&g_counts[idx[k]], 1);
            g_list[(size_t)idx[k] * N_TOK + pos] = slot;
        }
    }
}

// ---------------- aux loss ----------------
__global__ void aux_kernel(float* __restrict__ out, int out_size)
{
    __shared__ float sm[256 * NE];
    int t = threadIdx.x;
    float loc[NE];
    #pragma unroll
    for (int e = 0; e < NE; e++) loc[e] = 0.f;
    for (int n = t; n < N_TOK; n += 256) {
        #pragma unroll
        for (int e = 0; e < NE; e++) loc[e] += g_gw[(size_t)n * NE + e];
    }
    for (int e = 0; e < NE; e++) sm[t * NE + e] = loc[e];
    __syncthreads();
    for (int s = 128; s > 0; s >>= 1) {
        if (t < s)
            for (int e = 0; e < NE; e++) sm[t * NE + e] += sm[(t + s) * NE + e];
        __syncthreads();
    }
    if (t == 0 && out_size > N_TOK * DIM) {
        float aux = 0.f;
        for (int e = 0; e < NE; e++) {
            float P = sm[e] / (float)N_TOK;
            float F = ((float)NE * (float)g_counts[e]) / ((float)TOPK * (float)N_TOK);
            aux += P * F;
        }
        out[(size_t)N_TOK * DIM] = aux;
    }
}

// ---------------- pure fp16 GEMM, 128x128 tile, 64x32 warp tiles ----------------
// blockIdx.z: z<NE routed expert z, z==NE shared.
// MLP1P: Out = gelu(D+bias) -> fp16; else Out = (D+bias)[*tw] fp32
template<int KDIM, int NOUT, bool MLP1P>
__global__ void __launch_bounds__(256, 2) mma_mlp(
    const __half* __restrict__ ArH, const __half* __restrict__ AsH,
    const __half* __restrict__ BrH, const __half* __restrict__ BsH,
    const float* __restrict__ biasR, const float* __restrict__ biasS,
    float* __restrict__ OutRF, float* __restrict__ OutSF,
    __half* __restrict__ OutRH, __half* __restrict__ OutSH)
{
    constexpr int NC = KDIM / TBK;

    int ez = blockIdx.z;
    bool sh = (ez == NE);
    int cnt = sh ? N_TOK : g_counts[ez];
    int m0  = blockIdx.x * TBM;
    if (m0 >= cnt) return;
    int n0  = blockIdx.y * TBN;

    extern __shared__ char smem[];
    uint32_t sbase = smem_u32(smem);

    int tid  = threadIdx.x;
    int wid  = tid >> 5;
    int lane = tid & 31;
    int wm   = wid >> 2;   // 0..1 : rows wm*64..+63
    int wn   = wid & 3;    // 0..3 : cols wn*32..+31

    const __half* AH = sh ? AsH : ArH;
    const __half* BH = sh ? BsH : (BrH + (size_t)ez * KDIM * NOUT);
    const float* bias = sh ? biasS : (biasR + (size_t)ez * NOUT);

    // A: thread t -> row t>>1, half t&1 (16 elems = 2x16B units)
    int arow = tid >> 1;
    int au   = tid & 1;
    int gi_a = m0 + arow;
    int grow;
    if (sh) {
        grow = gi_a;
    } else {
        int gg   = (gi_a < cnt) ? gi_a : (cnt - 1);
        int slot = g_list[(size_t)ez * N_TOK + gg];
        grow = MLP1P ? (slot / TOPK) : slot;
    }
    const __half* ApH = AH + (size_t)grow * KDIM + au * 16;
    uint32_t aoff = (uint32_t)(arow * A_STRIDE + au * 32);

    // B: thread t -> k-row t>>3 (0..31), 16B unit t&7 (+128B for second half)
    int bk = tid >> 3;
    int bc = tid & 7;
    const __half* BpH = BH + (size_t)bk * NOUT + n0 + bc * 8;
    uint32_t boff = (uint32_t)(bk * B_STRIDE + bc * 16);

    auto issue_chunk = [&](int c, int st) {
        uint32_t sB = sbase + (uint32_t)(st * STG);
        int k0 = c * TBK;
        cpa16(sB + AH_OFF + aoff,       ApH + k0);
        cpa16(sB + AH_OFF + aoff + 16,  ApH + k0 + 8);
        cpa16(sB + BH_OFF + boff,       BpH + (size_t)k0 * NOUT);
        cpa16(sB + BH_OFF + boff + 128, BpH + (size_t)k0 * NOUT + 64);
        cpa_commit();
    };

    issue_chunk(0, 0);
    if (NC > 1) issue_chunk(1, 1);
    if (NC > 2) issue_chunk(2, 2);

    float acc[4][4][4];
    #pragma unroll
    for (int i = 0; i < 4; i++)
        #pragma unroll
        for (int j = 0; j < 4; j++)
            #pragma unroll
            for (int q = 0; q < 4; q++) acc[i][j][q] = 0.f;

    uint32_t aAddr = sbase + AH_OFF + (uint32_t)((wm * 64 + (lane & 15)) * A_STRIDE + ((lane >> 4) << 4));
    uint32_t bAddr = sbase + BH_OFF + (uint32_t)((lane & 15) * B_STRIDE + ((wn * 32 + (lane >> 4) * 8) << 1));

    int st = 0;
    for (int c = 0; c < NC; c++) {
        if (c + 3 <= NC)      cpa_wait<2>();
        else if (c + 2 == NC) cpa_wait<1>();
        else                  cpa_wait<0>();
        __syncthreads();
        if (c + 3 < NC) {
            int st3 = st + 3; if (st3 >= NSTAGE) st3 -= NSTAGE;
            issue_chunk(c + 3, st3);
        }
        uint32_t aS = aAddr + (uint32_t)(st * STG);
        uint32_t bS = bAddr + (uint32_t)(st * STG);
        #pragma unroll
        for (int ks = 0; ks < 2; ks++) {
            uint32_t ahF[4][4];
            #pragma unroll
            for (int i = 0; i < 4; i++)
                ldsm_x4(aS + ks * 32 + i * (16 * A_STRIDE), ahF[i]);
            uint32_t bhF[2][4];
            #pragma unroll
            for (int g = 0; g < 2; g++)
                ldsm_x4_t(bS + ks * (16 * B_STRIDE) + g * 32, bhF[g]);
            #pragma unroll
            for (int i = 0; i < 4; i++) {
                #pragma unroll
                for (int j = 0; j < 4; j++) {
                    int g = j >> 1, o = (j & 1) * 2;
                    mma_f16(acc[i][j], ahF[i], bhF[g][o], bhF[g][o + 1]);
                }
            }
        }
        if (++st == NSTAGE) st = 0;
        __syncthreads();
    }

    // ---- epilogue: frags -> smem (128 x 132 fp32), then coalesced global ----
    float* epi = (float*)smem;
    {
        int rb = wm * 64 + (lane >> 2);
        int cb = wn * 32 + (lane & 3) * 2;
        #pragma unroll
        for (int i = 0; i < 4; i++) {
            #pragma unroll
            for (int j = 0; j < 4; j++) {
                int r = rb + i * 16;
                int cc = cb + j * 8;
                epi[r * 132 + cc]           = acc[i][j][0];
                epi[r * 132 + cc + 1]       = acc[i][j][1];
                epi[(r + 8) * 132 + cc]     = acc[i][j][2];
                epi[(r + 8) * 132 + cc + 1] = acc[i][j][3];
            }
        }
    }
    __syncthreads();

    for (int i = tid; i < TBM * (TBN / 4); i += 256) {
        int r  = i >> 5;
        int c4 = i & 31;
        int gi = m0 + r;
        if (gi >= cnt) continue;
        float4 v = *(float4*)&epi[r * 132 + c4 * 4];
        int col = n0 + c4 * 4;
        float4 b4 = *(const float4*)(bias + col);
        v.x += b4.x; v.y += b4.y; v.z += b4.z; v.w += b4.w;
        if (MLP1P) {
            v.x = gelu_exact(v.x); v.y = gelu_exact(v.y);
            v.z = gelu_exact(v.z); v.w = gelu_exact(v.w);
            uint2 h;
            h.x = pack2h(__float2half_rn(v.x), __float2half_rn(v.y));
            h.y = pack2h(__float2half_rn(v.z), __float2half_rn(v.w));
            size_t orow;
            __half* OH;
            if (sh) { orow = (size_t)gi; OH = OutSH; }
            else    { orow = (size_t)g_list[(size_t)ez * N_TOK + gi]; OH = OutRH; }
            *(uint2*)(OH + orow * NOUT + col) = h;
        } else {
            float* Out;
            size_t orow;
            if (sh) {
                Out = OutSF; orow = (size_t)gi;
            } else {
                int slot = g_list[(size_t)ez * N_TOK + gi];
                Out = OutRF; orow = (size_t)slot;
                float w = g_tw[slot];
                v.x *= w; v.y *= w; v.z *= w; v.w *= w;
            }
            *(float4*)(Out + orow * NOUT + col) = v;
        }
    }
}

// ---------------- combine ----------------
__global__ void combine_kernel(float* __restrict__ out)
{
    int idx = blockIdx.x * blockDim.x + threadIdx.x;
    if (idx >= N_TOK * (DIM / 4)) return;
    int n  = idx / (DIM / 4);
    int d4 = idx % (DIM / 4);
    float4 v = ((float4*)out)[idx];
    const float4* yr = (const float4*)g_Yr;
    #pragma unroll
    for (int k = 0; k < TOPK; k++) {
        float4 y = yr[(size_t)(n * TOPK + k) * (DIM / 4) + d4];
        v.x += y.x; v.y += y.y; v.z += y.z; v.w += y.w;
    }
    ((float4*)out)[idx] = v;
}

// ---------------- launch ----------------
extern "C" void kernel_launch(void* const* d_in, const int* in_sizes, int n_in,
                              void* d_out, int out_size)
{
    const float* x   = (const float*)d_in[0];
    const float* gW  = (const float*)d_in[1];
    const float* gb  = (const float*)d_in[2];
    const float* rb  = (const float*)d_in[3];
    const float* W1  = (const float*)d_in[4];
    const float* b1  = (const float*)d_in[5];
    const float* W2  = (const float*)d_in[6];
    const float* b2  = (const float*)d_in[7];
    const float* sW1 = (const float*)d_in[8];
    const float* sb1 = (const float*)d_in[9];
    const float* sW2 = (const float*)d_in[10];
    const float* sb2 = (const float*)d_in[11];
    float* out = (float*)d_out;

    void* p;
    cudaGetSymbolAddress(&p, g_xh);   __half* xh   = (__half*)p;
    cudaGetSymbolAddress(&p, g_W1h);  __half* W1h  = (__half*)p;
    cudaGetSymbolAddress(&p, g_W2h);  __half* W2h  = (__half*)p;
    cudaGetSymbolAddress(&p, g_sW1h); __half* sW1h = (__half*)p;
    cudaGetSymbolAddress(&p, g_sW2h); __half* sW2h = (__half*)p;
    cudaGetSymbolAddress(&p, g_Hsh);  __half* Hsh  = (__half*)p;
    cudaGetSymbolAddress(&p, g_Hrh);  __half* Hrh  = (__half*)p;
    cudaGetSymbolAddress(&p, g_Yr);   float* Yr = (float*)p;

    cudaFuncSetAttribute(mma_mlp<DIM, HID, true >, cudaFuncAttributeMaxDynamicSharedMemorySize, SMEM_SZ);
    cudaFuncSetAttribute(mma_mlp<HID, DIM, false>, cudaFuncAttributeMaxDynamicSharedMemorySize, SMEM_SZ);

    init_kernel<<<1, 32>>>();
    gate_kernel<<<N_TOK, 128>>>(x, gW, gb, rb);
    aux_kernel<<<1, 256>>>(out, out_size);

    // prep: everything -> fp16 (single rounding), 16 elems/thread
    {
        int n16;
        n16 = N_TOK * DIM / 16;
        cvt16_kernel<<<(n16 + 255) / 256, 256>>>((const float4*)x, (uint4*)xh, n16);
        n16 = NE * DIM * HID / 16;
        cvt16_kernel<<<(n16 + 255) / 256, 256>>>((const float4*)W1, (uint4*)W1h, n16);
        n16 = NE * HID * DIM / 16;
        cvt16_kernel<<<(n16 + 255) / 256, 256>>>((const float4*)W2, (uint4*)W2h, n16);
        n16 = DIM * HID / 16;
        cvt16_kernel<<<(n16 + 255) / 256, 256>>>((const float4*)sW1, (uint4*)sW1h, n16);
        n16 = HID * DIM / 16;
        cvt16_kernel<<<(n16 + 255) / 256, 256>>>((const float4*)sW2, (uint4*)sW2h, n16);
    }

    // MLP1 (merged routed + shared): x -> Hr (slots, gelu, fp16), Hs (tokens)
    mma_mlp<DIM, HID, true ><<<dim3(N_TOK / TBM, HID / TBN, NE + 1), 256, SMEM_SZ>>>(
        xh, xh, W1h, sW1h, b1, sb1,
        nullptr, nullptr, Hrh, Hsh);
    // MLP2 (merged): Hr -> Yr (*tw), Hs -> out
    mma_mlp<HID, DIM, false><<<dim3(N_TOK / TBM, DIM / TBN, NE + 1), 256, SMEM_SZ>>>(
        Hrh, Hsh, W2h, sW2h, b2, sb2,
        Yr, out, nullptr, nullptr);

    combine_kernel<<<(N_TOK * (DIM / 4) + 255) / 256, 256>>>(out);
}

// round 11
// speedup vs baseline: 2.3852x; 1.0471x over previous
#include <cuda_runtime.h>
#include <cuda_fp16.h>
#include <math.h>
#include <stdint.h>

#define N_TOK 4096
#define DIM   1024
#define HID   768
#define NE    23
#define TOPK  3
#define NSLOT (N_TOK * TOPK)

#define TBM 128
#define TBN 128
#define TBK 32
#define A_STRIDE 80      // 64B data + 16B pad
#define B_STRIDE 272     // 256B data + 16B pad
#define A_STG   10240    // per A stage
#define NSTAGE_A 4
#define B_OFF   (NSTAGE_A * A_STG)          // 40960
#define B_STG   8704                        // 32 * 272
#define PIPE_SZ (B_OFF + 2 * B_STG)         // 58368
#define EPI_SZ  (128 * 132 * 4)             // 67584
#define SMEM_SZ EPI_SZ

// ---------------- scratch ----------------
__device__ float g_gw[(size_t)N_TOK * NE];
__device__ int   g_counts[NE];
__device__ int   g_list[(size_t)NE * N_TOK];
__device__ float g_tw[NSLOT];
__device__ float g_Yr[(size_t)NSLOT * DIM];

// fp16 activations
__device__ __half g_xh[(size_t)N_TOK * DIM];
__device__ __half g_Hsh[(size_t)N_TOK * HID];
__device__ __half g_Hrh[(size_t)NSLOT * HID];

__device__ __forceinline__ float gelu_exact(float v) {
    return 0.5f * v * (1.0f + erff(v * 0.7071067811865476f));
}
__device__ __forceinline__ uint32_t smem_u32(const void* p) {
    uint32_t a;
    asm("{ .reg .u64 t; cvta.to.shared.u64 t, %1; cvt.u32.u64 %0, t; }" : "=r"(a) : "l"(p));
    return a;
}
__device__ __forceinline__ void ldsm_x4(uint32_t addr, uint32_t* r) {
    asm volatile("ldmatrix.sync.aligned.m8n8.x4.shared.b16 {%0,%1,%2,%3}, [%4];"
                 : "=r"(r[0]), "=r"(r[1]), "=r"(r[2]), "=r"(r[3]) : "r"(addr));
}
__device__ __forceinline__ void ldsm_x4_t(uint32_t addr, uint32_t* r) {
    asm volatile("ldmatrix.sync.aligned.m8n8.x4.trans.shared.b16 {%0,%1,%2,%3}, [%4];"
                 : "=r"(r[0]), "=r"(r[1]), "=r"(r[2]), "=r"(r[3]) : "r"(addr));
}
__device__ __forceinline__ void mma_f16(float* c, const uint32_t* a, uint32_t b0, uint32_t b1) {
    asm volatile("mma.sync.aligned.m16n8k16.row.col.f32.f16.f16.f32 "
                 "{%0,%1,%2,%3}, {%4,%5,%6,%7}, {%8,%9}, {%0,%1,%2,%3};"
                 : "+f"(c[0]), "+f"(c[1]), "+f"(c[2]), "+f"(c[3])
                 : "r"(a[0]), "r"(a[1]), "r"(a[2]), "r"(a[3]), "r"(b0), "r"(b1));
}
__device__ __forceinline__ void cpa16(uint32_t dst, const void* src) {
    asm volatile("cp.async.cg.shared.global [%0], [%1], 16;" :: "r"(dst), "l"(src));
}
__device__ __forceinline__ void cpa_commit() {
    asm volatile("cp.async.commit_group;");
}
template<int N> __device__ __forceinline__ void cpa_wait() {
    asm volatile("cp.async.wait_group %0;" :: "n"(N));
}
__device__ __forceinline__ uint32_t pack2h(__half a, __half b) {
    return (uint32_t)__half_as_ushort(a) | ((uint32_t)__half_as_ushort(b) << 16);
}
__device__ __forceinline__ uint32_t cvt2h(float a, float b) {
    return pack2h(__float2half_rn(a), __float2half_rn(b));
}

// ---------------- prep: x -> fp16, 16 elems/thread ----------------
__global__ void cvt16_kernel(const float4* __restrict__ src, uint4* __restrict__ dst, int n16)
{
    int i = blockIdx.x * 256 + threadIdx.x;
    if (i < n16) {
        float4 a = src[4 * i];
        float4 b = src[4 * i + 1];
        float4 c = src[4 * i + 2];
        float4 d = src[4 * i + 3];
        uint4 o0, o1;
        o0.x = cvt2h(a.x, a.y); o0.y = cvt2h(a.z, a.w);
        o0.z = cvt2h(b.x, b.y); o0.w = cvt2h(b.z, b.w);
        o1.x = cvt2h(c.x, c.y); o1.y = cvt2h(c.z, c.w);
        o1.z = cvt2h(d.x, d.y); o1.w = cvt2h(d.z, d.w);
        dst[2 * i]     = o0;
        dst[2 * i + 1] = o1;
    }
}

// ---------------- init ----------------
__global__ void init_kernel() {
    int t = threadIdx.x;
    if (t < NE) g_counts[t] = 0;
}

// ---------------- gate (known-correct) ----------------
__global__ void gate_kernel(const float* __restrict__ x,
                            const float* __restrict__ gW,
                            const float* __restrict__ gb,
                            const float* __restrict__ rbias)
{
    __shared__ float xs[DIM];
    __shared__ float gv[NE];
    __shared__ float gsum_s;
    int n = blockIdx.x;
    int t = threadIdx.x;

    const float4* xv  = (const float4*)(x + (size_t)n * DIM);
    float4*       xsv = (float4*)xs;
    for (int i = t; i < DIM / 4; i += 128) xsv[i] = xv[i];
    __syncthreads();

    int e = t >> 2, j = t & 3;
    float acc = 0.f;
    if (e < NE) {
        for (int i = j; i < DIM; i += 4)
            acc += xs[i] * gW[i * NE + e];
    }
    acc += __shfl_xor_sync(0xffffffffu, acc, 1);
    acc += __shfl_xor_sync(0xffffffffu, acc, 2);
    if (e < NE && j == 0)
        gv[e] = 1.0f / (1.0f + expf(-(acc + gb[e])));
    __syncthreads();

    if (t == 0) {
        float s = 0.f;
        for (int q = 0; q < NE; q++) s += gv[q];
        gsum_s = s;
    }
    __syncthreads();

    if (t < NE) g_gw[(size_t)n * NE + t] = gv[t] / gsum_s;

    if (t == 0) {
        int   idx[TOPK];
        float w[TOPK];
        unsigned used = 0;
        for (int k = 0; k < TOPK; k++) {
            float best = -1e30f; int bi = 0;
            for (int q = 0; q < NE; q++) {
                if (used & (1u << q)) continue;
                float s = gv[q] + rbias[q];
                if (s > best) { best = s; bi = q; }
            }
            used |= (1u << bi);
            idx[k] = bi;
            w[k]   = gv[bi];
        }
        float ws = w[0] + w[1] + w[2];
        for (int k = 0; k < TOPK; k++) {
            int slot = n * TOPK + k;
            g_tw[slot] = w[k] / ws;
            int pos = atomicAdd(&g_counts[idx[k]], 1);
            g_list[(size_t)idx[k] * N_TOK + pos] = slot;
        }
    }
}

// ---------------- aux loss ----------------
__global__ void aux_kernel(float* __restrict__ out, int out_size)
{
    __shared__ float sm[256 * NE];
    int t = threadIdx.x;
    float loc[NE];
    #pragma unroll
    for (int e = 0; e < NE; e++) loc[e] = 0.f;
    for (int n = t; n < N_TOK; n += 256) {
        #pragma unroll
        for (int e = 0; e < NE; e++) loc[e] += g_gw[(size_t)n * NE + e];
    }
    for (int e = 0; e < NE; e++) sm[t * NE + e] = loc[e];
    __syncthreads();
    for (int s = 128; s > 0; s >>= 1) {
        if (t < s)
            for (int e = 0; e < NE; e++) sm[t * NE + e] += sm[(t + s) * NE + e];
        __syncthreads();
    }
    if (t == 0 && out_size > N_TOK * DIM) {
        float aux = 0.f;
        for (int e = 0; e < NE; e++) {
            float P = sm[e] / (float)N_TOK;
            float F = ((float)NE * (float)g_counts[e]) / ((float)TOPK * (float)N_TOK);
            aux += P * F;
        }
        out[(size_t)N_TOK * DIM] = aux;
    }
}

// ---------------- fp16 GEMM: A fp16 cp.async 4-stage, B fp32->fp16 in-loader ----------------
// blockIdx.z: z<NE routed expert z, z==NE shared.
// MLP1P: Out = gelu(D+bias) -> fp16; else Out = (D+bias)[*tw] fp32
template<int KDIM, int NOUT, bool MLP1P>
__global__ void __launch_bounds__(256, 2) mma_mlp(
    const __half* __restrict__ ArH, const __half* __restrict__ AsH,
    const float* __restrict__ BrF, const float* __restrict__ BsF,
    const float* __restrict__ biasR, const float* __restrict__ biasS,
    float* __restrict__ OutRF, float* __restrict__ OutSF,
    __half* __restrict__ OutRH, __half* __restrict__ OutSH)
{
    constexpr int NC = KDIM / TBK;

    int ez = blockIdx.z;
    bool sh = (ez == NE);
    int cnt = sh ? N_TOK : g_counts[ez];
    int m0  = blockIdx.x * TBM;
    if (m0 >= cnt) return;
    int n0  = blockIdx.y * TBN;

    extern __shared__ char smem[];
    uint32_t sbase = smem_u32(smem);

    int tid  = threadIdx.x;
    int wid  = tid >> 5;
    int lane = tid & 31;
    int wm   = wid >> 2;   // 0..1 : rows wm*64..+63
    int wn   = wid & 3;    // 0..3 : cols wn*32..+31

    const __half* AH  = sh ? AsH : ArH;
    const float*  BF  = sh ? BsF : (BrF + (size_t)ez * KDIM * NOUT);
    const float* bias = sh ? biasS : (biasR + (size_t)ez * NOUT);

    // A: thread t -> row t>>1, half t&1 (16 elems = 2x16B units)
    int arow = tid >> 1;
    int au   = tid & 1;
    int gi_a = m0 + arow;
    int grow;
    if (sh) {
        grow = gi_a;
    } else {
        int gg   = (gi_a < cnt) ? gi_a : (cnt - 1);
        int slot = g_list[(size_t)ez * N_TOK + gg];
        grow = MLP1P ? (slot / TOPK) : slot;
    }
    const __half* ApH = AH + (size_t)grow * KDIM + au * 16;
    uint32_t aoff = (uint32_t)(arow * A_STRIDE + au * 32);

    auto issue_A = [&](int c, int st) {
        uint32_t sA = sbase + (uint32_t)(st * A_STG);
        int k0 = c * TBK;
        cpa16(sA + aoff,      ApH + k0);
        cpa16(sA + aoff + 16, ApH + k0 + 8);
        cpa_commit();
    };

    // B: thread t -> k-row t>>3 (0..31), cols n0 + (t&7)*8 and +64; fp32 source
    int bk = tid >> 3;
    int bc = tid & 7;
    const float* BpF = BF + (size_t)bk * NOUT + n0 + bc * 8;
    uint32_t boff = (uint32_t)(bk * B_STRIDE + bc * 16);

    float4 fb[4];
    auto load_B = [&](int c) {
        size_t k0n = (size_t)(c * TBK) * NOUT;
        fb[0] = *(const float4*)(BpF + k0n);
        fb[1] = *(const float4*)(BpF + k0n + 4);
        fb[2] = *(const float4*)(BpF + k0n + 64);
        fb[3] = *(const float4*)(BpF + k0n + 68);
    };
    auto store_B = [&](int bs) {
        char* dst = smem + B_OFF + bs * B_STG;
        uint4 v0, v1;
        v0.x = cvt2h(fb[0].x, fb[0].y); v0.y = cvt2h(fb[0].z, fb[0].w);
        v0.z = cvt2h(fb[1].x, fb[1].y); v0.w = cvt2h(fb[1].z, fb[1].w);
        v1.x = cvt2h(fb[2].x, fb[2].y); v1.y = cvt2h(fb[2].z, fb[2].w);
        v1.z = cvt2h(fb[3].x, fb[3].y); v1.w = cvt2h(fb[3].z, fb[3].w);
        *(uint4*)(dst + boff)       = v0;
        *(uint4*)(dst + boff + 128) = v1;
    };

    // prologue
    issue_A(0, 0);
    if (NC > 1) issue_A(1, 1);
    if (NC > 2) issue_A(2, 2);
    load_B(0);
    store_B(0);
    if (NC > 1) load_B(1);

    float acc[4][4][4];
    #pragma unroll
    for (int i = 0; i < 4; i++)
        #pragma unroll
        for (int j = 0; j < 4; j++)
            #pragma unroll
            for (int q = 0; q < 4; q++) acc[i][j][q] = 0.f;

    uint32_t aAddr = sbase + (uint32_t)((wm * 64 + (lane & 15)) * A_STRIDE + ((lane >> 4) << 4));
    uint32_t bAddr = sbase + B_OFF + (uint32_t)((lane & 15) * B_STRIDE + ((wn * 32 + (lane >> 4) * 8) << 1));

    int st = 0;
    for (int c = 0; c < NC; c++) {
        if (c + 3 <= NC)      cpa_wait<2>();
        else if (c + 2 == NC) cpa_wait<1>();
        else                  cpa_wait<0>();
        __syncthreads();
        if (c + 3 < NC) {
            int st3 = st + 3; if (st3 >= NSTAGE_A) st3 -= NSTAGE_A;
            issue_A(c + 3, st3);
        }
        // stage B for chunk c+1 (safe: all warps passed sync -> done reading this B stage),
        // then issue B global prefetch for c+2 (retires under compute below)
        if (c + 1 < NC) {
            store_B((c + 1) & 1);
            if (c + 2 < NC) load_B(c + 2);
        }
        uint32_t aS = aAddr + (uint32_t)(st * A_STG);
        uint32_t bS = bAddr + (uint32_t)((c & 1) * B_STG);
        #pragma unroll
        for (int ks = 0; ks < 2; ks++) {
            uint32_t ahF[4][4];
            #pragma unroll
            for (int i = 0; i < 4; i++)
                ldsm_x4(aS + ks * 32 + i * (16 * A_STRIDE), ahF[i]);
            uint32_t bhF[2][4];
            #pragma unroll
            for (int g = 0; g < 2; g++)
                ldsm_x4_t(bS + ks * (16 * B_STRIDE) + g * 32, bhF[g]);
            #pragma unroll
            for (int i = 0; i < 4; i++) {
                #pragma unroll
                for (int j = 0; j < 4; j++) {
                    int g = j >> 1, o = (j & 1) * 2;
                    mma_f16(acc[i][j], ahF[i], bhF[g][o], bhF[g][o + 1]);
                }
            }
        }
        if (++st == NSTAGE_A) st = 0;
    }
    __syncthreads();

    // ---- epilogue: frags -> smem (128 x 132 fp32), then coalesced global ----
    float* epi = (float*)smem;
    {
        int rb = wm * 64 + (lane >> 2);
        int cb = wn * 32 + (lane & 3) * 2;
        #pragma unroll
        for (int i = 0; i < 4; i++) {
            #pragma unroll
            for (int j = 0; j < 4; j++) {
                int r = rb + i * 16;
                int cc = cb + j * 8;
                epi[r * 132 + cc]           = acc[i][j][0];
                epi[r * 132 + cc + 1]       = acc[i][j][1];
                epi[(r + 8) * 132 + cc]     = acc[i][j][2];
                epi[(r + 8) * 132 + cc + 1] = acc[i][j][3];
            }
        }
    }
    __syncthreads();

    for (int i = tid; i < TBM * (TBN / 4); i += 256) {
        int r  = i >> 5;
        int c4 = i & 31;
        int gi = m0 + r;
        if (gi >= cnt) continue;
        float4 v = *(float4*)&epi[r * 132 + c4 * 4];
        int col = n0 + c4 * 4;
        float4 b4 = *(const float4*)(bias + col);
        v.x += b4.x; v.y += b4.y; v.z += b4.z; v.w += b4.w;
        if (MLP1P) {
            v.x = gelu_exact(v.x); v.y = gelu_exact(v.y);
            v.z = gelu_exact(v.z); v.w = gelu_exact(v.w);
            uint2 h;
            h.x = cvt2h(v.x, v.y);
            h.y = cvt2h(v.z, v.w);
            size_t orow;
            __half* OH;
            if (sh) { orow = (size_t)gi; OH = OutSH; }
            else    { orow = (size_t)g_list[(size_t)ez * N_TOK + gi]; OH = OutRH; }
            *(uint2*)(OH + orow * NOUT + col) = h;
        } else {
            float* Out;
            size_t orow;
            if (sh) {
                Out = OutSF; orow = (size_t)gi;
            } else {
                int slot = g_list[(size_t)ez * N_TOK + gi];
                Out = OutRF; orow = (size_t)slot;
                float w = g_tw[slot];
                v.x *= w; v.y *= w; v.z *= w; v.w *= w;
            }
            *(float4*)(Out + orow * NOUT + col) = v;
        }
    }
}

// ---------------- combine ----------------
__global__ void combine_kernel(float* __restrict__ out)
{
    int idx = blockIdx.x * blockDim.x + threadIdx.x;
    if (idx >= N_TOK * (DIM / 4)) return;
    int n  = idx / (DIM / 4);
    int d4 = idx % (DIM / 4);
    float4 v = ((float4*)out)[idx];
    const float4* yr = (const float4*)g_Yr;
    #pragma unroll
    for (int k = 0; k < TOPK; k++) {
        float4 y = yr[(size_t)(n * TOPK + k) * (DIM / 4) + d4];
        v.x += y.x; v.y += y.y; v.z += y.z; v.w += y.w;
    }
    ((float4*)out)[idx] = v;
}

// ---------------- launch ----------------
extern "C" void kernel_launch(void* const* d_in, const int* in_sizes, int n_in,
                              void* d_out, int out_size)
{
    const float* x   = (const float*)d_in[0];
    const float* gW  = (const float*)d_in[1];
    const float* gb  = (const float*)d_in[2];
    const float* rb  = (const float*)d_in[3];
    const float* W1  = (const float*)d_in[4];
    const float* b1  = (const float*)d_in[5];
    const float* W2  = (const float*)d_in[6];
    const float* b2  = (const float*)d_in[7];
    const float* sW1 = (const float*)d_in[8];
    const float* sb1 = (const float*)d_in[9];
    const float* sW2 = (const float*)d_in[10];
    const float* sb2 = (const float*)d_in[11];
    float* out = (float*)d_out;

    void* p;
    cudaGetSymbolAddress(&p, g_xh);   __half* xh   = (__half*)p;
    cudaGetSymbolAddress(&p, g_Hsh);  __half* Hsh  = (__half*)p;
    cudaGetSymbolAddress(&p, g_Hrh);  __half* Hrh  = (__half*)p;
    cudaGetSymbolAddress(&p, g_Yr);   float* Yr = (float*)p;

    cudaFuncSetAttribute(mma_mlp<DIM, HID, true >, cudaFuncAttributeMaxDynamicSharedMemorySize, SMEM_SZ);
    cudaFuncSetAttribute(mma_mlp<HID, DIM, false>, cudaFuncAttributeMaxDynamicSharedMemorySize, SMEM_SZ);

    init_kernel<<<1, 32>>>();
    gate_kernel<<<N_TOK, 128>>>(x, gW, gb, rb);
    aux_kernel<<<1, 256>>>(out, out_size);

    // prep: only x -> fp16
    {
        int n16 = N_TOK * DIM / 16;
        cvt16_kernel<<<(n16 + 255) / 256, 256>>>((const float4*)x, (uint4*)xh, n16);
    }

    // MLP1 (merged routed + shared): x -> Hr (slots, gelu, fp16), Hs (tokens)
    mma_mlp<DIM, HID, true ><<<dim3(N_TOK / TBM, HID / TBN, NE + 1), 256, SMEM_SZ>>>(
        xh, xh, W1, sW1, b1, sb1,
        nullptr, nullptr, Hrh, Hsh);
    // MLP2 (merged): Hr -> Yr (*tw), Hs -> out
    mma_mlp<HID, DIM, false><<<dim3(N_TOK / TBM, DIM / TBN, NE + 1), 256, SMEM_SZ>>>(
        Hrh, Hsh, W2, sW2, b2, sb2,
        Yr, out, nullptr, nullptr);

    combine_kernel<<<(N_TOK * (DIM / 4) + 255) / 256, 256>>>(out);
}

// round 12
// speedup vs baseline: 2.3971x; 1.0050x over previous
#include <cuda_runtime.h>
#include <cuda_fp16.h>
#include <math.h>
#include <stdint.h>

#define N_TOK 4096
#define DIM   1024
#define HID   768
#define NE    23
#define TOPK  3
#define NSLOT (N_TOK * TOPK)

#define TBM 128
#define TBN 128
#define TBK 32
#define A_STRIDE 80      // 64B data + 16B pad
#define B_STRIDE 272     // 256B data + 16B pad
#define A_STG   10240    // per A stage
#define NSTAGE_A 4
#define B_OFF   (NSTAGE_A * A_STG)          // 40960
#define B_STG   8704                        // 32 * 272
#define EPI_SZ  (128 * 132 * 4)             // 67584
#define SMEM_SZ EPI_SZ

// ---------------- scratch ----------------
__device__ float g_gw[(size_t)N_TOK * NE];
__device__ int   g_counts[NE];
__device__ int   g_list[(size_t)NE * N_TOK];
__device__ float g_tw[NSLOT];
__device__ __half g_Yrh[(size_t)NSLOT * DIM];   // routed output, fp16

// fp16 activations
__device__ __half g_xh[(size_t)N_TOK * DIM];
__device__ __half g_Hsh[(size_t)N_TOK * HID];
__device__ __half g_Hrh[(size_t)NSLOT * HID];

__device__ __forceinline__ float gelu_exact(float v) {
    return 0.5f * v * (1.0f + erff(v * 0.7071067811865476f));
}
__device__ __forceinline__ uint32_t smem_u32(const void* p) {
    uint32_t a;
    asm("{ .reg .u64 t; cvta.to.shared.u64 t, %1; cvt.u32.u64 %0, t; }" : "=r"(a) : "l"(p));
    return a;
}
__device__ __forceinline__ void ldsm_x4(uint32_t addr, uint32_t* r) {
    asm volatile("ldmatrix.sync.aligned.m8n8.x4.shared.b16 {%0,%1,%2,%3}, [%4];"
                 : "=r"(r[0]), "=r"(r[1]), "=r"(r[2]), "=r"(r[3]) : "r"(addr));
}
__device__ __forceinline__ void ldsm_x4_t(uint32_t addr, uint32_t* r) {
    asm volatile("ldmatrix.sync.aligned.m8n8.x4.trans.shared.b16 {%0,%1,%2,%3}, [%4];"
                 : "=r"(r[0]), "=r"(r[1]), "=r"(r[2]), "=r"(r[3]) : "r"(addr));
}
__device__ __forceinline__ void mma_f16(float* c, const uint32_t* a, uint32_t b0, uint32_t b1) {
    asm volatile("mma.sync.aligned.m16n8k16.row.col.f32.f16.f16.f32 "
                 "{%0,%1,%2,%3}, {%4,%5,%6,%7}, {%8,%9}, {%0,%1,%2,%3};"
                 : "+f"(c[0]), "+f"(c[1]), "+f"(c[2]), "+f"(c[3])
                 : "r"(a[0]), "r"(a[1]), "r"(a[2]), "r"(a[3]), "r"(b0), "r"(b1));
}
__device__ __forceinline__ void cpa16(uint32_t dst, const void* src) {
    asm volatile("cp.async.cg.shared.global [%0], [%1], 16;" :: "r"(dst), "l"(src));
}
__device__ __forceinline__ void cpa_commit() {
    asm volatile("cp.async.commit_group;");
}
template<int N> __device__ __forceinline__ void cpa_wait() {
    asm volatile("cp.async.wait_group %0;" :: "n"(N));
}
__device__ __forceinline__ uint32_t pack2h(__half a, __half b) {
    return (uint32_t)__half_as_ushort(a) | ((uint32_t)__half_as_ushort(b) << 16);
}
__device__ __forceinline__ uint32_t cvt2h(float a, float b) {
    return pack2h(__float2half_rn(a), __float2half_rn(b));
}

// ---------------- prep: x -> fp16 (+ zero expert counters) ----------------
__global__ void cvt16_kernel(const float4* __restrict__ src, uint4* __restrict__ dst, int n16)
{
    if (blockIdx.x == 0 && threadIdx.x < NE) g_counts[threadIdx.x] = 0;
    int i = blockIdx.x * 256 + threadIdx.x;
    if (i < n16) {
        float4 a = src[4 * i];
        float4 b = src[4 * i + 1];
        float4 c = src[4 * i + 2];
        float4 d = src[4 * i + 3];
        uint4 o0, o1;
        o0.x = cvt2h(a.x, a.y); o0.y = cvt2h(a.z, a.w);
        o0.z = cvt2h(b.x, b.y); o0.w = cvt2h(b.z, b.w);
        o1.x = cvt2h(c.x, c.y); o1.y = cvt2h(c.z, c.w);
        o1.z = cvt2h(d.x, d.y); o1.w = cvt2h(d.z, d.w);
        dst[2 * i]     = o0;
        dst[2 * i + 1] = o1;
    }
}

// ---------------- gate (known-correct) ----------------
__global__ void gate_kernel(const float* __restrict__ x,
                            const float* __restrict__ gW,
                            const float* __restrict__ gb,
                            const float* __restrict__ rbias)
{
    __shared__ float xs[DIM];
    __shared__ float gv[NE];
    __shared__ float gsum_s;
    int n = blockIdx.x;
    int t = threadIdx.x;

    const float4* xv  = (const float4*)(x + (size_t)n * DIM);
    float4*       xsv = (float4*)xs;
    for (int i = t; i < DIM / 4; i += 128) xsv[i] = xv[i];
    __syncthreads();

    int e = t >> 2, j = t & 3;
    float acc = 0.f;
    if (e < NE) {
        for (int i = j; i < DIM; i += 4)
            acc += xs[i] * gW[i * NE + e];
    }
    acc += __shfl_xor_sync(0xffffffffu, acc, 1);
    acc += __shfl_xor_sync(0xffffffffu, acc, 2);
    if (e < NE && j == 0)
        gv[e] = 1.0f / (1.0f + expf(-(acc + gb[e])));
    __syncthreads();

    if (t == 0) {
        float s = 0.f;
        for (int q = 0; q < NE; q++) s += gv[q];
        gsum_s = s;
    }
    __syncthreads();

    if (t < NE) g_gw[(size_t)n * NE + t] = gv[t] / gsum_s;

    if (t == 0) {
        int   idx[TOPK];
        float w[TOPK];
        unsigned used = 0;
        for (int k = 0; k < TOPK; k++) {
            float best = -1e30f; int bi = 0;
            for (int q = 0; q < NE; q++) {
                if (used & (1u << q)) continue;
                float s = gv[q] + rbias[q];
                if (s > best) { best = s; bi = q; }
            }
            used |= (1u << bi);
            idx[k] = bi;
            w[k]   = gv[bi];
        }
        float ws = w[0] + w[1] + w[2];
        for (int k = 0; k < TOPK; k++) {
            int slot = n * TOPK + k;
            g_tw[slot] = w[k] / ws;
            int pos = atomicAdd(&g_counts[idx[k]], 1);
            g_list[(size_t)idx[k] * N_TOK + pos] = slot;
        }
    }
}

// ---------------- aux loss ----------------
__global__ void aux_kernel(float* __restrict__ out, int out_size)
{
    __shared__ float sm[256 * NE];
    int t = threadIdx.x;
    float loc[NE];
    #pragma unroll
    for (int e = 0; e < NE; e++) loc[e] = 0.f;
    for (int n = t; n < N_TOK; n += 256) {
        #pragma unroll
        for (int e = 0; e < NE; e++) loc[e] += g_gw[(size_t)n * NE + e];
    }
    for (int e = 0; e < NE; e++) sm[t * NE + e] = loc[e];
    __syncthreads();
    for (int s = 128; s > 0; s >>= 1) {
        if (t < s)
            for (int e = 0; e < NE; e++) sm[t * NE + e] += sm[(t + s) * NE + e];
        __syncthreads();
    }
    if (t == 0 && out_size > N_TOK * DIM) {
        float aux = 0.f;
        for (int e = 0; e < NE; e++) {
            float P = sm[e] / (float)N_TOK;
            float F = ((float)NE * (float)g_counts[e]) / ((float)TOPK * (float)N_TOK);
            aux += P * F;
        }
        out[(size_t)N_TOK * DIM] = aux;
    }
}

// ---------------- fp16 GEMM: A fp16 cp.async 4-stage, B fp32->fp16 in-loader ----------------
// blockIdx.z: z<NE routed expert z, z==NE shared.
// MLP1P: Out = gelu(D+bias) -> fp16 (OutRH/OutSH)
// else : routed -> fp16 (D+bias)*tw -> OutRH ; shared -> fp32 D+bias -> OutSF
template<int KDIM, int NOUT, bool MLP1P>
__global__ void __launch_bounds__(256, 2) mma_mlp(
    const __half* __restrict__ ArH, const __half* __restrict__ AsH,
    const float* __restrict__ BrF, const float* __restrict__ BsF,
    const float* __restrict__ biasR, const float* __restrict__ biasS,
    float* __restrict__ OutSF,
    __half* __restrict__ OutRH, __half* __restrict__ OutSH)
{
    constexpr int NC = KDIM / TBK;

    int ez = blockIdx.z;
    bool sh = (ez == NE);
    int cnt = sh ? N_TOK : g_counts[ez];
    int m0  = blockIdx.x * TBM;
    if (m0 >= cnt) return;
    int n0  = blockIdx.y * TBN;

    extern __shared__ char smem[];
    uint32_t sbase = smem_u32(smem);

    int tid  = threadIdx.x;
    int wid  = tid >> 5;
    int lane = tid & 31;
    int wm   = wid >> 2;   // 0..1 : rows wm*64..+63
    int wn   = wid & 3;    // 0..3 : cols wn*32..+31

    const __half* AH  = sh ? AsH : ArH;
    const float*  BF  = sh ? BsF : (BrF + (size_t)ez * KDIM * NOUT);
    const float* bias = sh ? biasS : (biasR + (size_t)ez * NOUT);

    // A: thread t -> row t>>1, half t&1 (16 elems = 2x16B units)
    int arow = tid >> 1;
    int au   = tid & 1;
    int gi_a = m0 + arow;
    int grow;
    if (sh) {
        grow = gi_a;
    } else {
        int gg   = (gi_a < cnt) ? gi_a : (cnt - 1);
        int slot = g_list[(size_t)ez * N_TOK + gg];
        grow = MLP1P ? (slot / TOPK) : slot;
    }
    const __half* ApH = AH + (size_t)grow * KDIM + au * 16;
    uint32_t aoff = (uint32_t)(arow * A_STRIDE + au * 32);

    auto issue_A = [&](int c, int st) {
        uint32_t sA = sbase + (uint32_t)(st * A_STG);
        int k0 = c * TBK;
        cpa16(sA + aoff,      ApH + k0);
        cpa16(sA + aoff + 16, ApH + k0 + 8);
        cpa_commit();
    };

    // B: thread t -> k-row t>>3 (0..31), cols n0 + (t&7)*8 and +64; fp32 source
    int bk = tid >> 3;
    int bc = tid & 7;
    const float* BpF = BF + (size_t)bk * NOUT + n0 + bc * 8;
    uint32_t boff = (uint32_t)(bk * B_STRIDE + bc * 16);

    float4 fb[4];
    auto load_B = [&](int c) {
        size_t k0n = (size_t)(c * TBK) * NOUT;
        fb[0] = *(const float4*)(BpF + k0n);
        fb[1] = *(const float4*)(BpF + k0n + 4);
        fb[2] = *(const float4*)(BpF + k0n + 64);
        fb[3] = *(const float4*)(BpF + k0n + 68);
    };
    auto store_B = [&](int bs) {
        char* dst = smem + B_OFF + bs * B_STG;
        uint4 v0, v1;
        v0.x = cvt2h(fb[0].x, fb[0].y); v0.y = cvt2h(fb[0].z, fb[0].w);
        v0.z = cvt2h(fb[1].x, fb[1].y); v0.w = cvt2h(fb[1].z, fb[1].w);
        v1.x = cvt2h(fb[2].x, fb[2].y); v1.y = cvt2h(fb[2].z, fb[2].w);
        v1.z = cvt2h(fb[3].x, fb[3].y); v1.w = cvt2h(fb[3].z, fb[3].w);
        *(uint4*)(dst + boff)       = v0;
        *(uint4*)(dst + boff + 128) = v1;
    };

    // prologue
    issue_A(0, 0);
    if (NC > 1) issue_A(1, 1);
    if (NC > 2) issue_A(2, 2);
    load_B(0);
    store_B(0);
    if (NC > 1) load_B(1);

    float acc[4][4][4];
    #pragma unroll
    for (int i = 0; i < 4; i++)
        #pragma unroll
        for (int j = 0; j < 4; j++)
            #pragma unroll
            for (int q = 0; q < 4; q++) acc[i][j][q] = 0.f;

    uint32_t aAddr = sbase + (uint32_t)((wm * 64 + (lane & 15)) * A_STRIDE + ((lane >> 4) << 4));
    uint32_t bAddr = sbase + B_OFF + (uint32_t)((lane & 15) * B_STRIDE + ((wn * 32 + (lane >> 4) * 8) << 1));

    int st = 0;
    for (int c = 0; c < NC; c++) {
        if (c + 3 <= NC)      cpa_wait<2>();
        else if (c + 2 == NC) cpa_wait<1>();
        else                  cpa_wait<0>();
        __syncthreads();
        if (c + 3 < NC) {
            int st3 = st + 3; if (st3 >= NSTAGE_A) st3 -= NSTAGE_A;
            issue_A(c + 3, st3);
        }
        if (c + 1 < NC) {
            store_B((c + 1) & 1);
            if (c + 2 < NC) load_B(c + 2);
        }
        uint32_t aS = aAddr + (uint32_t)(st * A_STG);
        uint32_t bS = bAddr + (uint32_t)((c & 1) * B_STG);
        #pragma unroll
        for (int ks = 0; ks < 2; ks++) {
            uint32_t ahF[4][4];
            #pragma unroll
            for (int i = 0; i < 4; i++)
                ldsm_x4(aS + ks * 32 + i * (16 * A_STRIDE), ahF[i]);
            uint32_t bhF[2][4];
            #pragma unroll
            for (int g = 0; g < 2; g++)
                ldsm_x4_t(bS + ks * (16 * B_STRIDE) + g * 32, bhF[g]);
            #pragma unroll
            for (int i = 0; i < 4; i++) {
                #pragma unroll
                for (int j = 0; j < 4; j++) {
                    int g = j >> 1, o = (j & 1) * 2;
                    mma_f16(acc[i][j], ahF[i], bhF[g][o], bhF[g][o + 1]);
                }
            }
        }
        if (++st == NSTAGE_A) st = 0;
    }
    __syncthreads();

    // ---- epilogue: frags -> smem (128 x 132 fp32), then coalesced global ----
    float* epi = (float*)smem;
    {
        int rb = wm * 64 + (lane >> 2);
        int cb = wn * 32 + (lane & 3) * 2;
        #pragma unroll
        for (int i = 0; i < 4; i++) {
            #pragma unroll
            for (int j = 0; j < 4; j++) {
                int r = rb + i * 16;
                int cc = cb + j * 8;
                epi[r * 132 + cc]           = acc[i][j][0];
                epi[r * 132 + cc + 1]       = acc[i][j][1];
                epi[(r + 8) * 132 + cc]     = acc[i][j][2];
                epi[(r + 8) * 132 + cc + 1] = acc[i][j][3];
            }
        }
    }
    __syncthreads();

    for (int i = tid; i < TBM * (TBN / 4); i += 256) {
        int r  = i >> 5;
        int c4 = i & 31;
        int gi = m0 + r;
        if (gi >= cnt) continue;
        float4 v = *(float4*)&epi[r * 132 + c4 * 4];
        int col = n0 + c4 * 4;
        float4 b4 = *(const float4*)(bias + col);
        v.x += b4.x; v.y += b4.y; v.z += b4.z; v.w += b4.w;
        if (MLP1P) {
            v.x = gelu_exact(v.x); v.y = gelu_exact(v.y);
            v.z = gelu_exact(v.z); v.w = gelu_exact(v.w);
            uint2 h;
            h.x = cvt2h(v.x, v.y);
            h.y = cvt2h(v.z, v.w);
            size_t orow;
            __half* OH;
            if (sh) { orow = (size_t)gi; OH = OutSH; }
            else    { orow = (size_t)g_list[(size_t)ez * N_TOK + gi]; OH = OutRH; }
            *(uint2*)(OH + orow * NOUT + col) = h;
        } else {
            if (sh) {
                *(float4*)(OutSF + (size_t)gi * NOUT + col) = v;
            } else {
                int slot = g_list[(size_t)ez * N_TOK + gi];
                float w = g_tw[slot];
                v.x *= w; v.y *= w; v.z *= w; v.w *= w;
                uint2 h;
                h.x = cvt2h(v.x, v.y);
                h.y = cvt2h(v.z, v.w);
                *(uint2*)(OutRH + (size_t)slot * NOUT + col) = h;
            }
        }
    }
}

// ---------------- combine: out += sum_k fp16 Yr[slot] ----------------
__global__ void combine_kernel(float* __restrict__ out)
{
    int idx = blockIdx.x * blockDim.x + threadIdx.x;
    if (idx >= N_TOK * (DIM / 4)) return;
    int n  = idx / (DIM / 4);
    int d4 = idx % (DIM / 4);
    float4 v = ((float4*)out)[idx];
    const uint2* yr = (const uint2*)g_Yrh;
    #pragma unroll
    for (int k = 0; k < TOPK; k++) {
        uint2 y = __ldg(&yr[(size_t)(n * TOPK + k) * (DIM / 4) + d4]);
        __half2 lo = *(__half2*)&y.x;
        __half2 hi = *(__half2*)&y.y;
        v.x += __low2float(lo);  v.y += __high2float(lo);
        v.z += __low2float(hi);  v.w += __high2float(hi);
    }
    ((float4*)out)[idx] = v;
}

// ---------------- launch ----------------
extern "C" void kernel_launch(void* const* d_in, const int* in_sizes, int n_in,
                              void* d_out, int out_size)
{
    const float* x   = (const float*)d_in[0];
    const float* gW  = (const float*)d_in[1];
    const float* gb  = (const float*)d_in[2];
    const float* rb  = (const float*)d_in[3];
    const float* W1  = (const float*)d_in[4];
    const float* b1  = (const float*)d_in[5];
    const float* W2  = (const float*)d_in[6];
    const float* b2  = (const float*)d_in[7];
    const float* sW1 = (const float*)d_in[8];
    const float* sb1 = (const float*)d_in[9];
    const float* sW2 = (const float*)d_in[10];
    const float* sb2 = (const float*)d_in[11];
    float* out = (float*)d_out;

    void* p;
    cudaGetSymbolAddress(&p, g_xh);   __half* xh   = (__half*)p;
    cudaGetSymbolAddress(&p, g_Hsh);  __half* Hsh  = (__half*)p;
    cudaGetSymbolAddress(&p, g_Hrh);  __half* Hrh  = (__half*)p;
    cudaGetSymbolAddress(&p, g_Yrh);  __half* Yrh  = (__half*)p;

    cudaFuncSetAttribute(mma_mlp<DIM, HID, true >, cudaFuncAttributeMaxDynamicSharedMemorySize, SMEM_SZ);
    cudaFuncSetAttribute(mma_mlp<HID, DIM, false>, cudaFuncAttributeMaxDynamicSharedMemorySize, SMEM_SZ);

    // launch order chosen so ncu's capture (cycle index 3) lands on mma1
    {
        int n16 = N_TOK * DIM / 16;
        cvt16_kernel<<<(n16 + 255) / 256, 256>>>((const float4*)x, (uint4*)xh, n16);  // 0 (+init)
    }
    gate_kernel<<<N_TOK, 128>>>(x, gW, gb, rb);                                        // 1
    aux_kernel<<<1, 256>>>(out, out_size);                                             // 2

    // 3: MLP1 (merged routed + shared): x -> Hr (slots, gelu, fp16), Hs (tokens)
    mma_mlp<DIM, HID, true ><<<dim3(N_TOK / TBM, HID / TBN, NE + 1), 256, SMEM_SZ>>>(
        xh, xh, W1, sW1, b1, sb1,
        nullptr, Hrh, Hsh);
    // 4: MLP2 (merged): Hr -> Yrh (*tw, fp16), Hs -> out (fp32)
    mma_mlp<HID, DIM, false><<<dim3(N_TOK / TBM, DIM / TBN, NE + 1), 256, SMEM_SZ>>>(
        Hrh, Hsh, W2, sW2, b2, sb2,
        out, Yrh, nullptr);

    combine_kernel<<<(N_TOK * (DIM / 4) + 255) / 256, 256>>>(out);                     // 5
}

// round 13
// speedup vs baseline: 2.4919x; 1.0395x over previous
#include <cuda_runtime.h>
#include <cuda_fp16.h>
#include <math.h>
#include <stdint.h>

#define N_TOK 4096
#define DIM   1024
#define HID   768
#define NE    23
#define TOPK  3
#define NSLOT (N_TOK * TOPK)

#define TBM 128
#define TBN 128
#define TBK 32
#define A_STRIDE 80      // 64B data + 16B pad
#define B_STRIDE 272     // 256B data + 16B pad
#define A_STG   10240    // per A stage
#define NSTAGE_A 4
#define B_OFF   (NSTAGE_A * A_STG)          // 40960
#define B_STG   8704                        // 32 * 272
#define EPI_SZ  (128 * 132 * 4)             // 67584
#define SMEM_SZ EPI_SZ

#define AUX_NB  64
#define AUX_TPB (N_TOK / AUX_NB)            // 64 tokens per block

// ---------------- scratch ----------------
__device__ float g_gw[(size_t)N_TOK * NE];
__device__ int   g_counts[NE];
__device__ int   g_list[(size_t)NE * N_TOK];
__device__ float g_tw[NSLOT];
__device__ float g_partial[AUX_NB * NE];
__device__ __half g_Yrh[(size_t)NSLOT * DIM];   // routed output, fp16

// fp16 activations
__device__ __half g_xh[(size_t)N_TOK * DIM];
__device__ __half g_Hsh[(size_t)N_TOK * HID];
__device__ __half g_Hrh[(size_t)NSLOT * HID];

__device__ __forceinline__ float gelu_exact(float v) {
    return 0.5f * v * (1.0f + erff(v * 0.7071067811865476f));
}
__device__ __forceinline__ uint32_t smem_u32(const void* p) {
    uint32_t a;
    asm("{ .reg .u64 t; cvta.to.shared.u64 t, %1; cvt.u32.u64 %0, t; }" : "=r"(a) : "l"(p));
    return a;
}
__device__ __forceinline__ void ldsm_x4(uint32_t addr, uint32_t* r) {
    asm volatile("ldmatrix.sync.aligned.m8n8.x4.shared.b16 {%0,%1,%2,%3}, [%4];"
                 : "=r"(r[0]), "=r"(r[1]), "=r"(r[2]), "=r"(r[3]) : "r"(addr));
}
__device__ __forceinline__ void ldsm_x4_t(uint32_t addr, uint32_t* r) {
    asm volatile("ldmatrix.sync.aligned.m8n8.x4.trans.shared.b16 {%0,%1,%2,%3}, [%4];"
                 : "=r"(r[0]), "=r"(r[1]), "=r"(r[2]), "=r"(r[3]) : "r"(addr));
}
__device__ __forceinline__ void mma_f16(float* c, const uint32_t* a, uint32_t b0, uint32_t b1) {
    asm volatile("mma.sync.aligned.m16n8k16.row.col.f32.f16.f16.f32 "
                 "{%0,%1,%2,%3}, {%4,%5,%6,%7}, {%8,%9}, {%0,%1,%2,%3};"
                 : "+f"(c[0]), "+f"(c[1]), "+f"(c[2]), "+f"(c[3])
                 : "r"(a[0]), "r"(a[1]), "r"(a[2]), "r"(a[3]), "r"(b0), "r"(b1));
}
__device__ __forceinline__ void cpa16(uint32_t dst, const void* src) {
    asm volatile("cp.async.cg.shared.global [%0], [%1], 16;" :: "r"(dst), "l"(src));
}
__device__ __forceinline__ void cpa_commit() {
    asm volatile("cp.async.commit_group;");
}
template<int N> __device__ __forceinline__ void cpa_wait() {
    asm volatile("cp.async.wait_group %0;" :: "n"(N));
}
__device__ __forceinline__ uint32_t pack2h(__half a, __half b) {
    return (uint32_t)__half_as_ushort(a) | ((uint32_t)__half_as_ushort(b) << 16);
}
__device__ __forceinline__ uint32_t cvt2h(float a, float b) {
    return pack2h(__float2half_rn(a), __float2half_rn(b));
}

// ---------------- prep: x -> fp16 (+ zero expert counters) ----------------
__global__ void cvt16_kernel(const float4* __restrict__ src, uint4* __restrict__ dst, int n16)
{
    if (blockIdx.x == 0 && threadIdx.x < NE) g_counts[threadIdx.x] = 0;
    int i = blockIdx.x * 256 + threadIdx.x;
    if (i < n16) {
        float4 a = src[4 * i];
        float4 b = src[4 * i + 1];
        float4 c = src[4 * i + 2];
        float4 d = src[4 * i + 3];
        uint4 o0, o1;
        o0.x = cvt2h(a.x, a.y); o0.y = cvt2h(a.z, a.w);
        o0.z = cvt2h(b.x, b.y); o0.w = cvt2h(b.z, b.w);
        o1.x = cvt2h(c.x, c.y); o1.y = cvt2h(c.z, c.w);
        o1.z = cvt2h(d.x, d.y); o1.w = cvt2h(d.z, d.w);
        dst[2 * i]     = o0;
        dst[2 * i + 1] = o1;
    }
}

// ---------------- gate (known-correct) ----------------
__global__ void gate_kernel(const float* __restrict__ x,
                            const float* __restrict__ gW,
                            const float* __restrict__ gb,
                            const float* __restrict__ rbias)
{
    __shared__ float xs[DIM];
    __shared__ float gv[NE];
    __shared__ float gsum_s;
    int n = blockIdx.x;
    int t = threadIdx.x;

    const float4* xv  = (const float4*)(x + (size_t)n * DIM);
    float4*       xsv = (float4*)xs;
    for (int i = t; i < DIM / 4; i += 128) xsv[i] = xv[i];
    __syncthreads();

    int e = t >> 2, j = t & 3;
    float acc = 0.f;
    if (e < NE) {
        for (int i = j; i < DIM; i += 4)
            acc += xs[i] * gW[i * NE + e];
    }
    acc += __shfl_xor_sync(0xffffffffu, acc, 1);
    acc += __shfl_xor_sync(0xffffffffu, acc, 2);
    if (e < NE && j == 0)
        gv[e] = 1.0f / (1.0f + expf(-(acc + gb[e])));
    __syncthreads();

    if (t == 0) {
        float s = 0.f;
        for (int q = 0; q < NE; q++) s += gv[q];
        gsum_s = s;
    }
    __syncthreads();

    if (t < NE) g_gw[(size_t)n * NE + t] = gv[t] / gsum_s;

    if (t == 0) {
        int   idx[TOPK];
        float w[TOPK];
        unsigned used = 0;
        for (int k = 0; k < TOPK; k++) {
            float best = -1e30f; int bi = 0;
            for (int q = 0; q < NE; q++) {
                if (used & (1u << q)) continue;
                float s = gv[q] + rbias[q];
                if (s > best) { best = s; bi = q; }
            }
            used |= (1u << bi);
            idx[k] = bi;
            w[k]   = gv[bi];
        }
        float ws = w[0] + w[1] + w[2];
        for (int k = 0; k < TOPK; k++) {
            int slot = n * TOPK + k;
            g_tw[slot] = w[k] / ws;
            int pos = atomicAdd(&g_counts[idx[k]], 1);
            g_list[(size_t)idx[k] * N_TOK + pos] = slot;
        }
    }
}

// ---------------- aux phase 1: coalesced per-block partial sums ----------------
__global__ void aux1_kernel()
{
    __shared__ float sm[AUX_TPB * NE];   // 64*23 = 1472 floats
    int b = blockIdx.x;
    int t = threadIdx.x;                 // 256 threads
    const float* src = g_gw + (size_t)b * AUX_TPB * NE;
    for (int i = t; i < AUX_TPB * NE; i += 256) sm[i] = src[i];
    __syncthreads();
    if (t < NE) {
        float s = 0.f;
        #pragma unroll
        for (int r = 0; r < AUX_TPB; r++) s += sm[r * NE + t];
        g_partial[b * NE + t] = s;
    }
}

// ---------------- aux phase 2: fold partials + counts ----------------
__global__ void aux2_kernel(float* __restrict__ out, int out_size)
{
    __shared__ float Ps[NE];
    int t = threadIdx.x;                 // 32 threads
    if (t < NE) {
        float s = 0.f;
        for (int b = 0; b < AUX_NB; b++) s += g_partial[b * NE + t];
        Ps[t] = s;
    }
    __syncwarp();
    if (t == 0 && out_size > N_TOK * DIM) {
        float aux = 0.f;
        for (int e = 0; e < NE; e++) {
            float P = Ps[e] / (float)N_TOK;
            float F = ((float)NE * (float)g_counts[e]) / ((float)TOPK * (float)N_TOK);
            aux += P * F;
        }
        out[(size_t)N_TOK * DIM] = aux;
    }
}

// ---------------- fp16 GEMM: A fp16 cp.async 4-stage, B fp32->fp16 in-loader ----------------
// blockIdx.z: z<NE routed expert z, z==NE shared.
// MLP1P: Out = gelu(D+bias) -> fp16 (OutRH/OutSH)
// else : routed -> fp16 (D+bias)*tw -> OutRH ; shared -> fp32 D+bias -> OutSF
template<int KDIM, int NOUT, bool MLP1P>
__global__ void __launch_bounds__(256, 2) mma_mlp(
    const __half* __restrict__ ArH, const __half* __restrict__ AsH,
    const float* __restrict__ BrF, const float* __restrict__ BsF,
    const float* __restrict__ biasR, const float* __restrict__ biasS,
    float* __restrict__ OutSF,
    __half* __restrict__ OutRH, __half* __restrict__ OutSH)
{
    constexpr int NC = KDIM / TBK;

    int ez = blockIdx.z;
    bool sh = (ez == NE);
    int cnt = sh ? N_TOK : g_counts[ez];
    int m0  = blockIdx.x * TBM;
    if (m0 >= cnt) return;
    int n0  = blockIdx.y * TBN;

    extern __shared__ char smem[];
    uint32_t sbase = smem_u32(smem);

    int tid  = threadIdx.x;
    int wid  = tid >> 5;
    int lane = tid & 31;
    int wm   = wid >> 2;   // 0..1 : rows wm*64..+63
    int wn   = wid & 3;    // 0..3 : cols wn*32..+31

    const __half* AH  = sh ? AsH : ArH;
    const float*  BF  = sh ? BsF : (BrF + (size_t)ez * KDIM * NOUT);
    const float* bias = sh ? biasS : (biasR + (size_t)ez * NOUT);

    // A: thread t -> row t>>1, half t&1 (16 elems = 2x16B units)
    int arow = tid >> 1;
    int au   = tid & 1;
    int gi_a = m0 + arow;
    int grow;
    if (sh) {
        grow = gi_a;
    } else {
        int gg   = (gi_a < cnt) ? gi_a : (cnt - 1);
        int slot = g_list[(size_t)ez * N_TOK + gg];
        grow = MLP1P ? (slot / TOPK) : slot;
    }
    const __half* ApH = AH + (size_t)grow * KDIM + au * 16;
    uint32_t aoff = (uint32_t)(arow * A_STRIDE + au * 32);

    auto issue_A = [&](int c, int st) {
        uint32_t sA = sbase + (uint32_t)(st * A_STG);
        int k0 = c * TBK;
        cpa16(sA + aoff,      ApH + k0);
        cpa16(sA + aoff + 16, ApH + k0 + 8);
        cpa_commit();
    };

    // B: thread t -> k-row t>>3 (0..31), cols n0 + (t&7)*8 and +64; fp32 source
    int bk = tid >> 3;
    int bc = tid & 7;
    const float* BpF = BF + (size_t)bk * NOUT + n0 + bc * 8;
    uint32_t boff = (uint32_t)(bk * B_STRIDE + bc * 16);

    float4 fb[4];
    auto load_B = [&](int c) {
        size_t k0n = (size_t)(c * TBK) * NOUT;
        fb[0] = *(const float4*)(BpF + k0n);
        fb[1] = *(const float4*)(BpF + k0n + 4);
        fb[2] = *(const float4*)(BpF + k0n + 64);
        fb[3] = *(const float4*)(BpF + k0n + 68);
    };
    auto store_B = [&](int bs) {
        char* dst = smem + B_OFF + bs * B_STG;
        uint4 v0, v1;
        v0.x = cvt2h(fb[0].x, fb[0].y); v0.y = cvt2h(fb[0].z, fb[0].w);
        v0.z = cvt2h(fb[1].x, fb[1].y); v0.w = cvt2h(fb[1].z, fb[1].w);
        v1.x = cvt2h(fb[2].x, fb[2].y); v1.y = cvt2h(fb[2].z, fb[2].w);
        v1.z = cvt2h(fb[3].x, fb[3].y); v1.w = cvt2h(fb[3].z, fb[3].w);
        *(uint4*)(dst + boff)       = v0;
        *(uint4*)(dst + boff + 128) = v1;
    };

    // prologue
    issue_A(0, 0);
    if (NC > 1) issue_A(1, 1);
    if (NC > 2) issue_A(2, 2);
    load_B(0);
    store_B(0);
    if (NC > 1) load_B(1);

    float acc[4][4][4];
    #pragma unroll
    for (int i = 0; i < 4; i++)
        #pragma unroll
        for (int j = 0; j < 4; j++)
            #pragma unroll
            for (int q = 0; q < 4; q++) acc[i][j][q] = 0.f;

    uint32_t aAddr = sbase + (uint32_t)((wm * 64 + (lane & 15)) * A_STRIDE + ((lane >> 4) << 4));
    uint32_t bAddr = sbase + B_OFF + (uint32_t)((lane & 15) * B_STRIDE + ((wn * 32 + (lane >> 4) * 8) << 1));

    int st = 0;
    for (int c = 0; c < NC; c++) {
        if (c + 3 <= NC)      cpa_wait<2>();
        else if (c + 2 == NC) cpa_wait<1>();
        else                  cpa_wait<0>();
        __syncthreads();
        if (c + 3 < NC) {
            int st3 = st + 3; if (st3 >= NSTAGE_A) st3 -= NSTAGE_A;
            issue_A(c + 3, st3);
        }
        if (c + 1 < NC) {
            store_B((c + 1) & 1);
            if (c + 2 < NC) load_B(c + 2);
        }
        uint32_t aS = aAddr + (uint32_t)(st * A_STG);
        uint32_t bS = bAddr + (uint32_t)((c & 1) * B_STG);
        #pragma unroll
        for (int ks = 0; ks < 2; ks++) {
            uint32_t ahF[4][4];
            #pragma unroll
            for (int i = 0; i < 4; i++)
                ldsm_x4(aS + ks * 32 + i * (16 * A_STRIDE), ahF[i]);
            uint32_t bhF[2][4];
            #pragma unroll
            for (int g = 0; g < 2; g++)
                ldsm_x4_t(bS + ks * (16 * B_STRIDE) + g * 32, bhF[g]);
            #pragma unroll
            for (int i = 0; i < 4; i++) {
                #pragma unroll
                for (int j = 0; j < 4; j++) {
                    int g = j >> 1, o = (j & 1) * 2;
                    mma_f16(acc[i][j], ahF[i], bhF[g][o], bhF[g][o + 1]);
                }
            }
        }
        if (++st == NSTAGE_A) st = 0;
    }
    __syncthreads();

    // ---- epilogue: frags -> smem (128 x 132 fp32), then coalesced global ----
    float* epi = (float*)smem;
    {
        int rb = wm * 64 + (lane >> 2);
        int cb = wn * 32 + (lane & 3) * 2;
        #pragma unroll
        for (int i = 0; i < 4; i++) {
            #pragma unroll
            for (int j = 0; j < 4; j++) {
                int r = rb + i * 16;
                int cc = cb + j * 8;
                epi[r * 132 + cc]           = acc[i][j][0];
                epi[r * 132 + cc + 1]       = acc[i][j][1];
                epi[(r + 8) * 132 + cc]     = acc[i][j][2];
                epi[(r + 8) * 132 + cc + 1] = acc[i][j][3];
            }
        }
    }
    __syncthreads();

    for (int i = tid; i < TBM * (TBN / 4); i += 256) {
        int r  = i >> 5;
        int c4 = i & 31;
        int gi = m0 + r;
        if (gi >= cnt) continue;
        float4 v = *(float4*)&epi[r * 132 + c4 * 4];
        int col = n0 + c4 * 4;
        float4 b4 = *(const float4*)(bias + col);
        v.x += b4.x; v.y += b4.y; v.z += b4.z; v.w += b4.w;
        if (MLP1P) {
            v.x = gelu_exact(v.x); v.y = gelu_exact(v.y);
            v.z = gelu_exact(v.z); v.w = gelu_exact(v.w);
            uint2 h;
            h.x = cvt2h(v.x, v.y);
            h.y = cvt2h(v.z, v.w);
            size_t orow;
            __half* OH;
            if (sh) { orow = (size_t)gi; OH = OutSH; }
            else    { orow = (size_t)g_list[(size_t)ez * N_TOK + gi]; OH = OutRH; }
            *(uint2*)(OH + orow * NOUT + col) = h;
        } else {
            if (sh) {
                *(float4*)(OutSF + (size_t)gi * NOUT + col) = v;
            } else {
                int slot = g_list[(size_t)ez * N_TOK + gi];
                float w = g_tw[slot];
                v.x *= w; v.y *= w; v.z *= w; v.w *= w;
                uint2 h;
                h.x = cvt2h(v.x, v.y);
                h.y = cvt2h(v.z, v.w);
                *(uint2*)(OutRH + (size_t)slot * NOUT + col) = h;
            }
        }
    }
}

// ---------------- combine: out += sum_k fp16 Yr[slot] ----------------
__global__ void combine_kernel(float* __restrict__ out)
{
    int idx = blockIdx.x * blockDim.x + threadIdx.x;
    if (idx >= N_TOK * (DIM / 4)) return;
    int n  = idx / (DIM / 4);
    int d4 = idx % (DIM / 4);
    float4 v = ((float4*)out)[idx];
    const uint2* yr = (const uint2*)g_Yrh;
    #pragma unroll
    for (int k = 0; k < TOPK; k++) {
        uint2 y = __ldg(&yr[(size_t)(n * TOPK + k) * (DIM / 4) + d4]);
        __half2 lo = *(__half2*)&y.x;
        __half2 hi = *(__half2*)&y.y;
        v.x += __low2float(lo);  v.y += __high2float(lo);
        v.z += __low2float(hi);  v.w += __high2float(hi);
    }
    ((float4*)out)[idx] = v;
}

// ---------------- launch ----------------
extern "C" void kernel_launch(void* const* d_in, const int* in_sizes, int n_in,
                              void* d_out, int out_size)
{
    const float* x   = (const float*)d_in[0];
    const float* gW  = (const float*)d_in[1];
    const float* gb  = (const float*)d_in[2];
    const float* rb  = (const float*)d_in[3];
    const float* W1  = (const float*)d_in[4];
    const float* b1  = (const float*)d_in[5];
    const float* W2  = (const float*)d_in[6];
    const float* b2  = (const float*)d_in[7];
    const float* sW1 = (const float*)d_in[8];
    const float* sb1 = (const float*)d_in[9];
    const float* sW2 = (const float*)d_in[10];
    const float* sb2 = (const float*)d_in[11];
    float* out = (float*)d_out;

    void* p;
    cudaGetSymbolAddress(&p, g_xh);   __half* xh   = (__half*)p;
    cudaGetSymbolAddress(&p, g_Hsh);  __half* Hsh  = (__half*)p;
    cudaGetSymbolAddress(&p, g_Hrh);  __half* Hrh  = (__half*)p;
    cudaGetSymbolAddress(&p, g_Yrh);  __half* Yrh  = (__half*)p;

    cudaFuncSetAttribute(mma_mlp<DIM, HID, true >, cudaFuncAttributeMaxDynamicSharedMemorySize, SMEM_SZ);
    cudaFuncSetAttribute(mma_mlp<HID, DIM, false>, cudaFuncAttributeMaxDynamicSharedMemorySize, SMEM_SZ);

    // launch order: index 3 (profiler capture slot) = mma2 this round
    {
        int n16 = N_TOK * DIM / 16;
        cvt16_kernel<<<(n16 + 255) / 256, 256>>>((const float4*)x, (uint4*)xh, n16);  // 0 (+init)
    }
    gate_kernel<<<N_TOK, 128>>>(x, gW, gb, rb);                                        // 1

    // 2: MLP1 (merged routed + shared): x -> Hr (slots, gelu, fp16), Hs (tokens)
    mma_mlp<DIM, HID, true ><<<dim3(N_TOK / TBM, HID / TBN, NE + 1), 256, SMEM_SZ>>>(
        xh, xh, W1, sW1, b1, sb1,
        nullptr, Hrh, Hsh);
    // 3: MLP2 (merged): Hr -> Yrh (*tw, fp16), Hs -> out (fp32)
    mma_mlp<HID, DIM, false><<<dim3(N_TOK / TBM, DIM / TBN, NE + 1), 256, SMEM_SZ>>>(
        Hrh, Hsh, W2, sW2, b2, sb2,
        out, Yrh, nullptr);

    aux1_kernel<<<AUX_NB, 256>>>();                                                    // 4
    aux2_kernel<<<1, 32>>>(out, out_size);                                             // 5
    combine_kernel<<<(N_TOK * (DIM / 4) + 255) / 256, 256>>>(out);                     // 6
}

// round 14
// speedup vs baseline: 2.5353x; 1.0174x over previous
#include <cuda_runtime.h>
#include <cuda_fp16.h>
#include <math.h>
#include <stdint.h>

#define N_TOK 4096
#define DIM   1024
#define HID   768
#define NE    23
#define TOPK  3
#define NSLOT (N_TOK * TOPK)

#define TBM 128
#define TBN 128
#define TBK 32
#define A_STRIDE 80      // 64B data + 16B pad
#define B_STRIDE 272     // 256B data + 16B pad
#define A_STG   10240    // per A stage
#define NSTAGE_A 4
#define B_OFF   (NSTAGE_A * A_STG)          // 40960
#define B_STG   8704                        // 32 * 272
#define EPI_SZ  (128 * 132 * 4)             // 67584
#define SMEM_SZ EPI_SZ

#define AUX_NB  64
#define AUX_TPB (N_TOK / AUX_NB)            // 64 tokens per block

#define GATE_TPB 8                          // tokens per gate block
#define GATE_SMEM ((DIM * NE + GATE_TPB * DIM) * 4)   // 92KB gW + 32KB x

// ---------------- scratch ----------------
__device__ float g_gw[(size_t)N_TOK * NE];
__device__ int   g_counts[NE];
__device__ int   g_list[(size_t)NE * N_TOK];
__device__ float g_tw[NSLOT];
__device__ float g_partial[AUX_NB * NE];
__device__ __half g_Yrh[(size_t)NSLOT * DIM];   // routed output, fp16

// fp16 activations
__device__ __half g_xh[(size_t)N_TOK * DIM];
__device__ __half g_Hsh[(size_t)N_TOK * HID];
__device__ __half g_Hrh[(size_t)NSLOT * HID];

__device__ __forceinline__ float gelu_exact(float v) {
    return 0.5f * v * (1.0f + erff(v * 0.7071067811865476f));
}
__device__ __forceinline__ uint32_t smem_u32(const void* p) {
    uint32_t a;
    asm("{ .reg .u64 t; cvta.to.shared.u64 t, %1; cvt.u32.u64 %0, t; }" : "=r"(a) : "l"(p));
    return a;
}
__device__ __forceinline__ void ldsm_x4(uint32_t addr, uint32_t* r) {
    asm volatile("ldmatrix.sync.aligned.m8n8.x4.shared.b16 {%0,%1,%2,%3}, [%4];"
                 : "=r"(r[0]), "=r"(r[1]), "=r"(r[2]), "=r"(r[3]) : "r"(addr));
}
__device__ __forceinline__ void ldsm_x4_t(uint32_t addr, uint32_t* r) {
    asm volatile("ldmatrix.sync.aligned.m8n8.x4.trans.shared.b16 {%0,%1,%2,%3}, [%4];"
                 : "=r"(r[0]), "=r"(r[1]), "=r"(r[2]), "=r"(r[3]) : "r"(addr));
}
__device__ __forceinline__ void mma_f16(float* c, const uint32_t* a, uint32_t b0, uint32_t b1) {
    asm volatile("mma.sync.aligned.m16n8k16.row.col.f32.f16.f16.f32 "
                 "{%0,%1,%2,%3}, {%4,%5,%6,%7}, {%8,%9}, {%0,%1,%2,%3};"
                 : "+f"(c[0]), "+f"(c[1]), "+f"(c[2]), "+f"(c[3])
                 : "r"(a[0]), "r"(a[1]), "r"(a[2]), "r"(a[3]), "r"(b0), "r"(b1));
}
__device__ __forceinline__ void cpa16(uint32_t dst, const void* src) {
    asm volatile("cp.async.cg.shared.global [%0], [%1], 16;" :: "r"(dst), "l"(src));
}
__device__ __forceinline__ void cpa_commit() {
    asm volatile("cp.async.commit_group;");
}
template<int N> __device__ __forceinline__ void cpa_wait() {
    asm volatile("cp.async.wait_group %0;" :: "n"(N));
}
__device__ __forceinline__ uint32_t pack2h(__half a, __half b) {
    return (uint32_t)__half_as_ushort(a) | ((uint32_t)__half_as_ushort(b) << 16);
}
__device__ __forceinline__ uint32_t cvt2h(float a, float b) {
    return pack2h(__float2half_rn(a), __float2half_rn(b));
}

// ---------------- prep: x -> fp16 (+ zero expert counters) ----------------
__global__ void cvt16_kernel(const float4* __restrict__ src, uint4* __restrict__ dst, int n16)
{
    if (blockIdx.x == 0 && threadIdx.x < NE) g_counts[threadIdx.x] = 0;
    int i = blockIdx.x * 256 + threadIdx.x;
    if (i < n16) {
        float4 a = src[4 * i];
        float4 b = src[4 * i + 1];
        float4 c = src[4 * i + 2];
        float4 d = src[4 * i + 3];
        uint4 o0, o1;
        o0.x = cvt2h(a.x, a.y); o0.y = cvt2h(a.z, a.w);
        o0.z = cvt2h(b.x, b.y); o0.w = cvt2h(b.z, b.w);
        o1.x = cvt2h(c.x, c.y); o1.y = cvt2h(c.z, c.w);
        o1.z = cvt2h(d.x, d.y); o1.w = cvt2h(d.z, d.w);
        dst[2 * i]     = o0;
        dst[2 * i + 1] = o1;
    }
}

// ---------------- gate: 8 tokens per block, gW staged in smem ----------------
__global__ void __launch_bounds__(256) gate8_kernel(
    const float* __restrict__ x,
    const float* __restrict__ gW,
    const float* __restrict__ gb,
    const float* __restrict__ rbias)
{
    extern __shared__ float dyn[];
    float* gWs = dyn;                    // DIM*NE floats
    float* xs  = dyn + DIM * NE;         // GATE_TPB*DIM floats
    __shared__ float gv[GATE_TPB][NE];

    int t = threadIdx.x;
    // stage gW (coalesced): DIM*NE = 23552 floats = 5888 float4
    const float4* gWv = (const float4*)gW;
    for (int i = t; i < DIM * NE / 4; i += 256) ((float4*)gWs)[i] = gWv[i];
    // stage 8 token rows
    const float4* xv = (const float4*)(x + (size_t)blockIdx.x * GATE_TPB * DIM);
    for (int i = t; i < GATE_TPB * DIM / 4; i += 256) ((float4*)xs)[i] = xv[i];
    __syncthreads();

    int w = t >> 5;      // warp = token within block
    int l = t & 31;      // lane = expert (l < NE)
    int n = blockIdx.x * GATE_TPB + w;

    if (l < NE) {
        const float* xrow = xs + w * DIM;
        float acc = 0.f;
        #pragma unroll 8
        for (int i = 0; i < DIM; i++)
            acc += xrow[i] * gWs[i * NE + l];
        gv[w][l] = 1.0f / (1.0f + expf(-(acc + gb[l])));
    }
    __syncwarp();

    // normalized gate weights (deterministic fixed-order sum)
    float gsum = 0.f;
    #pragma unroll
    for (int q = 0; q < NE; q++) gsum += gv[w][q];
    if (l < NE) g_gw[(size_t)n * NE + l] = gv[w][l] / gsum;

    if (l == 0) {
        int   idx[TOPK];
        float wv[TOPK];
        unsigned used = 0;
        for (int k = 0; k < TOPK; k++) {
            float best = -1e30f; int bi = 0;
            for (int q = 0; q < NE; q++) {
                if (used & (1u << q)) continue;
                float s = gv[w][q] + rbias[q];
                if (s > best) { best = s; bi = q; }
            }
            used |= (1u << bi);
            idx[k] = bi;
            wv[k]  = gv[w][bi];
        }
        float ws = wv[0] + wv[1] + wv[2];
        for (int k = 0; k < TOPK; k++) {
            int slot = n * TOPK + k;
            g_tw[slot] = wv[k] / ws;
            int pos = atomicAdd(&g_counts[idx[k]], 1);
            g_list[(size_t)idx[k] * N_TOK + pos] = slot;
        }
    }
}

// ---------------- aux phase 1: coalesced per-block partial sums ----------------
__global__ void aux1_kernel()
{
    __shared__ float sm[AUX_TPB * NE];
    int b = blockIdx.x;
    int t = threadIdx.x;
    const float* src = g_gw + (size_t)b * AUX_TPB * NE;
    for (int i = t; i < AUX_TPB * NE; i += 256) sm[i] = src[i];
    __syncthreads();
    if (t < NE) {
        float s = 0.f;
        #pragma unroll
        for (int r = 0; r < AUX_TPB; r++) s += sm[r * NE + t];
        g_partial[b * NE + t] = s;
    }
}

// ---------------- fp16 GEMM: A fp16 cp.async 4-stage, B fp32->fp16 in-loader ----------------
template<int KDIM, int NOUT, bool MLP1P>
__global__ void __launch_bounds__(256, 2) mma_mlp(
    const __half* __restrict__ ArH, const __half* __restrict__ AsH,
    const float* __restrict__ BrF, const float* __restrict__ BsF,
    const float* __restrict__ biasR, const float* __restrict__ biasS,
    float* __restrict__ OutSF,
    __half* __restrict__ OutRH, __half* __restrict__ OutSH)
{
    constexpr int NC = KDIM / TBK;

    int ez = blockIdx.z;
    bool sh = (ez == NE);
    int cnt = sh ? N_TOK : g_counts[ez];
    int m0  = blockIdx.x * TBM;
    if (m0 >= cnt) return;
    int n0  = blockIdx.y * TBN;

    extern __shared__ char smem[];
    uint32_t sbase = smem_u32(smem);

    int tid  = threadIdx.x;
    int wid  = tid >> 5;
    int lane = tid & 31;
    int wm   = wid >> 2;
    int wn   = wid & 3;

    const __half* AH  = sh ? AsH : ArH;
    const float*  BF  = sh ? BsF : (BrF + (size_t)ez * KDIM * NOUT);
    const float* bias = sh ? biasS : (biasR + (size_t)ez * NOUT);

    int arow = tid >> 1;
    int au   = tid & 1;
    int gi_a = m0 + arow;
    int grow;
    if (sh) {
        grow = gi_a;
    } else {
        int gg   = (gi_a < cnt) ? gi_a : (cnt - 1);
        int slot = g_list[(size_t)ez * N_TOK + gg];
        grow = MLP1P ? (slot / TOPK) : slot;
    }
    const __half* ApH = AH + (size_t)grow * KDIM + au * 16;
    uint32_t aoff = (uint32_t)(arow * A_STRIDE + au * 32);

    auto issue_A = [&](int c, int st) {
        uint32_t sA = sbase + (uint32_t)(st * A_STG);
        int k0 = c * TBK;
        cpa16(sA + aoff,      ApH + k0);
        cpa16(sA + aoff + 16, ApH + k0 + 8);
        cpa_commit();
    };

    int bk = tid >> 3;
    int bc = tid & 7;
    const float* BpF = BF + (size_t)bk * NOUT + n0 + bc * 8;
    uint32_t boff = (uint32_t)(bk * B_STRIDE + bc * 16);

    float4 fb[4];
    auto load_B = [&](int c) {
        size_t k0n = (size_t)(c * TBK) * NOUT;
        fb[0] = *(const float4*)(BpF + k0n);
        fb[1] = *(const float4*)(BpF + k0n + 4);
        fb[2] = *(const float4*)(BpF + k0n + 64);
        fb[3] = *(const float4*)(BpF + k0n + 68);
    };
    auto store_B = [&](int bs) {
        char* dst = smem + B_OFF + bs * B_STG;
        uint4 v0, v1;
        v0.x = cvt2h(fb[0].x, fb[0].y); v0.y = cvt2h(fb[0].z, fb[0].w);
        v0.z = cvt2h(fb[1].x, fb[1].y); v0.w = cvt2h(fb[1].z, fb[1].w);
        v1.x = cvt2h(fb[2].x, fb[2].y); v1.y = cvt2h(fb[2].z, fb[2].w);
        v1.z = cvt2h(fb[3].x, fb[3].y); v1.w = cvt2h(fb[3].z, fb[3].w);
        *(uint4*)(dst + boff)       = v0;
        *(uint4*)(dst + boff + 128) = v1;
    };

    issue_A(0, 0);
    if (NC > 1) issue_A(1, 1);
    if (NC > 2) issue_A(2, 2);
    load_B(0);
    store_B(0);
    if (NC > 1) load_B(1);

    float acc[4][4][4];
    #pragma unroll
    for (int i = 0; i < 4; i++)
        #pragma unroll
        for (int j = 0; j < 4; j++)
            #pragma unroll
            for (int q = 0; q < 4; q++) acc[i][j][q] = 0.f;

    uint32_t aAddr = sbase + (uint32_t)((wm * 64 + (lane & 15)) * A_STRIDE + ((lane >> 4) << 4));
    uint32_t bAddr = sbase + B_OFF + (uint32_t)((lane & 15) * B_STRIDE + ((wn * 32 + (lane >> 4) * 8) << 1));

    int st = 0;
    for (int c = 0; c < NC; c++) {
        if (c + 3 <= NC)      cpa_wait<2>();
        else if (c + 2 == NC) cpa_wait<1>();
        else                  cpa_wait<0>();
        __syncthreads();
        if (c + 3 < NC) {
            int st3 = st + 3; if (st3 >= NSTAGE_A) st3 -= NSTAGE_A;
            issue_A(c + 3, st3);
        }
        if (c + 1 < NC) {
            store_B((c + 1) & 1);
            if (c + 2 < NC) load_B(c + 2);
        }
        uint32_t aS = aAddr + (uint32_t)(st * A_STG);
        uint32_t bS = bAddr + (uint32_t)((c & 1) * B_STG);
        #pragma unroll
        for (int ks = 0; ks < 2; ks++) {
            uint32_t ahF[4][4];
            #pragma unroll
            for (int i = 0; i < 4; i++)
                ldsm_x4(aS + ks * 32 + i * (16 * A_STRIDE), ahF[i]);
            uint32_t bhF[2][4];
            #pragma unroll
            for (int g = 0; g < 2; g++)
                ldsm_x4_t(bS + ks * (16 * B_STRIDE) + g * 32, bhF[g]);
            #pragma unroll
            for (int i = 0; i < 4; i++) {
                #pragma unroll
                for (int j = 0; j < 4; j++) {
                    int g = j >> 1, o = (j & 1) * 2;
                    mma_f16(acc[i][j], ahF[i], bhF[g][o], bhF[g][o + 1]);
                }
            }
        }
        if (++st == NSTAGE_A) st = 0;
    }
    __syncthreads();

    float* epi = (float*)smem;
    {
        int rb = wm * 64 + (lane >> 2);
        int cb = wn * 32 + (lane & 3) * 2;
        #pragma unroll
        for (int i = 0; i < 4; i++) {
            #pragma unroll
            for (int j = 0; j < 4; j++) {
                int r = rb + i * 16;
                int cc = cb + j * 8;
                epi[r * 132 + cc]           = acc[i][j][0];
                epi[r * 132 + cc + 1]       = acc[i][j][1];
                epi[(r + 8) * 132 + cc]     = acc[i][j][2];
                epi[(r + 8) * 132 + cc + 1] = acc[i][j][3];
            }
        }
    }
    __syncthreads();

    for (int i = tid; i < TBM * (TBN / 4); i += 256) {
        int r  = i >> 5;
        int c4 = i & 31;
        int gi = m0 + r;
        if (gi >= cnt) continue;
        float4 v = *(float4*)&epi[r * 132 + c4 * 4];
        int col = n0 + c4 * 4;
        float4 b4 = *(const float4*)(bias + col);
        v.x += b4.x; v.y += b4.y; v.z += b4.z; v.w += b4.w;
        if (MLP1P) {
            v.x = gelu_exact(v.x); v.y = gelu_exact(v.y);
            v.z = gelu_exact(v.z); v.w = gelu_exact(v.w);
            uint2 h;
            h.x = cvt2h(v.x, v.y);
            h.y = cvt2h(v.z, v.w);
            size_t orow;
            __half* OH;
            if (sh) { orow = (size_t)gi; OH = OutSH; }
            else    { orow = (size_t)g_list[(size_t)ez * N_TOK + gi]; OH = OutRH; }
            *(uint2*)(OH + orow * NOUT + col) = h;
        } else {
            if (sh) {
                *(float4*)(OutSF + (size_t)gi * NOUT + col) = v;
            } else {
                int slot = g_list[(size_t)ez * N_TOK + gi];
                float w = g_tw[slot];
                v.x *= w; v.y *= w; v.z *= w; v.w *= w;
                uint2 h;
                h.x = cvt2h(v.x, v.y);
                h.y = cvt2h(v.z, v.w);
                *(uint2*)(OutRH + (size_t)slot * NOUT + col) = h;
            }
        }
    }
}

// ---------------- combine: out += sum_k fp16 Yr[slot]  (+ aux scalar in block 0) ----------------
__global__ void combine_kernel(float* __restrict__ out, int out_size)
{
    if (blockIdx.x == 0 && threadIdx.x == 0 && out_size > N_TOK * DIM) {
        float Ps[NE];
        #pragma unroll
        for (int e = 0; e < NE; e++) Ps[e] = 0.f;
        for (int b = 0; b < AUX_NB; b++)
            #pragma unroll
            for (int e = 0; e < NE; e++) Ps[e] += g_partial[b * NE + e];
        float aux = 0.f;
        for (int e = 0; e < NE; e++) {
            float P = Ps[e] / (float)N_TOK;
            float F = ((float)NE * (float)g_counts[e]) / ((float)TOPK * (float)N_TOK);
            aux += P * F;
        }
        out[(size_t)N_TOK * DIM] = aux;
    }
    int idx = blockIdx.x * blockDim.x + threadIdx.x;
    if (idx >= N_TOK * (DIM / 4)) return;
    int n  = idx / (DIM / 4);
    int d4 = idx % (DIM / 4);
    float4 v = ((float4*)out)[idx];
    const uint2* yr = (const uint2*)g_Yrh;
    #pragma unroll
    for (int k = 0; k < TOPK; k++) {
        uint2 y = __ldg(&yr[(size_t)(n * TOPK + k) * (DIM / 4) + d4]);
        __half2 lo = *(__half2*)&y.x;
        __half2 hi = *(__half2*)&y.y;
        v.x += __low2float(lo);  v.y += __high2float(lo);
        v.z += __low2float(hi);  v.w += __high2float(hi);
    }
    ((float4*)out)[idx] = v;
}

// ---------------- launch ----------------
extern "C" void kernel_launch(void* const* d_in, const int* in_sizes, int n_in,
                              void* d_out, int out_size)
{
    const float* x   = (const float*)d_in[0];
    const float* gW  = (const float*)d_in[1];
    const float* gb  = (const float*)d_in[2];
    const float* rb  = (const float*)d_in[3];
    const float* W1  = (const float*)d_in[4];
    const float* b1  = (const float*)d_in[5];
    const float* W2  = (const float*)d_in[6];
    const float* b2  = (const float*)d_in[7];
    const float* sW1 = (const float*)d_in[8];
    const float* sb1 = (const float*)d_in[9];
    const float* sW2 = (const float*)d_in[10];
    const float* sb2 = (const float*)d_in[11];
    float* out = (float*)d_out;

    void* p;
    cudaGetSymbolAddress(&p, g_xh);   __half* xh   = (__half*)p;
    cudaGetSymbolAddress(&p, g_Hsh);  __half* Hsh  = (__half*)p;
    cudaGetSymbolAddress(&p, g_Hrh);  __half* Hrh  = (__half*)p;
    cudaGetSymbolAddress(&p, g_Yrh);  __half* Yrh  = (__half*)p;

    cudaFuncSetAttribute(mma_mlp<DIM, HID, true >, cudaFuncAttributeMaxDynamicSharedMemorySize, SMEM_SZ);
    cudaFuncSetAttribute(mma_mlp<HID, DIM, false>, cudaFuncAttributeMaxDynamicSharedMemorySize, SMEM_SZ);
    cudaFuncSetAttribute(gate8_kernel, cudaFuncAttributeMaxDynamicSharedMemorySize, GATE_SMEM);

    {
        int n16 = N_TOK * DIM / 16;
        cvt16_kernel<<<(n16 + 255) / 256, 256>>>((const float4*)x, (uint4*)xh, n16);  // 0 (+init)
    }
    gate8_kernel<<<N_TOK / GATE_TPB, 256, GATE_SMEM>>>(x, gW, gb, rb);                 // 1

    // 2: MLP1 (merged routed + shared): x -> Hr (slots, gelu, fp16), Hs (tokens)
    mma_mlp<DIM, HID, true ><<<dim3(N_TOK / TBM, HID / TBN, NE + 1), 256, SMEM_SZ>>>(
        xh, xh, W1, sW1, b1, sb1,
        nullptr, Hrh, Hsh);
    // 3: MLP2 (merged): Hr -> Yrh (*tw, fp16), Hs -> out (fp32)
    mma_mlp<HID, DIM, false><<<dim3(N_TOK / TBM, DIM / TBN, NE + 1), 256, SMEM_SZ>>>(
        Hrh, Hsh, W2, sW2, b2, sb2,
        out, Yrh, nullptr);

    aux1_kernel<<<AUX_NB, 256>>>();                                                    // 4
    combine_kernel<<<(N_TOK * (DIM / 4) + 255) / 256, 256>>>(out, out_size);           // 5 (+aux fold)
}